// round 8
// baseline (speedup 1.0000x reference)
#include <cuda_runtime.h>
#include <cuda_bf16.h>
#include <math.h>
#include <stdint.h>

// ---------------- problem constants ----------------
static const int B_   = 2;
static const int L_   = 2048;
static const int DM   = 256;
static const int DS   = 128;
static const int DI   = 1024;
static const int NH   = 16;
static const int HD   = 64;
static const int CD   = 1280;
static const int DIP  = 2320;
static const int CH   = 256;
static const int NC   = 8;
#define GN_EPS 1.1920928955078125e-07f
#define RMS_EPS 1e-5f

#define SZ_ZX   ((long long)B_*L_*DIP)
#define SZ_XBC  ((long long)B_*L_*CD)
#define SZ_DT   ((long long)B_*L_*NH)
#define SZ_ACS  ((long long)B_*NH*L_)
#define SZ_CB   ((long long)B_*NC*CH*CH)
#define SZ_ST   ((long long)B_*NC*NH*HD*DS)
#define SZ_Y    ((long long)B_*L_*DI)

// ---------------- scratch ----------------
__device__ float g_t    [B_*L_*DM];
__device__ float g_zx   [2*B_*L_*DIP];
__device__ float g_xbc  [2*B_*L_*CD];
__device__ float g_dt   [2*B_*L_*NH];
__device__ float g_acs  [2*B_*NH*L_];
__device__ float g_cb   [2*B_*NC*CH*CH];
__device__ float g_st   [2*B_*NC*NH*HD*DS];
__device__ float g_pv   [2*B_*NC*NH*HD*DS];
__device__ float g_y    [2*B_*L_*DI];
__device__ float g_r    [B_*L_*2*DM];
__device__ float g_part [B_*64*2];
__device__ float g_stats[4];

__device__ __forceinline__ float siluf(float x) { return x / (1.f + __expf(-x)); }
__device__ __forceinline__ float softplusf(float x) { return x > 20.f ? x : log1pf(expf(x)); }
__device__ __forceinline__ uint32_t f2tf32(float x) {
    uint32_t r; asm("cvt.rna.tf32.f32 %0, %1;" : "=r"(r) : "f"(x)); return r;
}
__device__ __forceinline__ float tf32v(float x) { return __uint_as_float(f2tf32(x)); }

#define MMA_TF32(acc, a, b) \
    asm volatile( \
        "mma.sync.aligned.m16n8k8.row.col.f32.tf32.tf32.f32 " \
        "{%0,%1,%2,%3},{%4,%5,%6,%7},{%8,%9},{%0,%1,%2,%3};" \
        : "+f"((acc)[0]), "+f"((acc)[1]), "+f"((acc)[2]), "+f"((acc)[3]) \
        : "r"((a)[0]), "r"((a)[1]), "r"((a)[2]), "r"((a)[3]), \
          "r"((b)[0]), "r"((b)[1]))

__device__ __forceinline__ void cpa16(uint32_t dst, const void* src, bool valid) {
    int sz = valid ? 16 : 0;
    asm volatile("cp.async.cg.shared.global [%0], [%1], 16, %2;\n"
                 :: "r"(dst), "l"(src), "r"(sz));
}
#define CPA_COMMIT() asm volatile("cp.async.commit_group;\n" ::)
#define CPA_WAIT1()  asm volatile("cp.async.wait_group 1;\n" ::)

// ---------------- GroupNorm stats: stage 1 ----------------
__global__ void gn_part_k(const float* __restrict__ x, float* __restrict__ part) {
    int b = blockIdx.y;
    const float* xb = x + (size_t)b * DM * L_;
    float s = 0.f, ss = 0.f;
    for (int i = blockIdx.x * blockDim.x + threadIdx.x; i < DM * L_; i += 64 * 256) {
        float v = xb[i]; s += v; ss += v * v;
    }
    __shared__ float sh[256], sh2[256];
    sh[threadIdx.x] = s; sh2[threadIdx.x] = ss;
    __syncthreads();
    for (int o = 128; o > 0; o >>= 1) {
        if ((int)threadIdx.x < o) { sh[threadIdx.x] += sh[threadIdx.x + o]; sh2[threadIdx.x] += sh2[threadIdx.x + o]; }
        __syncthreads();
    }
    if (threadIdx.x == 0) {
        part[(b * 64 + blockIdx.x) * 2 + 0] = sh[0];
        part[(b * 64 + blockIdx.x) * 2 + 1] = sh2[0];
    }
}

// ---------------- GroupNorm stats: stage 2 ----------------
__global__ void gn_fin_k(const float* __restrict__ part, float* __restrict__ stats) {
    int b = blockIdx.x;
    __shared__ double sh[64], sh2[64];
    int i = threadIdx.x;
    sh[i]  = (double)part[(b * 64 + i) * 2 + 0];
    sh2[i] = (double)part[(b * 64 + i) * 2 + 1];
    __syncthreads();
    for (int o = 32; o > 0; o >>= 1) {
        if (i < o) { sh[i] += sh[i + o]; sh2[i] += sh2[i + o]; }
        __syncthreads();
    }
    if (i == 0) {
        double n = (double)DM * L_;
        double mu = sh[0] / n;
        double var = sh2[0] / n - mu * mu;
        stats[b * 2 + 0] = (float)mu;
        stats[b * 2 + 1] = rsqrtf((float)var + GN_EPS);
    }
}

// ---------------- GroupNorm apply + transpose ----------------
__global__ void gn_apply_k(const float* __restrict__ x, const float* __restrict__ gw,
                           const float* __restrict__ gb, const float* __restrict__ stats,
                           float* __restrict__ t) {
    int b = blockIdx.z;
    __shared__ float tile[32][33];
    int l0 = blockIdx.x * 32, d0 = blockIdx.y * 32;
    float mu = stats[b * 2], rs = stats[b * 2 + 1];
#pragma unroll
    for (int r = 0; r < 4; r++) {
        int d = d0 + threadIdx.y + r * 8;
        tile[threadIdx.y + r * 8][threadIdx.x] = x[((size_t)b * DM + d) * L_ + l0 + threadIdx.x];
    }
    __syncthreads();
    int d = d0 + threadIdx.x;
    float w = gw[d], bb = gb[d];
#pragma unroll
    for (int r = 0; r < 4; r++) {
        int l = l0 + threadIdx.y + r * 8;
        t[((size_t)b * L_ + l) * DM + d] = (tile[threadIdx.x][threadIdx.y + r * 8] - mu) * rs * w + bb;
    }
}

// ---------------- TF32 NT GEMM: 128x64 tile, 3-stage cp.async, 1 sync/iter --
template<int BM, int BN, int MODE>
__global__ void __launch_bounds__(256, 2)
gemm_tf32(const float* __restrict__ A, const float* __restrict__ B0,
          const float* __restrict__ B1, float* __restrict__ C,
          int M, int N, int K, int lda, int ldb, int ldc,
          long long sA, long long sB, long long sC,
          int zPerDir, long long dA, long long dC, int revL,
          const float* __restrict__ extra, const float* __restrict__ bias) {
    constexpr int BK = 32;
    constexpr int T  = 256;
    constexpr int ST = 3;
    constexpr int LA = BM * BK / (T * 4);
    constexpr int LB = BN * BK / (T * 4);
    constexpr int MF = BM / 32;
    constexpr int NF = BN / 32;
    __shared__ float As[ST][BM][BK + 4];
    __shared__ float Bs[ST][BN][BK + 4];
    int z = blockIdx.z;
    int dir = z / zPerDir, zz = z % zPerDir;
    const float* Ap = A + dir * dA + zz * sA;
    const float* Bp = (dir ? B1 : B0) + zz * sB;
    float* Cp = C + dir * dC + zz * sC;
    int rev = dir ? revL : 0;
    int m0 = blockIdx.y * BM, n0 = blockIdx.x * BN;
    int tid = threadIdx.x;
    int warp = tid >> 5, lane = tid & 31;
    int wm = warp >> 2, wn = warp & 3;
    int group = lane >> 2, tig = lane & 3;
    float acc[MF][NF][4] = {};

    auto issue = [&](int k0, int s) {
#pragma unroll
        for (int i = 0; i < LA; i++) {
            int e = tid + i * T;
            int mm = e / (BK / 4);
            int kc = (e % (BK / 4)) * 4;
            int gm = m0 + mm;
            int row = gm < M ? gm : 0;
            if (rev && gm < M) { int bb = gm / rev; int ll = gm % rev; row = bb * rev + (rev - 1 - ll); }
            cpa16((uint32_t)__cvta_generic_to_shared(&As[s][mm][kc]),
                  Ap + (long long)row * lda + k0 + kc, gm < M);
        }
#pragma unroll
        for (int i = 0; i < LB; i++) {
            int e = tid + i * T;
            int nn = e / (BK / 4);
            int kc = (e % (BK / 4)) * 4;
            int gn = n0 + nn;
            int rowb = gn < N ? gn : 0;
            cpa16((uint32_t)__cvta_generic_to_shared(&Bs[s][nn][kc]),
                  Bp + (long long)rowb * ldb + k0 + kc, gn < N);
        }
    };
    auto compute = [&](int s) {
#pragma unroll
        for (int ks = 0; ks < BK / 8; ks++) {
            uint32_t af[MF][4], bf[NF][2];
#pragma unroll
            for (int mf = 0; mf < MF; mf++) {
                int rm = wm * (MF * 16) + mf * 16 + group;
                af[mf][0] = __float_as_uint(As[s][rm    ][ks * 8 + tig]);
                af[mf][1] = __float_as_uint(As[s][rm + 8][ks * 8 + tig]);
                af[mf][2] = __float_as_uint(As[s][rm    ][ks * 8 + tig + 4]);
                af[mf][3] = __float_as_uint(As[s][rm + 8][ks * 8 + tig + 4]);
            }
#pragma unroll
            for (int nf = 0; nf < NF; nf++) {
                int rn = wn * (NF * 8) + nf * 8 + group;
                bf[nf][0] = __float_as_uint(Bs[s][rn][ks * 8 + tig]);
                bf[nf][1] = __float_as_uint(Bs[s][rn][ks * 8 + tig + 4]);
            }
#pragma unroll
            for (int mf = 0; mf < MF; mf++)
#pragma unroll
                for (int nf = 0; nf < NF; nf++) MMA_TF32(acc[mf][nf], af[mf], bf[nf]);
        }
    };

    int nIter = K / BK;
    issue(0, 0);
    CPA_COMMIT();
    if (nIter > 1) issue(BK, 1);
    CPA_COMMIT();
    for (int it = 0; it < nIter; it++) {
        CPA_WAIT1();
        __syncthreads();
        if (it + 2 < nIter) issue((it + 2) * BK, (it + 2) % ST);
        CPA_COMMIT();
        compute(it % ST);
    }

#pragma unroll
    for (int mf = 0; mf < MF; mf++) {
#pragma unroll
        for (int nf = 0; nf < NF; nf++) {
            int gn = n0 + wn * (NF * 8) + nf * 8 + 2 * tig;
#pragma unroll
            for (int rr = 0; rr < 2; rr++) {
                int gm = m0 + wm * (MF * 16) + mf * 16 + group + rr * 8;
                float a0 = acc[mf][nf][rr * 2 + 0], a1 = acc[mf][nf][rr * 2 + 1];
                if (MODE == 0) {
                    if (gm < M && gn < N)
                        *reinterpret_cast<float2*>(Cp + (long long)gm * ldc + gn) =
                            make_float2(a0, a1);
                } else if (MODE == 1) {
                    int b = gm / L_, l = gm % L_;
                    int ltm = dir ? (L_ - 1 - l) : l;
                    long long base = (long long)(b * L_ + ltm);
                    float2 tv = *reinterpret_cast<const float2*>(extra + base * DM + gn);
                    *reinterpret_cast<float2*>(C + base * (2 * DM) + dir * DM + gn) =
                        make_float2(a0 + tv.x, a1 + tv.y);
                } else {
                    int b = gm / L_, l = gm % L_;
                    long long i0 = ((long long)(b * DM + gn)) * L_ + l;
                    long long i1 = ((long long)(b * DM + gn + 1)) * L_ + l;
                    C[i0] = extra[i0] + bias[gn] + a0;
                    C[i1] = extra[i1] + bias[gn + 1] + a1;
                }
            }
        }
    }
}

// ---------------- depthwise conv + SiLU (float4 over channels) --------------
__global__ void conv_silu_k(const float* __restrict__ zx,
                            const float* __restrict__ cw0, const float* __restrict__ cb0,
                            const float* __restrict__ cw1, const float* __restrict__ cb1,
                            float* __restrict__ xbc) {
    long long idx = (long long)blockIdx.x * blockDim.x + threadIdx.x;
    if (idx >= 2LL * B_ * L_ * (CD / 4)) return;
    int cg = idx % (CD / 4);
    int l  = (idx / (CD / 4)) % L_;
    long long rest = idx / ((long long)(CD / 4) * L_);
    int b = rest % B_;
    int dir = rest / B_;
    const float* cw = (dir ? cw1 : cw0) + cg * 16;
    const float* cb = (dir ? cb1 : cb0) + cg * 4;
    const float* zxd = zx + dir * SZ_ZX + (size_t)(b * L_) * DIP + DI + cg * 4;
    float4 w0 = *reinterpret_cast<const float4*>(cw);
    float4 w1 = *reinterpret_cast<const float4*>(cw + 4);
    float4 w2 = *reinterpret_cast<const float4*>(cw + 8);
    float4 w3 = *reinterpret_cast<const float4*>(cw + 12);
    float4 acc = *reinterpret_cast<const float4*>(cb);
#pragma unroll
    for (int k = 0; k < 4; k++) {
        int lp = l - 3 + k;
        if (lp >= 0) {
            float4 v = *reinterpret_cast<const float4*>(zxd + (size_t)lp * DIP);
            acc.x += ((const float*)&w0)[k] * v.x;
            acc.y += ((const float*)&w1)[k] * v.y;
            acc.z += ((const float*)&w2)[k] * v.z;
            acc.w += ((const float*)&w3)[k] * v.w;
        }
    }
    acc.x = siluf(acc.x); acc.y = siluf(acc.y); acc.z = siluf(acc.z); acc.w = siluf(acc.w);
    *reinterpret_cast<float4*>(xbc + dir * SZ_XBC + ((size_t)(b * L_ + l)) * CD + cg * 4) = acc;
}

// ---------------- dt softplus + per-chunk cumsum (shuffle scan) -------------
__global__ void dt_scan_k(const float* __restrict__ zx,
                          const float* __restrict__ db0, const float* __restrict__ al0,
                          const float* __restrict__ db1, const float* __restrict__ al1,
                          float* __restrict__ dt, float* __restrict__ acs) {
    int bi = blockIdx.x;
    int dir = bi / (B_ * NH * NC);
    bi %= B_ * NH * NC;
    int c = bi % NC, h = (bi / NC) % NH, b = bi / (NC * NH);
    const float* dt_bias = dir ? db1 : db0;
    const float* A_log   = dir ? al1 : al0;
    int l = threadIdx.x;
    int lane = l & 31, warp = l >> 5;
    int gl = c * CH + l;
    int row = b * L_ + gl;
    float v = zx[dir * SZ_ZX + (size_t)row * DIP + (DIP - NH) + h] + dt_bias[h];
    float dtv = softplusf(v);
    dt[dir * SZ_DT + (size_t)row * NH + h] = dtv;
    float a = -expf(A_log[h]) * dtv;
#pragma unroll
    for (int o = 1; o < 32; o <<= 1) {
        float t = __shfl_up_sync(0xffffffff, a, o);
        if (lane >= o) a += t;
    }
    __shared__ float wsum[8];
    if (lane == 31) wsum[warp] = a;
    __syncthreads();
    float off = 0.f;
#pragma unroll
    for (int w = 0; w < 8; w++) if (w < warp) off += wsum[w];
    acs[dir * SZ_ACS + (size_t)(b * NH + h) * L_ + gl] = a + off;
}

// ---------------- per-chunk end state via tf32 mma ----------------
__global__ void __launch_bounds__(256)
states_mma_k(const float* __restrict__ xbc, const float* __restrict__ dt,
             const float* __restrict__ acs, float* __restrict__ st) {
    int h = blockIdx.x, c = blockIdx.y;
    int dir = blockIdx.z / B_, b = blockIdx.z % B_;
    const float* xbcd = xbc + dir * SZ_XBC;
    const float* dtd  = dt  + dir * SZ_DT;
    const float* acsd = acs + dir * SZ_ACS;
    int tid = threadIdx.x;
    int warp = tid >> 5, lane = tid & 31;
    int wm = warp >> 2, wn = warp & 3;
    int group = lane >> 2, tig = lane & 3;
    __shared__ float Xs[32][72];
    __shared__ float Bs[32][136];
    __shared__ float wrow[CH];
    int acsbase = (b * NH + h) * L_ + c * CH;
    float csLast = acsd[acsbase + CH - 1];
    {
        int row = b * L_ + c * CH + tid;
        wrow[tid] = dtd[(size_t)row * NH + h] * __expf(csLast - acsd[acsbase + tid]);
    }
    __syncthreads();
    float acc[2][4][4] = {};
    for (int s0 = 0; s0 < CH; s0 += 32) {
#pragma unroll
        for (int i = 0; i < 8; i++) {
            int e = tid + i * 256;
            int pp = e & 63, ss = e >> 6;
            int row = b * L_ + c * CH + s0 + ss;
            Xs[ss][pp] = tf32v(xbcd[(size_t)row * CD + h * HD + pp] * wrow[s0 + ss]);
        }
#pragma unroll
        for (int i = 0; i < 16; i++) {
            int e = tid + i * 256;
            int nn = e & 127, ss = e >> 7;
            int row = b * L_ + c * CH + s0 + ss;
            Bs[ss][nn] = tf32v(xbcd[(size_t)row * CD + DI + nn]);
        }
        __syncthreads();
#pragma unroll
        for (int ks = 0; ks < 4; ks++) {
            int k0 = ks * 8;
            uint32_t af[2][4], bf[4][2];
#pragma unroll
            for (int mf = 0; mf < 2; mf++) {
                int rm = wm * 32 + mf * 16 + group;
                af[mf][0] = __float_as_uint(Xs[k0 + tig    ][rm]);
                af[mf][1] = __float_as_uint(Xs[k0 + tig    ][rm + 8]);
                af[mf][2] = __float_as_uint(Xs[k0 + tig + 4][rm]);
                af[mf][3] = __float_as_uint(Xs[k0 + tig + 4][rm + 8]);
            }
#pragma unroll
            for (int nf = 0; nf < 4; nf++) {
                int rn = wn * 32 + nf * 8 + group;
                bf[nf][0] = __float_as_uint(Bs[k0 + tig    ][rn]);
                bf[nf][1] = __float_as_uint(Bs[k0 + tig + 4][rn]);
            }
#pragma unroll
            for (int mf = 0; mf < 2; mf++)
#pragma unroll
                for (int nf = 0; nf < 4; nf++) MMA_TF32(acc[mf][nf], af[mf], bf[nf]);
        }
        __syncthreads();
    }
    float* base = st + dir * SZ_ST + (size_t)((b * NC + c) * NH + h) * HD * DS;
#pragma unroll
    for (int mf = 0; mf < 2; mf++) {
#pragma unroll
        for (int nf = 0; nf < 4; nf++) {
            int gm = wm * 32 + mf * 16 + group;
            int gn = wn * 32 + nf * 8 + 2 * tig;
            *reinterpret_cast<float2*>(base + gm * DS + gn) =
                make_float2(acc[mf][nf][0], acc[mf][nf][1]);
            *reinterpret_cast<float2*>(base + (gm + 8) * DS + gn) =
                make_float2(acc[mf][nf][2], acc[mf][nf][3]);
        }
    }
}

// ---------------- inter-chunk recurrence ----------------
__global__ void chunkscan_k(const float* __restrict__ st, const float* __restrict__ acs,
                            float* __restrict__ pv) {
    int idx = blockIdx.x * blockDim.x + threadIdx.x;
    int n = idx & (DS - 1);
    int p = (idx >> 7) & (HD - 1);
    int h = (idx >> 13) & (NH - 1);
    int b = (idx >> 17) & (B_ - 1);
    int dir = idx >> 18;
    const float* std_ = st + dir * SZ_ST;
    const float* acsd = acs + dir * SZ_ACS;
    float* pvd = pv + dir * SZ_ST;
    float S = 0.f;
    for (int c = 0; c < NC; c++) {
        size_t off = ((size_t)((b * NC + c) * NH + h) * HD + p) * DS + n;
        pvd[off] = S;
        float at = acsd[(b * NH + h) * L_ + c * CH + CH - 1];
        S = S * expf(at) + std_[off];
    }
}

// ---------------- Y via tf32 mma, fully precomputed decay ----------------
__global__ void __launch_bounds__(256)
ssd_y_mma_k(const float* __restrict__ xbc, const float* __restrict__ dt,
            const float* __restrict__ acs, const float* __restrict__ cb,
            const float* __restrict__ pv,
            const float* __restrict__ Dh0, const float* __restrict__ Dh1,
            float* __restrict__ y) {
    int lt = blockIdx.x, h = blockIdx.y;
    int dir = blockIdx.z / (B_ * NC);
    int bc = blockIdx.z % (B_ * NC);
    int c = bc % NC, b = bc / NC;
    const float* xbcd = xbc + dir * SZ_XBC;
    const float* dtd  = dt  + dir * SZ_DT;
    const float* acsd = acs + dir * SZ_ACS;
    const float* Dh   = dir ? Dh1 : Dh0;
    int tid = threadIdx.x;
    int warp = tid >> 5, lane = tid & 31;
    int wm = warp >> 2, wn = warp & 3;
    int group = lane >> 2, tig = lane & 3;
    __shared__ float Ws[64][36];
    __shared__ float Xs[32][72];
    __shared__ float Ps[64][36];
    __shared__ float csl[64], el64[64], eoff[64];
    __shared__ float einv[CH];
    int l0 = lt * 64;
    int acsbase = (b * NH + h) * L_ + c * CH;
    float csl0 = acsd[acsbase + l0];
    if (tid < 64) {
        float v = acsd[acsbase + l0 + tid];
        csl[tid]  = v;
        el64[tid] = __expf(v - csl0);
        eoff[tid] = __expf(v);
    }
    einv[tid] = __expf(csl0 - acsd[acsbase + tid]);
    __syncthreads();
    const float* cbb = cb + dir * SZ_CB + (size_t)(b * NC + c) * CH * CH;
    float acc[2][2][4] = {};
    int nst = 2 * lt + 2;
    for (int stp = 0; stp < nst; stp++) {
        int s0 = stp * 32;
        bool lower = (s0 + 31 < l0);
        if (lower) {
#pragma unroll
            for (int i = 0; i < 8; i++) {
                int e = tid + i * 256;
                int j = e & 31, ii = e >> 5;
                Ws[ii][j] = tf32v(el64[ii] * einv[s0 + j] * cbb[(l0 + ii) * CH + s0 + j]);
            }
        } else {
#pragma unroll
            for (int i = 0; i < 8; i++) {
                int e = tid + i * 256;
                int j = e & 31, ii = e >> 5;
                float w = 0.f;
                if (s0 + j <= l0 + ii)
                    w = __expf(csl[ii] - acsd[acsbase + s0 + j]) * cbb[(l0 + ii) * CH + s0 + j];
                Ws[ii][j] = tf32v(w);
            }
        }
#pragma unroll
        for (int i = 0; i < 8; i++) {
            int e = tid + i * 256;
            int pp = e & 63, ss = e >> 6;
            int row = b * L_ + c * CH + s0 + ss;
            Xs[ss][pp] = tf32v(xbcd[(size_t)row * CD + h * HD + pp] * dtd[(size_t)row * NH + h]);
        }
        __syncthreads();
#pragma unroll
        for (int ks = 0; ks < 4; ks++) {
            int k0 = ks * 8;
            uint32_t af[2][4], bf[2][2];
#pragma unroll
            for (int mf = 0; mf < 2; mf++) {
                int rm = wm * 32 + mf * 16 + group;
                af[mf][0] = __float_as_uint(Ws[rm    ][k0 + tig]);
                af[mf][1] = __float_as_uint(Ws[rm + 8][k0 + tig]);
                af[mf][2] = __float_as_uint(Ws[rm    ][k0 + tig + 4]);
                af[mf][3] = __float_as_uint(Ws[rm + 8][k0 + tig + 4]);
            }
#pragma unroll
            for (int nf = 0; nf < 2; nf++) {
                int rn = wn * 16 + nf * 8 + group;
                bf[nf][0] = __float_as_uint(Xs[k0 + tig    ][rn]);
                bf[nf][1] = __float_as_uint(Xs[k0 + tig + 4][rn]);
            }
#pragma unroll
            for (int mf = 0; mf < 2; mf++)
#pragma unroll
                for (int nf = 0; nf < 2; nf++) MMA_TF32(acc[mf][nf], af[mf], bf[nf]);
        }
        __syncthreads();
    }
    const float* pvb = pv + dir * SZ_ST + (size_t)((b * NC + c) * NH + h) * HD * DS;
    for (int nt = 0; nt < 4; nt++) {
        int n0 = nt * 32;
#pragma unroll
        for (int i = 0; i < 8; i++) {
            int e = tid + i * 256;
            int j = e & 31, ii = e >> 5;
            int row = b * L_ + c * CH + l0 + ii;
            Ws[ii][j] = tf32v(xbcd[(size_t)row * CD + DI + DS + n0 + j] * eoff[ii]);
        }
#pragma unroll
        for (int i = 0; i < 8; i++) {
            int e = tid + i * 256;
            int j = e & 31, pp = e >> 5;
            Ps[pp][j] = tf32v(pvb[pp * DS + n0 + j]);
        }
        __syncthreads();
#pragma unroll
        for (int ks = 0; ks < 4; ks++) {
            int k0 = ks * 8;
            uint32_t af[2][4], bf[2][2];
#pragma unroll
            for (int mf = 0; mf < 2; mf++) {
                int rm = wm * 32 + mf * 16 + group;
                af[mf][0] = __float_as_uint(Ws[rm    ][k0 + tig]);
                af[mf][1] = __float_as_uint(Ws[rm + 8][k0 + tig]);
                af[mf][2] = __float_as_uint(Ws[rm    ][k0 + tig + 4]);
                af[mf][3] = __float_as_uint(Ws[rm + 8][k0 + tig + 4]);
            }
#pragma unroll
            for (int nf = 0; nf < 2; nf++) {
                int rn = wn * 16 + nf * 8 + group;
                bf[nf][0] = __float_as_uint(Ps[rn][k0 + tig]);
                bf[nf][1] = __float_as_uint(Ps[rn][k0 + tig + 4]);
            }
#pragma unroll
            for (int mf = 0; mf < 2; mf++)
#pragma unroll
                for (int nf = 0; nf < 2; nf++) MMA_TF32(acc[mf][nf], af[mf], bf[nf]);
        }
        __syncthreads();
    }
    float dh = Dh[h];
    float* yd = y + dir * SZ_Y;
#pragma unroll
    for (int mf = 0; mf < 2; mf++) {
#pragma unroll
        for (int nf = 0; nf < 2; nf++) {
            int ll = l0 + wm * 32 + mf * 16 + group;
            int pp = wn * 16 + nf * 8 + 2 * tig;
#pragma unroll
            for (int rr = 0; rr < 2; rr++) {
                int row = b * L_ + c * CH + ll + rr * 8;
                float2 xr = *reinterpret_cast<const float2*>(
                    xbcd + (size_t)row * CD + h * HD + pp);
                *reinterpret_cast<float2*>(yd + (size_t)row * DI + h * HD + pp) =
                    make_float2(acc[mf][nf][rr * 2 + 0] + xr.x * dh,
                                acc[mf][nf][rr * 2 + 1] + xr.y * dh);
            }
        }
    }
}

// ---------------- gating + RMSNorm (float4) ----------------
__global__ void gate_rms_k(float* __restrict__ y, const float* __restrict__ zx,
                           const float* __restrict__ nw0, const float* __restrict__ nw1) {
    int row = blockIdx.x;
    int dir = row / (B_ * L_);
    row %= B_ * L_;
    const float* nw = dir ? nw1 : nw0;
    float* yd = y + dir * SZ_Y + (size_t)row * DI;
    const float* zxd = zx + dir * SZ_ZX + (size_t)row * DIP;
    int tid = threadIdx.x;
    float4 yv = *reinterpret_cast<const float4*>(yd + tid * 4);
    float4 zv = *reinterpret_cast<const float4*>(zxd + tid * 4);
    yv.x *= siluf(zv.x); yv.y *= siluf(zv.y); yv.z *= siluf(zv.z); yv.w *= siluf(zv.w);
    float ss = yv.x * yv.x + yv.y * yv.y + yv.z * yv.z + yv.w * yv.w;
    __shared__ float sh[256];
    sh[tid] = ss;
    __syncthreads();
    for (int o = 128; o > 0; o >>= 1) {
        if (tid < o) sh[tid] += sh[tid + o];
        __syncthreads();
    }
    float scale = rsqrtf(sh[0] / DI + RMS_EPS);
    float4 wv = *reinterpret_cast<const float4*>(nw + tid * 4);
    yv.x *= scale * wv.x; yv.y *= scale * wv.y; yv.z *= scale * wv.z; yv.w *= scale * wv.w;
    *reinterpret_cast<float4*>(yd + tid * 4) = yv;
}

// ---------------- launch ----------------
extern "C" void kernel_launch(void* const* d_in, const int* in_sizes, int n_in,
                              void* d_out, int out_size) {
    (void)in_sizes; (void)n_in; (void)out_size;
    const float* x      = (const float*)d_in[0];
    const float* gn_w   = (const float*)d_in[1];
    const float* gn_b   = (const float*)d_in[2];
    const float* proj_w = (const float*)d_in[3];
    const float* proj_b = (const float*)d_in[4];
    const float* fw[8], *bw[8];
    for (int i = 0; i < 8; i++) { fw[i] = (const float*)d_in[5 + i]; bw[i] = (const float*)d_in[13 + i]; }
    float* out = (float*)d_out;

    float *t_, *zx_, *xbc_, *dt_, *acs_, *cb_, *st_, *pv_, *y_, *r_, *part_, *stats_;
    cudaGetSymbolAddress((void**)&t_,    g_t);
    cudaGetSymbolAddress((void**)&zx_,   g_zx);
    cudaGetSymbolAddress((void**)&xbc_,  g_xbc);
    cudaGetSymbolAddress((void**)&dt_,   g_dt);
    cudaGetSymbolAddress((void**)&acs_,  g_acs);
    cudaGetSymbolAddress((void**)&cb_,   g_cb);
    cudaGetSymbolAddress((void**)&st_,   g_st);
    cudaGetSymbolAddress((void**)&pv_,   g_pv);
    cudaGetSymbolAddress((void**)&y_,    g_y);
    cudaGetSymbolAddress((void**)&r_,    g_r);
    cudaGetSymbolAddress((void**)&part_, g_part);
    cudaGetSymbolAddress((void**)&stats_,g_stats);

    gn_part_k<<<dim3(64, B_), 256>>>(x, part_);
    gn_fin_k<<<B_, 64>>>(part_, stats_);
    gn_apply_k<<<dim3(L_ / 32, DM / 32, B_), dim3(32, 8)>>>(x, gn_w, gn_b, stats_, t_);

    gemm_tf32<128,64,0><<<dim3((DIP + 63) / 64, (B_ * L_) / 128, 2), 256>>>(
        t_, fw[0], bw[0], zx_, B_ * L_, DIP, DM, DM, DM, DIP,
        0, 0, 0, 1, 0, SZ_ZX, L_, nullptr, nullptr);

    conv_silu_k<<<(int)((2LL * B_ * L_ * (CD / 4) + 255) / 256), 256>>>(
        zx_, fw[1], fw[2], bw[1], bw[2], xbc_);
    dt_scan_k<<<2 * B_ * NH * NC, CH>>>(zx_, fw[3], fw[4], bw[3], bw[4], dt_, acs_);

    gemm_tf32<128,64,0><<<dim3(CH / 64, CH / 128, 2 * B_ * NC), 256>>>(
        xbc_ + DI + DS, xbc_ + DI, xbc_ + SZ_XBC + DI, cb_, CH, CH, DS, CD, CD, CH,
        (long long)CH * CD, (long long)CH * CD, (long long)CH * CH,
        B_ * NC, SZ_XBC, SZ_CB, 0, nullptr, nullptr);

    states_mma_k<<<dim3(NH, NC, 2 * B_), 256>>>(xbc_, dt_, acs_, st_);
    chunkscan_k<<<(2 * B_ * NH * HD * DS) / 256, 256>>>(st_, acs_, pv_);
    ssd_y_mma_k<<<dim3(CH / 64, NH, 2 * B_ * NC), 256>>>(
        xbc_, dt_, acs_, cb_, pv_, fw[5], bw[5], y_);
    gate_rms_k<<<2 * B_ * L_, 256>>>(y_, zx_, fw[6], bw[6]);

    gemm_tf32<128,64,1><<<dim3(DM / 64, (B_ * L_) / 128, 2), 256>>>(
        y_, fw[7], bw[7], r_, B_ * L_, DM, DI, DI, DI, DM,
        0, 0, 0, 1, SZ_Y, 0, 0, t_, nullptr);

    gemm_tf32<128,64,2><<<dim3(DM / 64, (B_ * L_) / 128, 1), 256>>>(
        r_, proj_w, proj_w, out, B_ * L_, DM, 2 * DM, 2 * DM, 2 * DM, DM,
        0, 0, 0, 1, 0, 0, 0, x, proj_b);
}

// round 9
// speedup vs baseline: 1.1336x; 1.1336x over previous
#include <cuda_runtime.h>
#include <cuda_bf16.h>
#include <math.h>
#include <stdint.h>

// ---------------- problem constants ----------------
static const int B_   = 2;
static const int L_   = 2048;
static const int DM   = 256;
static const int DS   = 128;
static const int DI   = 1024;
static const int NH   = 16;
static const int HD   = 64;
static const int CD   = 1280;
static const int DIP  = 2320;
static const int CH   = 256;
static const int NC   = 8;
#define GN_EPS 1.1920928955078125e-07f
#define RMS_EPS 1e-5f

#define SZ_ZX   ((long long)B_*L_*DIP)
#define SZ_XBC  ((long long)B_*L_*CD)
#define SZ_DT   ((long long)B_*L_*NH)
#define SZ_ACS  ((long long)B_*NH*L_)
#define SZ_CB   ((long long)B_*NC*CH*CH)
#define SZ_ST   ((long long)B_*NC*NH*HD*DS)
#define SZ_Y    ((long long)B_*L_*DI)

// ---------------- scratch ----------------
__device__ float g_t    [B_*L_*DM];
__device__ float g_zx   [2*B_*L_*DIP];
__device__ float g_xbc  [2*B_*L_*CD];
__device__ float g_dt   [2*B_*L_*NH];
__device__ float g_acs  [2*B_*NH*L_];
__device__ float g_cb   [2*B_*NC*CH*CH];
__device__ float g_st   [2*B_*NC*NH*HD*DS];
__device__ float g_pv   [2*B_*NC*NH*HD*DS];
__device__ float g_y    [2*B_*L_*DI];
__device__ float g_r    [B_*L_*2*DM];
__device__ float g_part [B_*64*2];
__device__ float g_stats[4];

__device__ __forceinline__ float siluf(float x) { return x / (1.f + __expf(-x)); }
__device__ __forceinline__ float softplusf(float x) { return x > 20.f ? x : log1pf(expf(x)); }
__device__ __forceinline__ uint32_t f2tf32(float x) {
    uint32_t r; asm("cvt.rna.tf32.f32 %0, %1;" : "=r"(r) : "f"(x)); return r;
}
__device__ __forceinline__ float tf32v(float x) { return __uint_as_float(f2tf32(x)); }

#define MMA_TF32(acc, a, b) \
    asm volatile( \
        "mma.sync.aligned.m16n8k8.row.col.f32.tf32.tf32.f32 " \
        "{%0,%1,%2,%3},{%4,%5,%6,%7},{%8,%9},{%0,%1,%2,%3};" \
        : "+f"((acc)[0]), "+f"((acc)[1]), "+f"((acc)[2]), "+f"((acc)[3]) \
        : "r"((a)[0]), "r"((a)[1]), "r"((a)[2]), "r"((a)[3]), \
          "r"((b)[0]), "r"((b)[1]))

__device__ __forceinline__ void cpa16(uint32_t dst, const void* src, bool valid) {
    int sz = valid ? 16 : 0;
    asm volatile("cp.async.cg.shared.global [%0], [%1], 16, %2;\n"
                 :: "r"(dst), "l"(src), "r"(sz));
}
#define CPA_COMMIT() asm volatile("cp.async.commit_group;\n" ::)
#define CPA_WAIT1()  asm volatile("cp.async.wait_group 1;\n" ::)

// ---------------- GroupNorm stats: stage 1 ----------------
__global__ void gn_part_k(const float* __restrict__ x, float* __restrict__ part) {
    int b = blockIdx.y;
    const float* xb = x + (size_t)b * DM * L_;
    float s = 0.f, ss = 0.f;
    for (int i = blockIdx.x * blockDim.x + threadIdx.x; i < DM * L_; i += 64 * 256) {
        float v = xb[i]; s += v; ss += v * v;
    }
    __shared__ float sh[256], sh2[256];
    sh[threadIdx.x] = s; sh2[threadIdx.x] = ss;
    __syncthreads();
    for (int o = 128; o > 0; o >>= 1) {
        if ((int)threadIdx.x < o) { sh[threadIdx.x] += sh[threadIdx.x + o]; sh2[threadIdx.x] += sh2[threadIdx.x + o]; }
        __syncthreads();
    }
    if (threadIdx.x == 0) {
        part[(b * 64 + blockIdx.x) * 2 + 0] = sh[0];
        part[(b * 64 + blockIdx.x) * 2 + 1] = sh2[0];
    }
}

// ---------------- GroupNorm stats: stage 2 ----------------
__global__ void gn_fin_k(const float* __restrict__ part, float* __restrict__ stats) {
    int b = blockIdx.x;
    __shared__ double sh[64], sh2[64];
    int i = threadIdx.x;
    sh[i]  = (double)part[(b * 64 + i) * 2 + 0];
    sh2[i] = (double)part[(b * 64 + i) * 2 + 1];
    __syncthreads();
    for (int o = 32; o > 0; o >>= 1) {
        if (i < o) { sh[i] += sh[i + o]; sh2[i] += sh2[i + o]; }
        __syncthreads();
    }
    if (i == 0) {
        double n = (double)DM * L_;
        double mu = sh[0] / n;
        double var = sh2[0] / n - mu * mu;
        stats[b * 2 + 0] = (float)mu;
        stats[b * 2 + 1] = rsqrtf((float)var + GN_EPS);
    }
}

// ---------------- GroupNorm apply + transpose ----------------
__global__ void gn_apply_k(const float* __restrict__ x, const float* __restrict__ gw,
                           const float* __restrict__ gb, const float* __restrict__ stats,
                           float* __restrict__ t) {
    int b = blockIdx.z;
    __shared__ float tile[32][33];
    int l0 = blockIdx.x * 32, d0 = blockIdx.y * 32;
    float mu = stats[b * 2], rs = stats[b * 2 + 1];
#pragma unroll
    for (int r = 0; r < 4; r++) {
        int d = d0 + threadIdx.y + r * 8;
        tile[threadIdx.y + r * 8][threadIdx.x] = x[((size_t)b * DM + d) * L_ + l0 + threadIdx.x];
    }
    __syncthreads();
    int d = d0 + threadIdx.x;
    float w = gw[d], bb = gb[d];
#pragma unroll
    for (int r = 0; r < 4; r++) {
        int l = l0 + threadIdx.y + r * 8;
        t[((size_t)b * L_ + l) * DM + d] = (tile[threadIdx.x][threadIdx.y + r * 8] - mu) * rs * w + bb;
    }
}

// ---- TF32 NT GEMM: 128x128 CTA tile, 4 warps (64x64 each), 3-stage async ---
// Crossbar-optimal: MF=4, NF=8 -> 128 B smem traffic per MMA.
// Dynamic smem: ST*(BM+BN)*(BK+4)*4 = 110592 bytes.
#define GBM 128
#define GBN 128
#define GBK 32
#define GST 3
#define GLD 36               // BK+4
#define G_SMEM_BYTES (GST * (GBM + GBN) * GLD * 4)

template<int MODE>
__global__ void __launch_bounds__(128, 2)
gemm_tf32(const float* __restrict__ A, const float* __restrict__ B0,
          const float* __restrict__ B1, float* __restrict__ C,
          int M, int N, int K, int lda, int ldb, int ldc,
          long long sA, long long sB, long long sC,
          int zPerDir, long long dA, long long dC, int revL,
          const float* __restrict__ extra, const float* __restrict__ bias) {
    constexpr int T  = 128;
    constexpr int LA = GBM * GBK / (T * 4);   // 8
    constexpr int LB = GBN * GBK / (T * 4);   // 8
    constexpr int MF = 4;
    constexpr int NF = 8;
    extern __shared__ float smem[];
    float* Asm = smem;                         // [GST][GBM][GLD]
    float* Bsm = smem + GST * GBM * GLD;       // [GST][GBN][GLD]
    int z = blockIdx.z;
    int dir = z / zPerDir, zz = z % zPerDir;
    const float* Ap = A + dir * dA + zz * sA;
    const float* Bp = (dir ? B1 : B0) + zz * sB;
    float* Cp = C + dir * dC + zz * sC;
    int rev = dir ? revL : 0;
    int m0 = blockIdx.y * GBM, n0 = blockIdx.x * GBN;
    int tid = threadIdx.x;
    int warp = tid >> 5, lane = tid & 31;
    int wm = warp >> 1, wn = warp & 1;         // 2x2 warps
    int group = lane >> 2, tig = lane & 3;
    float acc[MF][NF][4] = {};

    auto issue = [&](int k0, int s) {
        float* As = Asm + s * GBM * GLD;
        float* Bs = Bsm + s * GBN * GLD;
#pragma unroll
        for (int i = 0; i < LA; i++) {
            int e = tid + i * T;
            int mm = e / (GBK / 4);
            int kc = (e % (GBK / 4)) * 4;
            int gm = m0 + mm;
            int row = gm < M ? gm : 0;
            if (rev && gm < M) { int bb = gm / rev; int ll = gm % rev; row = bb * rev + (rev - 1 - ll); }
            cpa16((uint32_t)__cvta_generic_to_shared(As + mm * GLD + kc),
                  Ap + (long long)row * lda + k0 + kc, gm < M);
        }
#pragma unroll
        for (int i = 0; i < LB; i++) {
            int e = tid + i * T;
            int nn = e / (GBK / 4);
            int kc = (e % (GBK / 4)) * 4;
            int gn = n0 + nn;
            int rowb = gn < N ? gn : 0;
            cpa16((uint32_t)__cvta_generic_to_shared(Bs + nn * GLD + kc),
                  Bp + (long long)rowb * ldb + k0 + kc, gn < N);
        }
    };
    auto compute = [&](int s) {
        const float* As = Asm + s * GBM * GLD;
        const float* Bs = Bsm + s * GBN * GLD;
#pragma unroll
        for (int ks = 0; ks < GBK / 8; ks++) {
            uint32_t af[MF][4], bf[NF][2];
#pragma unroll
            for (int mf = 0; mf < MF; mf++) {
                int rm = wm * (MF * 16) + mf * 16 + group;
                af[mf][0] = __float_as_uint(As[(rm    ) * GLD + ks * 8 + tig]);
                af[mf][1] = __float_as_uint(As[(rm + 8) * GLD + ks * 8 + tig]);
                af[mf][2] = __float_as_uint(As[(rm    ) * GLD + ks * 8 + tig + 4]);
                af[mf][3] = __float_as_uint(As[(rm + 8) * GLD + ks * 8 + tig + 4]);
            }
#pragma unroll
            for (int nf = 0; nf < NF; nf++) {
                int rn = wn * (NF * 8) + nf * 8 + group;
                bf[nf][0] = __float_as_uint(Bs[rn * GLD + ks * 8 + tig]);
                bf[nf][1] = __float_as_uint(Bs[rn * GLD + ks * 8 + tig + 4]);
            }
#pragma unroll
            for (int mf = 0; mf < MF; mf++)
#pragma unroll
                for (int nf = 0; nf < NF; nf++) MMA_TF32(acc[mf][nf], af[mf], bf[nf]);
        }
    };

    int nIter = K / GBK;
    issue(0, 0);
    CPA_COMMIT();
    if (nIter > 1) issue(GBK, 1);
    CPA_COMMIT();
    for (int it = 0; it < nIter; it++) {
        CPA_WAIT1();
        __syncthreads();
        if (it + 2 < nIter) issue((it + 2) * GBK, (it + 2) % GST);
        CPA_COMMIT();
        compute(it % GST);
    }

#pragma unroll
    for (int mf = 0; mf < MF; mf++) {
#pragma unroll
        for (int nf = 0; nf < NF; nf++) {
            int gn = n0 + wn * (NF * 8) + nf * 8 + 2 * tig;
#pragma unroll
            for (int rr = 0; rr < 2; rr++) {
                int gm = m0 + wm * (MF * 16) + mf * 16 + group + rr * 8;
                float a0 = acc[mf][nf][rr * 2 + 0], a1 = acc[mf][nf][rr * 2 + 1];
                if (MODE == 0) {
                    if (gm < M && gn < N)
                        *reinterpret_cast<float2*>(Cp + (long long)gm * ldc + gn) =
                            make_float2(a0, a1);
                } else if (MODE == 1) {
                    int b = gm / L_, l = gm % L_;
                    int ltm = dir ? (L_ - 1 - l) : l;
                    long long base = (long long)(b * L_ + ltm);
                    float2 tv = *reinterpret_cast<const float2*>(extra + base * DM + gn);
                    *reinterpret_cast<float2*>(C + base * (2 * DM) + dir * DM + gn) =
                        make_float2(a0 + tv.x, a1 + tv.y);
                } else {
                    int b = gm / L_, l = gm % L_;
                    long long i0 = ((long long)(b * DM + gn)) * L_ + l;
                    long long i1 = ((long long)(b * DM + gn + 1)) * L_ + l;
                    C[i0] = extra[i0] + bias[gn] + a0;
                    C[i1] = extra[i1] + bias[gn + 1] + a1;
                }
            }
        }
    }
}

// ---------------- depthwise conv + SiLU (4 l-values per thread) -------------
__global__ void conv_silu_k(const float* __restrict__ zx,
                            const float* __restrict__ cw0, const float* __restrict__ cb0,
                            const float* __restrict__ cw1, const float* __restrict__ cb1,
                            float* __restrict__ xbc) {
    long long idx = (long long)blockIdx.x * blockDim.x + threadIdx.x;
    if (idx >= 2LL * B_ * (L_ / 4) * (CD / 4)) return;
    int cg = idx % (CD / 4);
    int lb = (idx / (CD / 4)) % (L_ / 4);
    long long rest = idx / ((long long)(CD / 4) * (L_ / 4));
    int b = rest % B_;
    int dir = rest / B_;
    int l0 = lb * 4;
    const float* cw = (dir ? cw1 : cw0) + cg * 16;
    const float* cb = (dir ? cb1 : cb0) + cg * 4;
    const float* zxd = zx + dir * SZ_ZX + (size_t)(b * L_) * DIP + DI + cg * 4;
    float4 w0 = *reinterpret_cast<const float4*>(cw);
    float4 w1 = *reinterpret_cast<const float4*>(cw + 4);
    float4 w2 = *reinterpret_cast<const float4*>(cw + 8);
    float4 w3 = *reinterpret_cast<const float4*>(cw + 12);
    float4 bv = *reinterpret_cast<const float4*>(cb);
    float4 v[7];
#pragma unroll
    for (int r = 0; r < 7; r++) {
        int lp = l0 - 3 + r;
        v[r] = (lp >= 0) ? *reinterpret_cast<const float4*>(zxd + (size_t)lp * DIP)
                         : make_float4(0.f, 0.f, 0.f, 0.f);
    }
    float* outp = xbc + dir * SZ_XBC + ((size_t)(b * L_ + l0)) * CD + cg * 4;
#pragma unroll
    for (int j = 0; j < 4; j++) {
        float4 acc = bv;
#pragma unroll
        for (int k = 0; k < 4; k++) {
            float4 f = v[j + k];
            acc.x += ((const float*)&w0)[k] * f.x;
            acc.y += ((const float*)&w1)[k] * f.y;
            acc.z += ((const float*)&w2)[k] * f.z;
            acc.w += ((const float*)&w3)[k] * f.w;
        }
        acc.x = siluf(acc.x); acc.y = siluf(acc.y); acc.z = siluf(acc.z); acc.w = siluf(acc.w);
        *reinterpret_cast<float4*>(outp + (size_t)j * CD) = acc;
    }
}

// ---------------- dt softplus + per-chunk cumsum (shuffle scan) -------------
__global__ void dt_scan_k(const float* __restrict__ zx,
                          const float* __restrict__ db0, const float* __restrict__ al0,
                          const float* __restrict__ db1, const float* __restrict__ al1,
                          float* __restrict__ dt, float* __restrict__ acs) {
    int bi = blockIdx.x;
    int dir = bi / (B_ * NH * NC);
    bi %= B_ * NH * NC;
    int c = bi % NC, h = (bi / NC) % NH, b = bi / (NC * NH);
    const float* dt_bias = dir ? db1 : db0;
    const float* A_log   = dir ? al1 : al0;
    int l = threadIdx.x;
    int lane = l & 31, warp = l >> 5;
    int gl = c * CH + l;
    int row = b * L_ + gl;
    float v = zx[dir * SZ_ZX + (size_t)row * DIP + (DIP - NH) + h] + dt_bias[h];
    float dtv = softplusf(v);
    dt[dir * SZ_DT + (size_t)row * NH + h] = dtv;
    float a = -expf(A_log[h]) * dtv;
#pragma unroll
    for (int o = 1; o < 32; o <<= 1) {
        float t = __shfl_up_sync(0xffffffff, a, o);
        if (lane >= o) a += t;
    }
    __shared__ float wsum[8];
    if (lane == 31) wsum[warp] = a;
    __syncthreads();
    float off = 0.f;
#pragma unroll
    for (int w = 0; w < 8; w++) if (w < warp) off += wsum[w];
    acs[dir * SZ_ACS + (size_t)(b * NH + h) * L_ + gl] = a + off;
}

// ---------------- per-chunk end state via tf32 mma ----------------
__global__ void __launch_bounds__(256)
states_mma_k(const float* __restrict__ xbc, const float* __restrict__ dt,
             const float* __restrict__ acs, float* __restrict__ st) {
    int h = blockIdx.x, c = blockIdx.y;
    int dir = blockIdx.z / B_, b = blockIdx.z % B_;
    const float* xbcd = xbc + dir * SZ_XBC;
    const float* dtd  = dt  + dir * SZ_DT;
    const float* acsd = acs + dir * SZ_ACS;
    int tid = threadIdx.x;
    int warp = tid >> 5, lane = tid & 31;
    int wm = warp >> 2, wn = warp & 3;
    int group = lane >> 2, tig = lane & 3;
    __shared__ float Xs[32][72];
    __shared__ float Bs[32][136];
    __shared__ float wrow[CH];
    int acsbase = (b * NH + h) * L_ + c * CH;
    float csLast = acsd[acsbase + CH - 1];
    {
        int row = b * L_ + c * CH + tid;
        wrow[tid] = dtd[(size_t)row * NH + h] * __expf(csLast - acsd[acsbase + tid]);
    }
    __syncthreads();
    float acc[2][4][4] = {};
    for (int s0 = 0; s0 < CH; s0 += 32) {
#pragma unroll
        for (int i = 0; i < 8; i++) {
            int e = tid + i * 256;
            int pp = e & 63, ss = e >> 6;
            int row = b * L_ + c * CH + s0 + ss;
            Xs[ss][pp] = tf32v(xbcd[(size_t)row * CD + h * HD + pp] * wrow[s0 + ss]);
        }
#pragma unroll
        for (int i = 0; i < 16; i++) {
            int e = tid + i * 256;
            int nn = e & 127, ss = e >> 7;
            int row = b * L_ + c * CH + s0 + ss;
            Bs[ss][nn] = tf32v(xbcd[(size_t)row * CD + DI + nn]);
        }
        __syncthreads();
#pragma unroll
        for (int ks = 0; ks < 4; ks++) {
            int k0 = ks * 8;
            uint32_t af[2][4], bf[4][2];
#pragma unroll
            for (int mf = 0; mf < 2; mf++) {
                int rm = wm * 32 + mf * 16 + group;
                af[mf][0] = __float_as_uint(Xs[k0 + tig    ][rm]);
                af[mf][1] = __float_as_uint(Xs[k0 + tig    ][rm + 8]);
                af[mf][2] = __float_as_uint(Xs[k0 + tig + 4][rm]);
                af[mf][3] = __float_as_uint(Xs[k0 + tig + 4][rm + 8]);
            }
#pragma unroll
            for (int nf = 0; nf < 4; nf++) {
                int rn = wn * 32 + nf * 8 + group;
                bf[nf][0] = __float_as_uint(Bs[k0 + tig    ][rn]);
                bf[nf][1] = __float_as_uint(Bs[k0 + tig + 4][rn]);
            }
#pragma unroll
            for (int mf = 0; mf < 2; mf++)
#pragma unroll
                for (int nf = 0; nf < 4; nf++) MMA_TF32(acc[mf][nf], af[mf], bf[nf]);
        }
        __syncthreads();
    }
    float* base = st + dir * SZ_ST + (size_t)((b * NC + c) * NH + h) * HD * DS;
#pragma unroll
    for (int mf = 0; mf < 2; mf++) {
#pragma unroll
        for (int nf = 0; nf < 4; nf++) {
            int gm = wm * 32 + mf * 16 + group;
            int gn = wn * 32 + nf * 8 + 2 * tig;
            *reinterpret_cast<float2*>(base + gm * DS + gn) =
                make_float2(acc[mf][nf][0], acc[mf][nf][1]);
            *reinterpret_cast<float2*>(base + (gm + 8) * DS + gn) =
                make_float2(acc[mf][nf][2], acc[mf][nf][3]);
        }
    }
}

// ---------------- inter-chunk recurrence ----------------
__global__ void chunkscan_k(const float* __restrict__ st, const float* __restrict__ acs,
                            float* __restrict__ pv) {
    int idx = blockIdx.x * blockDim.x + threadIdx.x;
    int n = idx & (DS - 1);
    int p = (idx >> 7) & (HD - 1);
    int h = (idx >> 13) & (NH - 1);
    int b = (idx >> 17) & (B_ - 1);
    int dir = idx >> 18;
    const float* std_ = st + dir * SZ_ST;
    const float* acsd = acs + dir * SZ_ACS;
    float* pvd = pv + dir * SZ_ST;
    float S = 0.f;
    for (int c = 0; c < NC; c++) {
        size_t off = ((size_t)((b * NC + c) * NH + h) * HD + p) * DS + n;
        pvd[off] = S;
        float at = acsd[(b * NH + h) * L_ + c * CH + CH - 1];
        S = S * expf(at) + std_[off];
    }
}

// ---------------- Y via tf32 mma, fully precomputed decay ----------------
__global__ void __launch_bounds__(256)
ssd_y_mma_k(const float* __restrict__ xbc, const float* __restrict__ dt,
            const float* __restrict__ acs, const float* __restrict__ cb,
            const float* __restrict__ pv,
            const float* __restrict__ Dh0, const float* __restrict__ Dh1,
            float* __restrict__ y) {
    int lt = blockIdx.x, h = blockIdx.y;
    int dir = blockIdx.z / (B_ * NC);
    int bc = blockIdx.z % (B_ * NC);
    int c = bc % NC, b = bc / NC;
    const float* xbcd = xbc + dir * SZ_XBC;
    const float* dtd  = dt  + dir * SZ_DT;
    const float* acsd = acs + dir * SZ_ACS;
    const float* Dh   = dir ? Dh1 : Dh0;
    int tid = threadIdx.x;
    int warp = tid >> 5, lane = tid & 31;
    int wm = warp >> 2, wn = warp & 3;
    int group = lane >> 2, tig = lane & 3;
    __shared__ float Ws[64][36];
    __shared__ float Xs[32][72];
    __shared__ float Ps[64][36];
    __shared__ float csl[64], el64[64], eoff[64];
    __shared__ float einv[CH];
    int l0 = lt * 64;
    int acsbase = (b * NH + h) * L_ + c * CH;
    float csl0 = acsd[acsbase + l0];
    if (tid < 64) {
        float v = acsd[acsbase + l0 + tid];
        csl[tid]  = v;
        el64[tid] = __expf(v - csl0);
        eoff[tid] = __expf(v);
    }
    einv[tid] = __expf(csl0 - acsd[acsbase + tid]);
    __syncthreads();
    const float* cbb = cb + dir * SZ_CB + (size_t)(b * NC + c) * CH * CH;
    float acc[2][2][4] = {};
    int nst = 2 * lt + 2;
    for (int stp = 0; stp < nst; stp++) {
        int s0 = stp * 32;
        bool lower = (s0 + 31 < l0);
        if (lower) {
#pragma unroll
            for (int i = 0; i < 8; i++) {
                int e = tid + i * 256;
                int j = e & 31, ii = e >> 5;
                Ws[ii][j] = tf32v(el64[ii] * einv[s0 + j] * cbb[(l0 + ii) * CH + s0 + j]);
            }
        } else {
#pragma unroll
            for (int i = 0; i < 8; i++) {
                int e = tid + i * 256;
                int j = e & 31, ii = e >> 5;
                float w = 0.f;
                if (s0 + j <= l0 + ii)
                    w = __expf(csl[ii] - acsd[acsbase + s0 + j]) * cbb[(l0 + ii) * CH + s0 + j];
                Ws[ii][j] = tf32v(w);
            }
        }
#pragma unroll
        for (int i = 0; i < 8; i++) {
            int e = tid + i * 256;
            int pp = e & 63, ss = e >> 6;
            int row = b * L_ + c * CH + s0 + ss;
            Xs[ss][pp] = tf32v(xbcd[(size_t)row * CD + h * HD + pp] * dtd[(size_t)row * NH + h]);
        }
        __syncthreads();
#pragma unroll
        for (int ks = 0; ks < 4; ks++) {
            int k0 = ks * 8;
            uint32_t af[2][4], bf[2][2];
#pragma unroll
            for (int mf = 0; mf < 2; mf++) {
                int rm = wm * 32 + mf * 16 + group;
                af[mf][0] = __float_as_uint(Ws[rm    ][k0 + tig]);
                af[mf][1] = __float_as_uint(Ws[rm + 8][k0 + tig]);
                af[mf][2] = __float_as_uint(Ws[rm    ][k0 + tig + 4]);
                af[mf][3] = __float_as_uint(Ws[rm + 8][k0 + tig + 4]);
            }
#pragma unroll
            for (int nf = 0; nf < 2; nf++) {
                int rn = wn * 16 + nf * 8 + group;
                bf[nf][0] = __float_as_uint(Xs[k0 + tig    ][rn]);
                bf[nf][1] = __float_as_uint(Xs[k0 + tig + 4][rn]);
            }
#pragma unroll
            for (int mf = 0; mf < 2; mf++)
#pragma unroll
                for (int nf = 0; nf < 2; nf++) MMA_TF32(acc[mf][nf], af[mf], bf[nf]);
        }
        __syncthreads();
    }
    const float* pvb = pv + dir * SZ_ST + (size_t)((b * NC + c) * NH + h) * HD * DS;
    for (int nt = 0; nt < 4; nt++) {
        int n0 = nt * 32;
#pragma unroll
        for (int i = 0; i < 8; i++) {
            int e = tid + i * 256;
            int j = e & 31, ii = e >> 5;
            int row = b * L_ + c * CH + l0 + ii;
            Ws[ii][j] = tf32v(xbcd[(size_t)row * CD + DI + DS + n0 + j] * eoff[ii]);
        }
#pragma unroll
        for (int i = 0; i < 8; i++) {
            int e = tid + i * 256;
            int j = e & 31, pp = e >> 5;
            Ps[pp][j] = tf32v(pvb[pp * DS + n0 + j]);
        }
        __syncthreads();
#pragma unroll
        for (int ks = 0; ks < 4; ks++) {
            int k0 = ks * 8;
            uint32_t af[2][4], bf[2][2];
#pragma unroll
            for (int mf = 0; mf < 2; mf++) {
                int rm = wm * 32 + mf * 16 + group;
                af[mf][0] = __float_as_uint(Ws[rm    ][k0 + tig]);
                af[mf][1] = __float_as_uint(Ws[rm + 8][k0 + tig]);
                af[mf][2] = __float_as_uint(Ws[rm    ][k0 + tig + 4]);
                af[mf][3] = __float_as_uint(Ws[rm + 8][k0 + tig + 4]);
            }
#pragma unroll
            for (int nf = 0; nf < 2; nf++) {
                int rn = wn * 16 + nf * 8 + group;
                bf[nf][0] = __float_as_uint(Ps[rn][k0 + tig]);
                bf[nf][1] = __float_as_uint(Ps[rn][k0 + tig + 4]);
            }
#pragma unroll
            for (int mf = 0; mf < 2; mf++)
#pragma unroll
                for (int nf = 0; nf < 2; nf++) MMA_TF32(acc[mf][nf], af[mf], bf[nf]);
        }
        __syncthreads();
    }
    float dh = Dh[h];
    float* yd = y + dir * SZ_Y;
#pragma unroll
    for (int mf = 0; mf < 2; mf++) {
#pragma unroll
        for (int nf = 0; nf < 2; nf++) {
            int ll = l0 + wm * 32 + mf * 16 + group;
            int pp = wn * 16 + nf * 8 + 2 * tig;
#pragma unroll
            for (int rr = 0; rr < 2; rr++) {
                int row = b * L_ + c * CH + ll + rr * 8;
                float2 xr = *reinterpret_cast<const float2*>(
                    xbcd + (size_t)row * CD + h * HD + pp);
                *reinterpret_cast<float2*>(yd + (size_t)row * DI + h * HD + pp) =
                    make_float2(acc[mf][nf][rr * 2 + 0] + xr.x * dh,
                                acc[mf][nf][rr * 2 + 1] + xr.y * dh);
            }
        }
    }
}

// ---------------- gating + RMSNorm (float4) ----------------
__global__ void gate_rms_k(float* __restrict__ y, const float* __restrict__ zx,
                           const float* __restrict__ nw0, const float* __restrict__ nw1) {
    int row = blockIdx.x;
    int dir = row / (B_ * L_);
    row %= B_ * L_;
    const float* nw = dir ? nw1 : nw0;
    float* yd = y + dir * SZ_Y + (size_t)row * DI;
    const float* zxd = zx + dir * SZ_ZX + (size_t)row * DIP;
    int tid = threadIdx.x;
    float4 yv = *reinterpret_cast<const float4*>(yd + tid * 4);
    float4 zv = *reinterpret_cast<const float4*>(zxd + tid * 4);
    yv.x *= siluf(zv.x); yv.y *= siluf(zv.y); yv.z *= siluf(zv.z); yv.w *= siluf(zv.w);
    float ss = yv.x * yv.x + yv.y * yv.y + yv.z * yv.z + yv.w * yv.w;
    __shared__ float sh[256];
    sh[tid] = ss;
    __syncthreads();
    for (int o = 128; o > 0; o >>= 1) {
        if (tid < o) sh[tid] += sh[tid + o];
        __syncthreads();
    }
    float scale = rsqrtf(sh[0] / DI + RMS_EPS);
    float4 wv = *reinterpret_cast<const float4*>(nw + tid * 4);
    yv.x *= scale * wv.x; yv.y *= scale * wv.y; yv.z *= scale * wv.z; yv.w *= scale * wv.w;
    *reinterpret_cast<float4*>(yd + tid * 4) = yv;
}

// ---------------- launch ----------------
extern "C" void kernel_launch(void* const* d_in, const int* in_sizes, int n_in,
                              void* d_out, int out_size) {
    (void)in_sizes; (void)n_in; (void)out_size;
    const float* x      = (const float*)d_in[0];
    const float* gn_w   = (const float*)d_in[1];
    const float* gn_b   = (const float*)d_in[2];
    const float* proj_w = (const float*)d_in[3];
    const float* proj_b = (const float*)d_in[4];
    const float* fw[8], *bw[8];
    for (int i = 0; i < 8; i++) { fw[i] = (const float*)d_in[5 + i]; bw[i] = (const float*)d_in[13 + i]; }
    float* out = (float*)d_out;

    float *t_, *zx_, *xbc_, *dt_, *acs_, *cb_, *st_, *pv_, *y_, *r_, *part_, *stats_;
    cudaGetSymbolAddress((void**)&t_,    g_t);
    cudaGetSymbolAddress((void**)&zx_,   g_zx);
    cudaGetSymbolAddress((void**)&xbc_,  g_xbc);
    cudaGetSymbolAddress((void**)&dt_,   g_dt);
    cudaGetSymbolAddress((void**)&acs_,  g_acs);
    cudaGetSymbolAddress((void**)&cb_,   g_cb);
    cudaGetSymbolAddress((void**)&st_,   g_st);
    cudaGetSymbolAddress((void**)&pv_,   g_pv);
    cudaGetSymbolAddress((void**)&y_,    g_y);
    cudaGetSymbolAddress((void**)&r_,    g_r);
    cudaGetSymbolAddress((void**)&part_, g_part);
    cudaGetSymbolAddress((void**)&stats_,g_stats);

    // raise dynamic smem limit (idempotent host-side state; no stream work)
    static bool attr_done = false;
    if (!attr_done) {
        cudaFuncSetAttribute(gemm_tf32<0>, cudaFuncAttributeMaxDynamicSharedMemorySize, G_SMEM_BYTES);
        cudaFuncSetAttribute(gemm_tf32<1>, cudaFuncAttributeMaxDynamicSharedMemorySize, G_SMEM_BYTES);
        cudaFuncSetAttribute(gemm_tf32<2>, cudaFuncAttributeMaxDynamicSharedMemorySize, G_SMEM_BYTES);
        attr_done = true;
    }

    gn_part_k<<<dim3(64, B_), 256>>>(x, part_);
    gn_fin_k<<<B_, 64>>>(part_, stats_);
    gn_apply_k<<<dim3(L_ / 32, DM / 32, B_), dim3(32, 8)>>>(x, gn_w, gn_b, stats_, t_);

    gemm_tf32<0><<<dim3((DIP + 127) / 128, (B_ * L_) / 128, 2), 128, G_SMEM_BYTES>>>(
        t_, fw[0], bw[0], zx_, B_ * L_, DIP, DM, DM, DM, DIP,
        0, 0, 0, 1, 0, SZ_ZX, L_, nullptr, nullptr);

    conv_silu_k<<<(int)((2LL * B_ * (L_ / 4) * (CD / 4) + 255) / 256), 256>>>(
        zx_, fw[1], fw[2], bw[1], bw[2], xbc_);
    dt_scan_k<<<2 * B_ * NH * NC, CH>>>(zx_, fw[3], fw[4], bw[3], bw[4], dt_, acs_);

    gemm_tf32<0><<<dim3(CH / 128, CH / 128, 2 * B_ * NC), 128, G_SMEM_BYTES>>>(
        xbc_ + DI + DS, xbc_ + DI, xbc_ + SZ_XBC + DI, cb_, CH, CH, DS, CD, CD, CH,
        (long long)CH * CD, (long long)CH * CD, (long long)CH * CH,
        B_ * NC, SZ_XBC, SZ_CB, 0, nullptr, nullptr);

    states_mma_k<<<dim3(NH, NC, 2 * B_), 256>>>(xbc_, dt_, acs_, st_);
    chunkscan_k<<<(2 * B_ * NH * HD * DS) / 256, 256>>>(st_, acs_, pv_);
    ssd_y_mma_k<<<dim3(CH / 64, NH, 2 * B_ * NC), 256>>>(
        xbc_, dt_, acs_, cb_, pv_, fw[5], bw[5], y_);
    gate_rms_k<<<2 * B_ * L_, 256>>>(y_, zx_, fw[6], bw[6]);

    gemm_tf32<1><<<dim3(DM / 128, (B_ * L_) / 128, 2), 128, G_SMEM_BYTES>>>(
        y_, fw[7], bw[7], r_, B_ * L_, DM, DI, DI, DI, DM,
        0, 0, 0, 1, SZ_Y, 0, 0, t_, nullptr);

    gemm_tf32<2><<<dim3(DM / 128, (B_ * L_) / 128, 1), 128, G_SMEM_BYTES>>>(
        r_, proj_w, proj_w, out, B_ * L_, DM, 2 * DM, 2 * DM, 2 * DM, DM,
        0, 0, 0, 1, 0, 0, 0, x, proj_b);
}

// round 10
// speedup vs baseline: 1.2860x; 1.1345x over previous
#include <cuda_runtime.h>
#include <cuda_bf16.h>
#include <cuda_fp16.h>
#include <math.h>
#include <stdint.h>

// ---------------- problem constants ----------------
static const int B_   = 2;
static const int L_   = 2048;
static const int DM   = 256;
static const int DS   = 128;
static const int DI   = 1024;
static const int NH   = 16;
static const int HD   = 64;
static const int CD   = 1280;
static const int DIP  = 2320;
static const int CH   = 256;
static const int NC   = 8;
#define GN_EPS 1.1920928955078125e-07f
#define RMS_EPS 1e-5f

#define SZ_ZX   ((long long)B_*L_*DIP)
#define SZ_XBC  ((long long)B_*L_*CD)
#define SZ_DT   ((long long)B_*L_*NH)
#define SZ_ACS  ((long long)B_*NH*L_)
#define SZ_CB   ((long long)B_*NC*CH*CH)
#define SZ_ST   ((long long)B_*NC*NH*HD*DS)
#define SZ_Y    ((long long)B_*L_*DI)
#define SZ_BCH  ((long long)B_*L_*2*DS)

// ---------------- scratch ----------------
__device__ float  g_t    [B_*L_*DM];
__device__ __half g_th   [B_*L_*DM];
__device__ float  g_zx   [2*B_*L_*DIP];
__device__ float  g_xbc  [2*B_*L_*CD];
__device__ __half g_bch  [2*B_*L_*2*DS];
__device__ float  g_dt   [2*B_*L_*NH];
__device__ float  g_acs  [2*B_*NH*L_];
__device__ float  g_cb   [2*B_*NC*CH*CH];
__device__ float  g_st   [2*B_*NC*NH*HD*DS];
__device__ float  g_pv   [2*B_*NC*NH*HD*DS];
__device__ float  g_y    [2*B_*L_*DI];
__device__ __half g_yh   [2*B_*L_*DI];
__device__ __half g_rh   [B_*L_*2*DM];
__device__ __half g_wih  [2*DIP*DM];
__device__ __half g_woh  [2*DM*DI];
__device__ __half g_wph  [DM*2*DM];
__device__ float  g_part [B_*64*2];
__device__ float  g_stats[4];

__device__ __forceinline__ float siluf(float x) { return x / (1.f + __expf(-x)); }
__device__ __forceinline__ float softplusf(float x) { return x > 20.f ? x : log1pf(expf(x)); }
__device__ __forceinline__ uint32_t f2tf32(float x) {
    uint32_t r; asm("cvt.rna.tf32.f32 %0, %1;" : "=r"(r) : "f"(x)); return r;
}
__device__ __forceinline__ float tf32v(float x) { return __uint_as_float(f2tf32(x)); }

#define MMA_TF32(acc, a, b) \
    asm volatile( \
        "mma.sync.aligned.m16n8k8.row.col.f32.tf32.tf32.f32 " \
        "{%0,%1,%2,%3},{%4,%5,%6,%7},{%8,%9},{%0,%1,%2,%3};" \
        : "+f"((acc)[0]), "+f"((acc)[1]), "+f"((acc)[2]), "+f"((acc)[3]) \
        : "r"((a)[0]), "r"((a)[1]), "r"((a)[2]), "r"((a)[3]), \
          "r"((b)[0]), "r"((b)[1]))

#define MMA_F16(acc, a, b) \
    asm volatile( \
        "mma.sync.aligned.m16n8k16.row.col.f32.f16.f16.f32 " \
        "{%0,%1,%2,%3},{%4,%5,%6,%7},{%8,%9},{%0,%1,%2,%3};" \
        : "+f"((acc)[0]), "+f"((acc)[1]), "+f"((acc)[2]), "+f"((acc)[3]) \
        : "r"((a)[0]), "r"((a)[1]), "r"((a)[2]), "r"((a)[3]), \
          "r"((b)[0]), "r"((b)[1]))

__device__ __forceinline__ void cpa16(uint32_t dst, const void* src, bool valid) {
    int sz = valid ? 16 : 0;
    asm volatile("cp.async.cg.shared.global [%0], [%1], 16, %2;\n"
                 :: "r"(dst), "l"(src), "r"(sz));
}
#define CPA_COMMIT() asm volatile("cp.async.commit_group;\n" ::)
#define CPA_WAIT1()  asm volatile("cp.async.wait_group 1;\n" ::)

// ---------------- weight fp32->fp16 conversion (5 tensors, one kernel) ------
__global__ void cvt5_k(const float* __restrict__ a0, const float* __restrict__ a1,
                       const float* __restrict__ a2, const float* __restrict__ a3,
                       const float* __restrict__ a4,
                       __half* __restrict__ w_in, __half* __restrict__ w_out,
                       __half* __restrict__ w_pj) {
    const int N1 = DIP * DM, N2 = DM * DI, N3 = DM * 2 * DM;
    int i = blockIdx.x * blockDim.x + threadIdx.x;
    if (i < N1) w_in[i] = __float2half(a0[i]);
    else if (i < 2 * N1) w_in[i] = __float2half(a1[i - N1]);
    else {
        int j = i - 2 * N1;
        if (j < N2) w_out[j] = __float2half(a2[j]);
        else if (j < 2 * N2) w_out[j] = __float2half(a3[j - N2]);
        else { int k = j - 2 * N2; if (k < N3) w_pj[k] = __float2half(a4[k]); }
    }
}

// ---------------- GroupNorm stats ----------------
__global__ void gn_part_k(const float* __restrict__ x, float* __restrict__ part) {
    int b = blockIdx.y;
    const float* xb = x + (size_t)b * DM * L_;
    float s = 0.f, ss = 0.f;
    for (int i = blockIdx.x * blockDim.x + threadIdx.x; i < DM * L_; i += 64 * 256) {
        float v = xb[i]; s += v; ss += v * v;
    }
    __shared__ float sh[256], sh2[256];
    sh[threadIdx.x] = s; sh2[threadIdx.x] = ss;
    __syncthreads();
    for (int o = 128; o > 0; o >>= 1) {
        if ((int)threadIdx.x < o) { sh[threadIdx.x] += sh[threadIdx.x + o]; sh2[threadIdx.x] += sh2[threadIdx.x + o]; }
        __syncthreads();
    }
    if (threadIdx.x == 0) {
        part[(b * 64 + blockIdx.x) * 2 + 0] = sh[0];
        part[(b * 64 + blockIdx.x) * 2 + 1] = sh2[0];
    }
}

__global__ void gn_fin_k(const float* __restrict__ part, float* __restrict__ stats) {
    int b = blockIdx.x;
    __shared__ double sh[64], sh2[64];
    int i = threadIdx.x;
    sh[i]  = (double)part[(b * 64 + i) * 2 + 0];
    sh2[i] = (double)part[(b * 64 + i) * 2 + 1];
    __syncthreads();
    for (int o = 32; o > 0; o >>= 1) {
        if (i < o) { sh[i] += sh[i + o]; sh2[i] += sh2[i + o]; }
        __syncthreads();
    }
    if (i == 0) {
        double n = (double)DM * L_;
        double mu = sh[0] / n;
        double var = sh2[0] / n - mu * mu;
        stats[b * 2 + 0] = (float)mu;
        stats[b * 2 + 1] = rsqrtf((float)var + GN_EPS);
    }
}

// ---------------- GroupNorm apply + transpose (fp32 + fp16 outputs) ---------
__global__ void gn_apply_k(const float* __restrict__ x, const float* __restrict__ gw,
                           const float* __restrict__ gb, const float* __restrict__ stats,
                           float* __restrict__ t, __half* __restrict__ th) {
    int b = blockIdx.z;
    __shared__ float tile[32][33];
    int l0 = blockIdx.x * 32, d0 = blockIdx.y * 32;
    float mu = stats[b * 2], rs = stats[b * 2 + 1];
#pragma unroll
    for (int r = 0; r < 4; r++) {
        int d = d0 + threadIdx.y + r * 8;
        tile[threadIdx.y + r * 8][threadIdx.x] = x[((size_t)b * DM + d) * L_ + l0 + threadIdx.x];
    }
    __syncthreads();
    int d = d0 + threadIdx.x;
    float w = gw[d], bb = gb[d];
#pragma unroll
    for (int r = 0; r < 4; r++) {
        int l = l0 + threadIdx.y + r * 8;
        float v = (tile[threadIdx.x][threadIdx.y + r * 8] - mu) * rs * w + bb;
        t[((size_t)b * L_ + l) * DM + d] = v;
        th[((size_t)b * L_ + l) * DM + d] = __float2half(v);
    }
}

// ---- FP16 NT GEMM: 128x128 CTA tile, 4 warps (64x64), m16n8k16, 3-stage ----
#define GBM 128
#define GBN 128
#define HBK 32               // halves per k-iter
#define GST 3
#define GLDH 40              // smem row stride in halves (20 half2 -> conflict-free)
#define H_SMEM_BYTES (GST * (GBM + GBN) * GLDH * 2)

template<int MODE>
__global__ void __launch_bounds__(128, 2)
gemm_h(const __half* __restrict__ A, const __half* __restrict__ B0,
       const __half* __restrict__ B1, float* __restrict__ C,
       int M, int N, int K, int lda, int ldb, int ldc,
       long long sA, long long sB, long long sC,
       int zPerDir, long long dA, long long dC, int revL,
       const float* __restrict__ extra, const float* __restrict__ bias) {
    constexpr int T  = 128;
    constexpr int MF = 4;
    constexpr int NF = 8;
    extern __shared__ __half hsm[];
    __half* Asm = hsm;
    __half* Bsm = hsm + GST * GBM * GLDH;
    int z = blockIdx.z;
    int dir = z / zPerDir, zz = z % zPerDir;
    const __half* Ap = A + dir * dA + zz * sA;
    const __half* Bp = (dir ? B1 : B0) + zz * sB;
    float* Cp = C + dir * dC + zz * sC;
    int rev = dir ? revL : 0;
    int m0 = blockIdx.y * GBM, n0 = blockIdx.x * GBN;
    int tid = threadIdx.x;
    int warp = tid >> 5, lane = tid & 31;
    int wm = warp >> 1, wn = warp & 1;
    int group = lane >> 2, tig = lane & 3;
    float acc[MF][NF][4] = {};

    auto issue = [&](int k0, int s) {       // k0 in halves
        __half* As = Asm + s * GBM * GLDH;
        __half* Bs = Bsm + s * GBN * GLDH;
#pragma unroll
        for (int i = 0; i < 4; i++) {
            int e = tid + i * T;
            int mm = e >> 2;
            int kc = (e & 3) * 8;
            int gm = m0 + mm;
            int row = gm < M ? gm : 0;
            if (rev && gm < M) { int bb = gm / rev; int ll = gm % rev; row = bb * rev + (rev - 1 - ll); }
            cpa16((uint32_t)__cvta_generic_to_shared(As + mm * GLDH + kc),
                  Ap + (long long)row * lda + k0 + kc, gm < M);
        }
#pragma unroll
        for (int i = 0; i < 4; i++) {
            int e = tid + i * T;
            int nn = e >> 2;
            int kc = (e & 3) * 8;
            int gn = n0 + nn;
            int rowb = gn < N ? gn : 0;
            cpa16((uint32_t)__cvta_generic_to_shared(Bs + nn * GLDH + kc),
                  Bp + (long long)rowb * ldb + k0 + kc, gn < N);
        }
    };
    auto compute = [&](int s) {
        const __half2* As2 = reinterpret_cast<const __half2*>(Asm + s * GBM * GLDH);
        const __half2* Bs2 = reinterpret_cast<const __half2*>(Bsm + s * GBN * GLDH);
#pragma unroll
        for (int ks = 0; ks < 2; ks++) {     // two k16 steps per 32-half iter
            int k2 = ks * 8;
            uint32_t af[MF][4], bf[NF][2];
#pragma unroll
            for (int mf = 0; mf < MF; mf++) {
                int rm = wm * 64 + mf * 16 + group;
                af[mf][0] = *reinterpret_cast<const uint32_t*>(&As2[(rm    ) * 20 + k2 + tig]);
                af[mf][1] = *reinterpret_cast<const uint32_t*>(&As2[(rm + 8) * 20 + k2 + tig]);
                af[mf][2] = *reinterpret_cast<const uint32_t*>(&As2[(rm    ) * 20 + k2 + tig + 4]);
                af[mf][3] = *reinterpret_cast<const uint32_t*>(&As2[(rm + 8) * 20 + k2 + tig + 4]);
            }
#pragma unroll
            for (int nf = 0; nf < NF; nf++) {
                int rn = wn * 64 + nf * 8 + group;
                bf[nf][0] = *reinterpret_cast<const uint32_t*>(&Bs2[rn * 20 + k2 + tig]);
                bf[nf][1] = *reinterpret_cast<const uint32_t*>(&Bs2[rn * 20 + k2 + tig + 4]);
            }
#pragma unroll
            for (int mf = 0; mf < MF; mf++)
#pragma unroll
                for (int nf = 0; nf < NF; nf++) MMA_F16(acc[mf][nf], af[mf], bf[nf]);
        }
    };

    int nIter = K / HBK;
    issue(0, 0);
    CPA_COMMIT();
    if (nIter > 1) issue(HBK, 1);
    CPA_COMMIT();
    for (int it = 0; it < nIter; it++) {
        CPA_WAIT1();
        __syncthreads();
        if (it + 2 < nIter) issue((it + 2) * HBK, (it + 2) % GST);
        CPA_COMMIT();
        compute(it % GST);
    }

#pragma unroll
    for (int mf = 0; mf < MF; mf++) {
#pragma unroll
        for (int nf = 0; nf < NF; nf++) {
            int gn = n0 + wn * 64 + nf * 8 + 2 * tig;
#pragma unroll
            for (int rr = 0; rr < 2; rr++) {
                int gm = m0 + wm * 64 + mf * 16 + group + rr * 8;
                float a0 = acc[mf][nf][rr * 2 + 0], a1 = acc[mf][nf][rr * 2 + 1];
                if (MODE == 0) {
                    if (gm < M && gn < N)
                        *reinterpret_cast<float2*>(Cp + (long long)gm * ldc + gn) =
                            make_float2(a0, a1);
                } else if (MODE == 1) {
                    int b = gm / L_, l = gm % L_;
                    int ltm = dir ? (L_ - 1 - l) : l;
                    long long base = (long long)(b * L_ + ltm);
                    float2 tv = *reinterpret_cast<const float2*>(extra + base * DM + gn);
                    __half2* rp = reinterpret_cast<__half2*>(C);
                    rp[(base * (2 * DM) + dir * DM + gn) >> 1] =
                        __floats2half2_rn(a0 + tv.x, a1 + tv.y);
                } else {
                    int b = gm / L_, l = gm % L_;
                    long long i0 = ((long long)(b * DM + gn)) * L_ + l;
                    long long i1 = ((long long)(b * DM + gn + 1)) * L_ + l;
                    C[i0] = extra[i0] + bias[gn] + a0;
                    C[i1] = extra[i1] + bias[gn + 1] + a1;
                }
            }
        }
    }
}

// ---------------- depthwise conv + SiLU (4 l per thread, fp16 BC copy) ------
__global__ void conv_silu_k(const float* __restrict__ zx,
                            const float* __restrict__ cw0, const float* __restrict__ cb0,
                            const float* __restrict__ cw1, const float* __restrict__ cb1,
                            float* __restrict__ xbc, __half* __restrict__ bch) {
    long long idx = (long long)blockIdx.x * blockDim.x + threadIdx.x;
    if (idx >= 2LL * B_ * (L_ / 4) * (CD / 4)) return;
    int cg = idx % (CD / 4);
    int lb = (idx / (CD / 4)) % (L_ / 4);
    long long rest = idx / ((long long)(CD / 4) * (L_ / 4));
    int b = rest % B_;
    int dir = rest / B_;
    int l0 = lb * 4;
    const float* cw = (dir ? cw1 : cw0) + cg * 16;
    const float* cb = (dir ? cb1 : cb0) + cg * 4;
    const float* zxd = zx + dir * SZ_ZX + (size_t)(b * L_) * DIP + DI + cg * 4;
    float4 w0 = *reinterpret_cast<const float4*>(cw);
    float4 w1 = *reinterpret_cast<const float4*>(cw + 4);
    float4 w2 = *reinterpret_cast<const float4*>(cw + 8);
    float4 w3 = *reinterpret_cast<const float4*>(cw + 12);
    float4 bv = *reinterpret_cast<const float4*>(cb);
    float4 v[7];
#pragma unroll
    for (int r = 0; r < 7; r++) {
        int lp = l0 - 3 + r;
        v[r] = (lp >= 0) ? *reinterpret_cast<const float4*>(zxd + (size_t)lp * DIP)
                         : make_float4(0.f, 0.f, 0.f, 0.f);
    }
    float* outp = xbc + dir * SZ_XBC + ((size_t)(b * L_ + l0)) * CD + cg * 4;
    int bcoff = cg * 4 - DI;   // channel offset within BC region
#pragma unroll
    for (int j = 0; j < 4; j++) {
        float4 acc = bv;
#pragma unroll
        for (int k = 0; k < 4; k++) {
            float4 f = v[j + k];
            acc.x += ((const float*)&w0)[k] * f.x;
            acc.y += ((const float*)&w1)[k] * f.y;
            acc.z += ((const float*)&w2)[k] * f.z;
            acc.w += ((const float*)&w3)[k] * f.w;
        }
        acc.x = siluf(acc.x); acc.y = siluf(acc.y); acc.z = siluf(acc.z); acc.w = siluf(acc.w);
        *reinterpret_cast<float4*>(outp + (size_t)j * CD) = acc;
        if ((unsigned)bcoff < (unsigned)(2 * DS)) {
            __half2* bp = reinterpret_cast<__half2*>(
                bch + dir * SZ_BCH + ((size_t)(b * L_ + l0 + j)) * (2 * DS) + bcoff);
            bp[0] = __floats2half2_rn(acc.x, acc.y);
            bp[1] = __floats2half2_rn(acc.z, acc.w);
        }
    }
}

// ---------------- dt softplus + per-chunk cumsum (shuffle scan) -------------
__global__ void dt_scan_k(const float* __restrict__ zx,
                          const float* __restrict__ db0, const float* __restrict__ al0,
                          const float* __restrict__ db1, const float* __restrict__ al1,
                          float* __restrict__ dt, float* __restrict__ acs) {
    int bi = blockIdx.x;
    int dir = bi / (B_ * NH * NC);
    bi %= B_ * NH * NC;
    int c = bi % NC, h = (bi / NC) % NH, b = bi / (NC * NH);
    const float* dt_bias = dir ? db1 : db0;
    const float* A_log   = dir ? al1 : al0;
    int l = threadIdx.x;
    int lane = l & 31, warp = l >> 5;
    int gl = c * CH + l;
    int row = b * L_ + gl;
    float v = zx[dir * SZ_ZX + (size_t)row * DIP + (DIP - NH) + h] + dt_bias[h];
    float dtv = softplusf(v);
    dt[dir * SZ_DT + (size_t)row * NH + h] = dtv;
    float a = -expf(A_log[h]) * dtv;
#pragma unroll
    for (int o = 1; o < 32; o <<= 1) {
        float t = __shfl_up_sync(0xffffffff, a, o);
        if (lane >= o) a += t;
    }
    __shared__ float wsum[8];
    if (lane == 31) wsum[warp] = a;
    __syncthreads();
    float off = 0.f;
#pragma unroll
    for (int w = 0; w < 8; w++) if (w < warp) off += wsum[w];
    acs[dir * SZ_ACS + (size_t)(b * NH + h) * L_ + gl] = a + off;
}

// ---------------- per-chunk end state via tf32 mma ----------------
__global__ void __launch_bounds__(256)
states_mma_k(const float* __restrict__ xbc, const float* __restrict__ dt,
             const float* __restrict__ acs, float* __restrict__ st) {
    int h = blockIdx.x, c = blockIdx.y;
    int dir = blockIdx.z / B_, b = blockIdx.z % B_;
    const float* xbcd = xbc + dir * SZ_XBC;
    const float* dtd  = dt  + dir * SZ_DT;
    const float* acsd = acs + dir * SZ_ACS;
    int tid = threadIdx.x;
    int warp = tid >> 5, lane = tid & 31;
    int wm = warp >> 2, wn = warp & 3;
    int group = lane >> 2, tig = lane & 3;
    __shared__ float Xs[32][72];
    __shared__ float Bs[32][136];
    __shared__ float wrow[CH];
    int acsbase = (b * NH + h) * L_ + c * CH;
    float csLast = acsd[acsbase + CH - 1];
    {
        int row = b * L_ + c * CH + tid;
        wrow[tid] = dtd[(size_t)row * NH + h] * __expf(csLast - acsd[acsbase + tid]);
    }
    __syncthreads();
    float acc[2][4][4] = {};
    for (int s0 = 0; s0 < CH; s0 += 32) {
#pragma unroll
        for (int i = 0; i < 8; i++) {
            int e = tid + i * 256;
            int pp = e & 63, ss = e >> 6;
            int row = b * L_ + c * CH + s0 + ss;
            Xs[ss][pp] = tf32v(xbcd[(size_t)row * CD + h * HD + pp] * wrow[s0 + ss]);
        }
#pragma unroll
        for (int i = 0; i < 16; i++) {
            int e = tid + i * 256;
            int nn = e & 127, ss = e >> 7;
            int row = b * L_ + c * CH + s0 + ss;
            Bs[ss][nn] = tf32v(xbcd[(size_t)row * CD + DI + nn]);
        }
        __syncthreads();
#pragma unroll
        for (int ks = 0; ks < 4; ks++) {
            int k0 = ks * 8;
            uint32_t af[2][4], bf[4][2];
#pragma unroll
            for (int mf = 0; mf < 2; mf++) {
                int rm = wm * 32 + mf * 16 + group;
                af[mf][0] = __float_as_uint(Xs[k0 + tig    ][rm]);
                af[mf][1] = __float_as_uint(Xs[k0 + tig    ][rm + 8]);
                af[mf][2] = __float_as_uint(Xs[k0 + tig + 4][rm]);
                af[mf][3] = __float_as_uint(Xs[k0 + tig + 4][rm + 8]);
            }
#pragma unroll
            for (int nf = 0; nf < 4; nf++) {
                int rn = wn * 32 + nf * 8 + group;
                bf[nf][0] = __float_as_uint(Bs[k0 + tig    ][rn]);
                bf[nf][1] = __float_as_uint(Bs[k0 + tig + 4][rn]);
            }
#pragma unroll
            for (int mf = 0; mf < 2; mf++)
#pragma unroll
                for (int nf = 0; nf < 4; nf++) MMA_TF32(acc[mf][nf], af[mf], bf[nf]);
        }
        __syncthreads();
    }
    float* base = st + dir * SZ_ST + (size_t)((b * NC + c) * NH + h) * HD * DS;
#pragma unroll
    for (int mf = 0; mf < 2; mf++) {
#pragma unroll
        for (int nf = 0; nf < 4; nf++) {
            int gm = wm * 32 + mf * 16 + group;
            int gn = wn * 32 + nf * 8 + 2 * tig;
            *reinterpret_cast<float2*>(base + gm * DS + gn) =
                make_float2(acc[mf][nf][0], acc[mf][nf][1]);
            *reinterpret_cast<float2*>(base + (gm + 8) * DS + gn) =
                make_float2(acc[mf][nf][2], acc[mf][nf][3]);
        }
    }
}

// ---------------- inter-chunk recurrence ----------------
__global__ void chunkscan_k(const float* __restrict__ st, const float* __restrict__ acs,
                            float* __restrict__ pv) {
    int idx = blockIdx.x * blockDim.x + threadIdx.x;
    int n = idx & (DS - 1);
    int p = (idx >> 7) & (HD - 1);
    int h = (idx >> 13) & (NH - 1);
    int b = (idx >> 17) & (B_ - 1);
    int dir = idx >> 18;
    const float* std_ = st + dir * SZ_ST;
    const float* acsd = acs + dir * SZ_ACS;
    float* pvd = pv + dir * SZ_ST;
    float S = 0.f;
    for (int c = 0; c < NC; c++) {
        size_t off = ((size_t)((b * NC + c) * NH + h) * HD + p) * DS + n;
        pvd[off] = S;
        float at = acsd[(b * NH + h) * L_ + c * CH + CH - 1];
        S = S * expf(at) + std_[off];
    }
}

// ---------------- Y via tf32 mma, fully precomputed decay ----------------
__global__ void __launch_bounds__(256)
ssd_y_mma_k(const float* __restrict__ xbc, const float* __restrict__ dt,
            const float* __restrict__ acs, const float* __restrict__ cb,
            const float* __restrict__ pv,
            const float* __restrict__ Dh0, const float* __restrict__ Dh1,
            float* __restrict__ y) {
    int lt = blockIdx.x, h = blockIdx.y;
    int dir = blockIdx.z / (B_ * NC);
    int bc = blockIdx.z % (B_ * NC);
    int c = bc % NC, b = bc / NC;
    const float* xbcd = xbc + dir * SZ_XBC;
    const float* dtd  = dt  + dir * SZ_DT;
    const float* acsd = acs + dir * SZ_ACS;
    const float* Dh   = dir ? Dh1 : Dh0;
    int tid = threadIdx.x;
    int warp = tid >> 5, lane = tid & 31;
    int wm = warp >> 2, wn = warp & 3;
    int group = lane >> 2, tig = lane & 3;
    __shared__ float Ws[64][36];
    __shared__ float Xs[32][72];
    __shared__ float Ps[64][36];
    __shared__ float csl[64], el64[64], eoff[64];
    __shared__ float einv[CH];
    int l0 = lt * 64;
    int acsbase = (b * NH + h) * L_ + c * CH;
    float csl0 = acsd[acsbase + l0];
    if (tid < 64) {
        float v = acsd[acsbase + l0 + tid];
        csl[tid]  = v;
        el64[tid] = __expf(v - csl0);
        eoff[tid] = __expf(v);
    }
    einv[tid] = __expf(csl0 - acsd[acsbase + tid]);
    __syncthreads();
    const float* cbb = cb + dir * SZ_CB + (size_t)(b * NC + c) * CH * CH;
    float acc[2][2][4] = {};
    int nst = 2 * lt + 2;
    for (int stp = 0; stp < nst; stp++) {
        int s0 = stp * 32;
        bool lower = (s0 + 31 < l0);
        if (lower) {
#pragma unroll
            for (int i = 0; i < 8; i++) {
                int e = tid + i * 256;
                int j = e & 31, ii = e >> 5;
                Ws[ii][j] = tf32v(el64[ii] * einv[s0 + j] * cbb[(l0 + ii) * CH + s0 + j]);
            }
        } else {
#pragma unroll
            for (int i = 0; i < 8; i++) {
                int e = tid + i * 256;
                int j = e & 31, ii = e >> 5;
                float w = 0.f;
                if (s0 + j <= l0 + ii)
                    w = __expf(csl[ii] - acsd[acsbase + s0 + j]) * cbb[(l0 + ii) * CH + s0 + j];
                Ws[ii][j] = tf32v(w);
            }
        }
#pragma unroll
        for (int i = 0; i < 8; i++) {
            int e = tid + i * 256;
            int pp = e & 63, ss = e >> 6;
            int row = b * L_ + c * CH + s0 + ss;
            Xs[ss][pp] = tf32v(xbcd[(size_t)row * CD + h * HD + pp] * dtd[(size_t)row * NH + h]);
        }
        __syncthreads();
#pragma unroll
        for (int ks = 0; ks < 4; ks++) {
            int k0 = ks * 8;
            uint32_t af[2][4], bf[2][2];
#pragma unroll
            for (int mf = 0; mf < 2; mf++) {
                int rm = wm * 32 + mf * 16 + group;
                af[mf][0] = __float_as_uint(Ws[rm    ][k0 + tig]);
                af[mf][1] = __float_as_uint(Ws[rm + 8][k0 + tig]);
                af[mf][2] = __float_as_uint(Ws[rm    ][k0 + tig + 4]);
                af[mf][3] = __float_as_uint(Ws[rm + 8][k0 + tig + 4]);
            }
#pragma unroll
            for (int nf = 0; nf < 2; nf++) {
                int rn = wn * 16 + nf * 8 + group;
                bf[nf][0] = __float_as_uint(Xs[k0 + tig    ][rn]);
                bf[nf][1] = __float_as_uint(Xs[k0 + tig + 4][rn]);
            }
#pragma unroll
            for (int mf = 0; mf < 2; mf++)
#pragma unroll
                for (int nf = 0; nf < 2; nf++) MMA_TF32(acc[mf][nf], af[mf], bf[nf]);
        }
        __syncthreads();
    }
    const float* pvb = pv + dir * SZ_ST + (size_t)((b * NC + c) * NH + h) * HD * DS;
    for (int nt = 0; nt < 4; nt++) {
        int n0 = nt * 32;
#pragma unroll
        for (int i = 0; i < 8; i++) {
            int e = tid + i * 256;
            int j = e & 31, ii = e >> 5;
            int row = b * L_ + c * CH + l0 + ii;
            Ws[ii][j] = tf32v(xbcd[(size_t)row * CD + DI + DS + n0 + j] * eoff[ii]);
        }
#pragma unroll
        for (int i = 0; i < 8; i++) {
            int e = tid + i * 256;
            int j = e & 31, pp = e >> 5;
            Ps[pp][j] = tf32v(pvb[pp * DS + n0 + j]);
        }
        __syncthreads();
#pragma unroll
        for (int ks = 0; ks < 4; ks++) {
            int k0 = ks * 8;
            uint32_t af[2][4], bf[2][2];
#pragma unroll
            for (int mf = 0; mf < 2; mf++) {
                int rm = wm * 32 + mf * 16 + group;
                af[mf][0] = __float_as_uint(Ws[rm    ][k0 + tig]);
                af[mf][1] = __float_as_uint(Ws[rm + 8][k0 + tig]);
                af[mf][2] = __float_as_uint(Ws[rm    ][k0 + tig + 4]);
                af[mf][3] = __float_as_uint(Ws[rm + 8][k0 + tig + 4]);
            }
#pragma unroll
            for (int nf = 0; nf < 2; nf++) {
                int rn = wn * 16 + nf * 8 + group;
                bf[nf][0] = __float_as_uint(Ps[rn][k0 + tig]);
                bf[nf][1] = __float_as_uint(Ps[rn][k0 + tig + 4]);
            }
#pragma unroll
            for (int mf = 0; mf < 2; mf++)
#pragma unroll
                for (int nf = 0; nf < 2; nf++) MMA_TF32(acc[mf][nf], af[mf], bf[nf]);
        }
        __syncthreads();
    }
    float dh = Dh[h];
    float* yd = y + dir * SZ_Y;
#pragma unroll
    for (int mf = 0; mf < 2; mf++) {
#pragma unroll
        for (int nf = 0; nf < 2; nf++) {
            int ll = l0 + wm * 32 + mf * 16 + group;
            int pp = wn * 16 + nf * 8 + 2 * tig;
#pragma unroll
            for (int rr = 0; rr < 2; rr++) {
                int row = b * L_ + c * CH + ll + rr * 8;
                float2 xr = *reinterpret_cast<const float2*>(
                    xbcd + (size_t)row * CD + h * HD + pp);
                *reinterpret_cast<float2*>(yd + (size_t)row * DI + h * HD + pp) =
                    make_float2(acc[mf][nf][rr * 2 + 0] + xr.x * dh,
                                acc[mf][nf][rr * 2 + 1] + xr.y * dh);
            }
        }
    }
}

// ---------------- gating + RMSNorm -> fp16 output ----------------
__global__ void gate_rms_k(const float* __restrict__ y, const float* __restrict__ zx,
                           const float* __restrict__ nw0, const float* __restrict__ nw1,
                           __half* __restrict__ yh) {
    int row = blockIdx.x;
    int dir = row / (B_ * L_);
    row %= B_ * L_;
    const float* nw = dir ? nw1 : nw0;
    const float* yd = y + dir * SZ_Y + (size_t)row * DI;
    const float* zxd = zx + dir * SZ_ZX + (size_t)row * DIP;
    int tid = threadIdx.x;
    float4 yv = *reinterpret_cast<const float4*>(yd + tid * 4);
    float4 zv = *reinterpret_cast<const float4*>(zxd + tid * 4);
    yv.x *= siluf(zv.x); yv.y *= siluf(zv.y); yv.z *= siluf(zv.z); yv.w *= siluf(zv.w);
    float ss = yv.x * yv.x + yv.y * yv.y + yv.z * yv.z + yv.w * yv.w;
    __shared__ float sh[256];
    sh[tid] = ss;
    __syncthreads();
    for (int o = 128; o > 0; o >>= 1) {
        if (tid < o) sh[tid] += sh[tid + o];
        __syncthreads();
    }
    float scale = rsqrtf(sh[0] / DI + RMS_EPS);
    float4 wv = *reinterpret_cast<const float4*>(nw + tid * 4);
    __half2* yp = reinterpret_cast<__half2*>(yh + dir * SZ_Y + (size_t)row * DI) + tid * 2;
    yp[0] = __floats2half2_rn(yv.x * scale * wv.x, yv.y * scale * wv.y);
    yp[1] = __floats2half2_rn(yv.z * scale * wv.z, yv.w * scale * wv.w);
}

// ---------------- launch ----------------
extern "C" void kernel_launch(void* const* d_in, const int* in_sizes, int n_in,
                              void* d_out, int out_size) {
    (void)in_sizes; (void)n_in; (void)out_size;
    const float* x      = (const float*)d_in[0];
    const float* gn_w   = (const float*)d_in[1];
    const float* gn_b   = (const float*)d_in[2];
    const float* proj_w = (const float*)d_in[3];
    const float* proj_b = (const float*)d_in[4];
    const float* fw[8], *bw[8];
    for (int i = 0; i < 8; i++) { fw[i] = (const float*)d_in[5 + i]; bw[i] = (const float*)d_in[13 + i]; }
    float* out = (float*)d_out;

    float *t_, *zx_, *xbc_, *dt_, *acs_, *cb_, *st_, *pv_, *y_, *part_, *stats_;
    __half *th_, *bch_, *yh_, *rh_, *wih_, *woh_, *wph_;
    cudaGetSymbolAddress((void**)&t_,    g_t);
    cudaGetSymbolAddress((void**)&th_,   g_th);
    cudaGetSymbolAddress((void**)&zx_,   g_zx);
    cudaGetSymbolAddress((void**)&xbc_,  g_xbc);
    cudaGetSymbolAddress((void**)&bch_,  g_bch);
    cudaGetSymbolAddress((void**)&dt_,   g_dt);
    cudaGetSymbolAddress((void**)&acs_,  g_acs);
    cudaGetSymbolAddress((void**)&cb_,   g_cb);
    cudaGetSymbolAddress((void**)&st_,   g_st);
    cudaGetSymbolAddress((void**)&pv_,   g_pv);
    cudaGetSymbolAddress((void**)&y_,    g_y);
    cudaGetSymbolAddress((void**)&yh_,   g_yh);
    cudaGetSymbolAddress((void**)&rh_,   g_rh);
    cudaGetSymbolAddress((void**)&wih_,  g_wih);
    cudaGetSymbolAddress((void**)&woh_,  g_woh);
    cudaGetSymbolAddress((void**)&wph_,  g_wph);
    cudaGetSymbolAddress((void**)&part_, g_part);
    cudaGetSymbolAddress((void**)&stats_,g_stats);

    static bool attr_done = false;
    if (!attr_done) {
        cudaFuncSetAttribute(gemm_h<0>, cudaFuncAttributeMaxDynamicSharedMemorySize, H_SMEM_BYTES);
        cudaFuncSetAttribute(gemm_h<1>, cudaFuncAttributeMaxDynamicSharedMemorySize, H_SMEM_BYTES);
        cudaFuncSetAttribute(gemm_h<2>, cudaFuncAttributeMaxDynamicSharedMemorySize, H_SMEM_BYTES);
        attr_done = true;
    }

    // weight conversion (independent of data path)
    {
        int total = 2 * DIP * DM + 2 * DM * DI + DM * 2 * DM;
        cvt5_k<<<(total + 255) / 256, 256>>>(fw[0], bw[0], fw[7], bw[7], proj_w,
                                             wih_, woh_, wph_);
    }

    gn_part_k<<<dim3(64, B_), 256>>>(x, part_);
    gn_fin_k<<<B_, 64>>>(part_, stats_);
    gn_apply_k<<<dim3(L_ / 32, DM / 32, B_), dim3(32, 8)>>>(x, gn_w, gn_b, stats_, t_, th_);

    // in-projection (fp16 m16n8k16)
    gemm_h<0><<<dim3((DIP + 127) / 128, (B_ * L_) / 128, 2), 128, H_SMEM_BYTES>>>(
        th_, wih_, wih_ + (long long)DIP * DM, zx_, B_ * L_, DIP, DM, DM, DM, DIP,
        0, 0, 0, 1, 0, SZ_ZX, L_, nullptr, nullptr);

    conv_silu_k<<<(int)((2LL * B_ * (L_ / 4) * (CD / 4) + 255) / 256), 256>>>(
        zx_, fw[1], fw[2], bw[1], bw[2], xbc_, bch_);
    dt_scan_k<<<2 * B_ * NH * NC, CH>>>(zx_, fw[3], fw[4], bw[3], bw[4], dt_, acs_);

    // CB = C @ B^T per (dir,b,c) from fp16 BC buffer
    gemm_h<0><<<dim3(CH / 128, CH / 128, 2 * B_ * NC), 128, H_SMEM_BYTES>>>(
        bch_ + DS, bch_, bch_ + SZ_BCH, cb_, CH, CH, DS, 2 * DS, 2 * DS, CH,
        (long long)CH * 2 * DS, (long long)CH * 2 * DS, (long long)CH * CH,
        B_ * NC, SZ_BCH, SZ_CB, 0, nullptr, nullptr);

    states_mma_k<<<dim3(NH, NC, 2 * B_), 256>>>(xbc_, dt_, acs_, st_);
    chunkscan_k<<<(2 * B_ * NH * HD * DS) / 256, 256>>>(st_, acs_, pv_);
    ssd_y_mma_k<<<dim3(CH / 64, NH, 2 * B_ * NC), 256>>>(
        xbc_, dt_, acs_, cb_, pv_, fw[5], bw[5], y_);
    gate_rms_k<<<2 * B_ * L_, 256>>>(y_, zx_, fw[6], bw[6], yh_);

    // out-projection (fp16), fused epilogue -> r (fp16)
    gemm_h<1><<<dim3(DM / 128, (B_ * L_) / 128, 2), 128, H_SMEM_BYTES>>>(
        yh_, woh_, woh_ + (long long)DM * DI, (float*)rh_, B_ * L_, DM, DI, DI, DI, DM,
        0, 0, 0, 1, SZ_Y, 0, 0, t_, nullptr);

    // final projection (fp16), fused epilogue (transpose + x + bias)
    gemm_h<2><<<dim3(DM / 128, (B_ * L_) / 128, 1), 128, H_SMEM_BYTES>>>(
        rh_, wph_, wph_, out, B_ * L_, DM, 2 * DM, 2 * DM, 2 * DM, DM,
        0, 0, 0, 1, 0, 0, 0, x, proj_b);
}

// round 11
// speedup vs baseline: 1.3704x; 1.0656x over previous
#include <cuda_runtime.h>
#include <cuda_bf16.h>
#include <cuda_fp16.h>
#include <math.h>
#include <stdint.h>

// ---------------- problem constants ----------------
static const int B_   = 2;
static const int L_   = 2048;
static const int DM   = 256;
static const int DS   = 128;
static const int DI   = 1024;
static const int NH   = 16;
static const int HD   = 64;
static const int CD   = 1280;
static const int DIP  = 2320;
static const int CH   = 256;
static const int NC   = 8;
#define GN_EPS 1.1920928955078125e-07f
#define RMS_EPS 1e-5f

#define SZ_ZX   ((long long)B_*L_*DIP)
#define SZ_XBC  ((long long)B_*L_*CD)
#define SZ_DT   ((long long)B_*L_*NH)
#define SZ_ACS  ((long long)B_*NH*L_)
#define SZ_CB   ((long long)B_*NC*CH*CH)
#define SZ_ST   ((long long)B_*NC*NH*HD*DS)
#define SZ_Y    ((long long)B_*L_*DI)
#define SZ_BCH  ((long long)B_*L_*2*DS)

// ---------------- scratch ----------------
__device__ float  g_t    [B_*L_*DM];
__device__ __half g_th   [B_*L_*DM];
__device__ float  g_zx   [2*B_*L_*DIP];
__device__ float  g_xbc  [2*B_*L_*CD];
__device__ __half g_bch  [2*B_*L_*2*DS];
__device__ float  g_dt   [2*B_*L_*NH];
__device__ float  g_acs  [2*B_*NH*L_];
__device__ float  g_cb   [2*B_*NC*CH*CH];
__device__ float  g_st   [2*B_*NC*NH*HD*DS];
__device__ float  g_pv   [2*B_*NC*NH*HD*DS];
__device__ float  g_y    [2*B_*L_*DI];
__device__ __half g_yh   [2*B_*L_*DI];
__device__ __half g_rh   [B_*L_*2*DM];
__device__ __half g_wih  [2*DIP*DM];
__device__ __half g_woh  [2*DM*DI];
__device__ __half g_wph  [DM*2*DM];
__device__ float  g_part [B_*64*2];
__device__ float  g_stats[4];

__device__ __forceinline__ float siluf(float x) { return x / (1.f + __expf(-x)); }
__device__ __forceinline__ float softplusf(float x) { return x > 20.f ? x : log1pf(expf(x)); }

#define MMA_F16(acc, a, b) \
    asm volatile( \
        "mma.sync.aligned.m16n8k16.row.col.f32.f16.f16.f32 " \
        "{%0,%1,%2,%3},{%4,%5,%6,%7},{%8,%9},{%0,%1,%2,%3};" \
        : "+f"((acc)[0]), "+f"((acc)[1]), "+f"((acc)[2]), "+f"((acc)[3]) \
        : "r"((a)[0]), "r"((a)[1]), "r"((a)[2]), "r"((a)[3]), \
          "r"((b)[0]), "r"((b)[1]))

__device__ __forceinline__ void cpa16(uint32_t dst, const void* src, bool valid) {
    int sz = valid ? 16 : 0;
    asm volatile("cp.async.cg.shared.global [%0], [%1], 16, %2;\n"
                 :: "r"(dst), "l"(src), "r"(sz));
}
#define CPA_COMMIT() asm volatile("cp.async.commit_group;\n" ::)
#define CPA_WAIT1()  asm volatile("cp.async.wait_group 1;\n" ::)

// ---------------- weight fp32->fp16 conversion ----------------
__global__ void cvt5_k(const float* __restrict__ a0, const float* __restrict__ a1,
                       const float* __restrict__ a2, const float* __restrict__ a3,
                       const float* __restrict__ a4,
                       __half* __restrict__ w_in, __half* __restrict__ w_out,
                       __half* __restrict__ w_pj) {
    const int N1 = DIP * DM, N2 = DM * DI, N3 = DM * 2 * DM;
    int i = blockIdx.x * blockDim.x + threadIdx.x;
    if (i < N1) w_in[i] = __float2half(a0[i]);
    else if (i < 2 * N1) w_in[i] = __float2half(a1[i - N1]);
    else {
        int j = i - 2 * N1;
        if (j < N2) w_out[j] = __float2half(a2[j]);
        else if (j < 2 * N2) w_out[j] = __float2half(a3[j - N2]);
        else { int k = j - 2 * N2; if (k < N3) w_pj[k] = __float2half(a4[k]); }
    }
}

// ---------------- GroupNorm stats ----------------
__global__ void gn_part_k(const float* __restrict__ x, float* __restrict__ part) {
    int b = blockIdx.y;
    const float* xb = x + (size_t)b * DM * L_;
    float s = 0.f, ss = 0.f;
    for (int i = blockIdx.x * blockDim.x + threadIdx.x; i < DM * L_; i += 64 * 256) {
        float v = xb[i]; s += v; ss += v * v;
    }
    __shared__ float sh[256], sh2[256];
    sh[threadIdx.x] = s; sh2[threadIdx.x] = ss;
    __syncthreads();
    for (int o = 128; o > 0; o >>= 1) {
        if ((int)threadIdx.x < o) { sh[threadIdx.x] += sh[threadIdx.x + o]; sh2[threadIdx.x] += sh2[threadIdx.x + o]; }
        __syncthreads();
    }
    if (threadIdx.x == 0) {
        part[(b * 64 + blockIdx.x) * 2 + 0] = sh[0];
        part[(b * 64 + blockIdx.x) * 2 + 1] = sh2[0];
    }
}

__global__ void gn_fin_k(const float* __restrict__ part, float* __restrict__ stats) {
    int b = blockIdx.x;
    __shared__ double sh[64], sh2[64];
    int i = threadIdx.x;
    sh[i]  = (double)part[(b * 64 + i) * 2 + 0];
    sh2[i] = (double)part[(b * 64 + i) * 2 + 1];
    __syncthreads();
    for (int o = 32; o > 0; o >>= 1) {
        if (i < o) { sh[i] += sh[i + o]; sh2[i] += sh2[i + o]; }
        __syncthreads();
    }
    if (i == 0) {
        double n = (double)DM * L_;
        double mu = sh[0] / n;
        double var = sh2[0] / n - mu * mu;
        stats[b * 2 + 0] = (float)mu;
        stats[b * 2 + 1] = rsqrtf((float)var + GN_EPS);
    }
}

// ---------------- GroupNorm apply + transpose (fp32 + fp16 outputs) ---------
__global__ void gn_apply_k(const float* __restrict__ x, const float* __restrict__ gw,
                           const float* __restrict__ gb, const float* __restrict__ stats,
                           float* __restrict__ t, __half* __restrict__ th) {
    int b = blockIdx.z;
    __shared__ float tile[32][33];
    int l0 = blockIdx.x * 32, d0 = blockIdx.y * 32;
    float mu = stats[b * 2], rs = stats[b * 2 + 1];
#pragma unroll
    for (int r = 0; r < 4; r++) {
        int d = d0 + threadIdx.y + r * 8;
        tile[threadIdx.y + r * 8][threadIdx.x] = x[((size_t)b * DM + d) * L_ + l0 + threadIdx.x];
    }
    __syncthreads();
    int d = d0 + threadIdx.x;
    float w = gw[d], bb = gb[d];
#pragma unroll
    for (int r = 0; r < 4; r++) {
        int l = l0 + threadIdx.y + r * 8;
        float v = (tile[threadIdx.x][threadIdx.y + r * 8] - mu) * rs * w + bb;
        t[((size_t)b * L_ + l) * DM + d] = v;
        th[((size_t)b * L_ + l) * DM + d] = __float2half(v);
    }
}

// ---- FP16 NT GEMM: 128x128 CTA tile, 4 warps (64x64), m16n8k16, 3-stage ----
#define GBM 128
#define GBN 128
#define HBK 32
#define GST 3
#define GLDH 40
#define H_SMEM_BYTES (GST * (GBM + GBN) * GLDH * 2)

template<int MODE>
__global__ void __launch_bounds__(128, 2)
gemm_h(const __half* __restrict__ A, const __half* __restrict__ B0,
       const __half* __restrict__ B1, float* __restrict__ C,
       int M, int N, int K, int lda, int ldb, int ldc,
       long long sA, long long sB, long long sC,
       int zPerDir, long long dA, long long dC, int revL,
       const float* __restrict__ extra, const float* __restrict__ bias) {
    constexpr int T  = 128;
    constexpr int MF = 4;
    constexpr int NF = 8;
    extern __shared__ __half hsm[];
    __half* Asm = hsm;
    __half* Bsm = hsm + GST * GBM * GLDH;
    int z = blockIdx.z;
    int dir = z / zPerDir, zz = z % zPerDir;
    const __half* Ap = A + dir * dA + zz * sA;
    const __half* Bp = (dir ? B1 : B0) + zz * sB;
    float* Cp = C + dir * dC + zz * sC;
    int rev = dir ? revL : 0;
    int m0 = blockIdx.y * GBM, n0 = blockIdx.x * GBN;
    int tid = threadIdx.x;
    int warp = tid >> 5, lane = tid & 31;
    int wm = warp >> 1, wn = warp & 1;
    int group = lane >> 2, tig = lane & 3;
    float acc[MF][NF][4] = {};

    auto issue = [&](int k0, int s) {
        __half* As = Asm + s * GBM * GLDH;
        __half* Bs = Bsm + s * GBN * GLDH;
#pragma unroll
        for (int i = 0; i < 4; i++) {
            int e = tid + i * T;
            int mm = e >> 2;
            int kc = (e & 3) * 8;
            int gm = m0 + mm;
            int row = gm < M ? gm : 0;
            if (rev && gm < M) { int bb = gm / rev; int ll = gm % rev; row = bb * rev + (rev - 1 - ll); }
            cpa16((uint32_t)__cvta_generic_to_shared(As + mm * GLDH + kc),
                  Ap + (long long)row * lda + k0 + kc, gm < M);
        }
#pragma unroll
        for (int i = 0; i < 4; i++) {
            int e = tid + i * T;
            int nn = e >> 2;
            int kc = (e & 3) * 8;
            int gn = n0 + nn;
            int rowb = gn < N ? gn : 0;
            cpa16((uint32_t)__cvta_generic_to_shared(Bs + nn * GLDH + kc),
                  Bp + (long long)rowb * ldb + k0 + kc, gn < N);
        }
    };
    auto compute = [&](int s) {
        const __half2* As2 = reinterpret_cast<const __half2*>(Asm + s * GBM * GLDH);
        const __half2* Bs2 = reinterpret_cast<const __half2*>(Bsm + s * GBN * GLDH);
#pragma unroll
        for (int ks = 0; ks < 2; ks++) {
            int k2 = ks * 8;
            uint32_t af[MF][4], bf[NF][2];
#pragma unroll
            for (int mf = 0; mf < MF; mf++) {
                int rm = wm * 64 + mf * 16 + group;
                af[mf][0] = *reinterpret_cast<const uint32_t*>(&As2[(rm    ) * 20 + k2 + tig]);
                af[mf][1] = *reinterpret_cast<const uint32_t*>(&As2[(rm + 8) * 20 + k2 + tig]);
                af[mf][2] = *reinterpret_cast<const uint32_t*>(&As2[(rm    ) * 20 + k2 + tig + 4]);
                af[mf][3] = *reinterpret_cast<const uint32_t*>(&As2[(rm + 8) * 20 + k2 + tig + 4]);
            }
#pragma unroll
            for (int nf = 0; nf < NF; nf++) {
                int rn = wn * 64 + nf * 8 + group;
                bf[nf][0] = *reinterpret_cast<const uint32_t*>(&Bs2[rn * 20 + k2 + tig]);
                bf[nf][1] = *reinterpret_cast<const uint32_t*>(&Bs2[rn * 20 + k2 + tig + 4]);
            }
#pragma unroll
            for (int mf = 0; mf < MF; mf++)
#pragma unroll
                for (int nf = 0; nf < NF; nf++) MMA_F16(acc[mf][nf], af[mf], bf[nf]);
        }
    };

    int nIter = K / HBK;
    issue(0, 0);
    CPA_COMMIT();
    if (nIter > 1) issue(HBK, 1);
    CPA_COMMIT();
    for (int it = 0; it < nIter; it++) {
        CPA_WAIT1();
        __syncthreads();
        if (it + 2 < nIter) issue((it + 2) * HBK, (it + 2) % GST);
        CPA_COMMIT();
        compute(it % GST);
    }

#pragma unroll
    for (int mf = 0; mf < MF; mf++) {
#pragma unroll
        for (int nf = 0; nf < NF; nf++) {
            int gn = n0 + wn * 64 + nf * 8 + 2 * tig;
#pragma unroll
            for (int rr = 0; rr < 2; rr++) {
                int gm = m0 + wm * 64 + mf * 16 + group + rr * 8;
                float a0 = acc[mf][nf][rr * 2 + 0], a1 = acc[mf][nf][rr * 2 + 1];
                if (MODE == 0) {
                    if (gm < M && gn < N)
                        *reinterpret_cast<float2*>(Cp + (long long)gm * ldc + gn) =
                            make_float2(a0, a1);
                } else if (MODE == 1) {
                    int b = gm / L_, l = gm % L_;
                    int ltm = dir ? (L_ - 1 - l) : l;
                    long long base = (long long)(b * L_ + ltm);
                    float2 tv = *reinterpret_cast<const float2*>(extra + base * DM + gn);
                    __half2* rp = reinterpret_cast<__half2*>(C);
                    rp[(base * (2 * DM) + dir * DM + gn) >> 1] =
                        __floats2half2_rn(a0 + tv.x, a1 + tv.y);
                } else {
                    int b = gm / L_, l = gm % L_;
                    long long i0 = ((long long)(b * DM + gn)) * L_ + l;
                    long long i1 = ((long long)(b * DM + gn + 1)) * L_ + l;
                    C[i0] = extra[i0] + bias[gn] + a0;
                    C[i1] = extra[i1] + bias[gn + 1] + a1;
                }
            }
        }
    }
}

// ---------------- depthwise conv + SiLU (4 l per thread, fp16 BC copy) ------
__global__ void conv_silu_k(const float* __restrict__ zx,
                            const float* __restrict__ cw0, const float* __restrict__ cb0,
                            const float* __restrict__ cw1, const float* __restrict__ cb1,
                            float* __restrict__ xbc, __half* __restrict__ bch) {
    long long idx = (long long)blockIdx.x * blockDim.x + threadIdx.x;
    if (idx >= 2LL * B_ * (L_ / 4) * (CD / 4)) return;
    int cg = idx % (CD / 4);
    int lb = (idx / (CD / 4)) % (L_ / 4);
    long long rest = idx / ((long long)(CD / 4) * (L_ / 4));
    int b = rest % B_;
    int dir = rest / B_;
    int l0 = lb * 4;
    const float* cw = (dir ? cw1 : cw0) + cg * 16;
    const float* cb = (dir ? cb1 : cb0) + cg * 4;
    const float* zxd = zx + dir * SZ_ZX + (size_t)(b * L_) * DIP + DI + cg * 4;
    float4 w0 = *reinterpret_cast<const float4*>(cw);
    float4 w1 = *reinterpret_cast<const float4*>(cw + 4);
    float4 w2 = *reinterpret_cast<const float4*>(cw + 8);
    float4 w3 = *reinterpret_cast<const float4*>(cw + 12);
    float4 bv = *reinterpret_cast<const float4*>(cb);
    float4 v[7];
#pragma unroll
    for (int r = 0; r < 7; r++) {
        int lp = l0 - 3 + r;
        v[r] = (lp >= 0) ? *reinterpret_cast<const float4*>(zxd + (size_t)lp * DIP)
                         : make_float4(0.f, 0.f, 0.f, 0.f);
    }
    float* outp = xbc + dir * SZ_XBC + ((size_t)(b * L_ + l0)) * CD + cg * 4;
    int bcoff = cg * 4 - DI;
#pragma unroll
    for (int j = 0; j < 4; j++) {
        float4 acc = bv;
#pragma unroll
        for (int k = 0; k < 4; k++) {
            float4 f = v[j + k];
            acc.x += ((const float*)&w0)[k] * f.x;
            acc.y += ((const float*)&w1)[k] * f.y;
            acc.z += ((const float*)&w2)[k] * f.z;
            acc.w += ((const float*)&w3)[k] * f.w;
        }
        acc.x = siluf(acc.x); acc.y = siluf(acc.y); acc.z = siluf(acc.z); acc.w = siluf(acc.w);
        *reinterpret_cast<float4*>(outp + (size_t)j * CD) = acc;
        if ((unsigned)bcoff < (unsigned)(2 * DS)) {
            __half2* bp = reinterpret_cast<__half2*>(
                bch + dir * SZ_BCH + ((size_t)(b * L_ + l0 + j)) * (2 * DS) + bcoff);
            bp[0] = __floats2half2_rn(acc.x, acc.y);
            bp[1] = __floats2half2_rn(acc.z, acc.w);
        }
    }
}

// ---------------- dt softplus + per-chunk cumsum ----------------
__global__ void dt_scan_k(const float* __restrict__ zx,
                          const float* __restrict__ db0, const float* __restrict__ al0,
                          const float* __restrict__ db1, const float* __restrict__ al1,
                          float* __restrict__ dt, float* __restrict__ acs) {
    int bi = blockIdx.x;
    int dir = bi / (B_ * NH * NC);
    bi %= B_ * NH * NC;
    int c = bi % NC, h = (bi / NC) % NH, b = bi / (NC * NH);
    const float* dt_bias = dir ? db1 : db0;
    const float* A_log   = dir ? al1 : al0;
    int l = threadIdx.x;
    int lane = l & 31, warp = l >> 5;
    int gl = c * CH + l;
    int row = b * L_ + gl;
    float v = zx[dir * SZ_ZX + (size_t)row * DIP + (DIP - NH) + h] + dt_bias[h];
    float dtv = softplusf(v);
    dt[dir * SZ_DT + (size_t)row * NH + h] = dtv;
    float a = -expf(A_log[h]) * dtv;
#pragma unroll
    for (int o = 1; o < 32; o <<= 1) {
        float t = __shfl_up_sync(0xffffffff, a, o);
        if (lane >= o) a += t;
    }
    __shared__ float wsum[8];
    if (lane == 31) wsum[warp] = a;
    __syncthreads();
    float off = 0.f;
#pragma unroll
    for (int w = 0; w < 8; w++) if (w < warp) off += wsum[w];
    acs[dir * SZ_ACS + (size_t)(b * NH + h) * L_ + gl] = a + off;
}

// ---------------- per-chunk end state via fp16 mma ----------------
// st[p,n] = sum_l (x[l,p]*w[l]) * B[l,n]; 64x128, K=256, fp32 accumulate.
__global__ void __launch_bounds__(256)
states_mma_k(const float* __restrict__ xbc, const float* __restrict__ dt,
             const float* __restrict__ acs, float* __restrict__ st) {
    int h = blockIdx.x, c = blockIdx.y;
    int dir = blockIdx.z / B_, b = blockIdx.z % B_;
    const float* xbcd = xbc + dir * SZ_XBC;
    const float* dtd  = dt  + dir * SZ_DT;
    const float* acsd = acs + dir * SZ_ACS;
    int tid = threadIdx.x;
    int warp = tid >> 5, lane = tid & 31;
    int wm = warp >> 2, wn = warp & 3;   // 2 x 4
    int group = lane >> 2, tig = lane & 3;
    __shared__ __half Xs[64][GLDH];    // [p][l]
    __shared__ __half Bs[128][GLDH];   // [n][l]
    __shared__ float wrow[CH];
    int acsbase = (b * NH + h) * L_ + c * CH;
    float csLast = acsd[acsbase + CH - 1];
    {
        int row = b * L_ + c * CH + tid;
        wrow[tid] = dtd[(size_t)row * NH + h] * __expf(csLast - acsd[acsbase + tid]);
    }
    __syncthreads();
    float acc[2][4][4] = {};
    for (int s0 = 0; s0 < CH; s0 += 32) {
#pragma unroll
        for (int i = 0; i < 8; i++) {
            int e = tid + i * 256;
            int pp = e & 63, ss = e >> 6;
            int row = b * L_ + c * CH + s0 + ss;
            Xs[pp][ss] = __float2half(xbcd[(size_t)row * CD + h * HD + pp] * wrow[s0 + ss]);
        }
#pragma unroll
        for (int i = 0; i < 16; i++) {
            int e = tid + i * 256;
            int nn = e & 127, ss = e >> 7;
            int row = b * L_ + c * CH + s0 + ss;
            Bs[nn][ss] = __float2half(xbcd[(size_t)row * CD + DI + nn]);
        }
        __syncthreads();
        const __half2* Xs2 = reinterpret_cast<const __half2*>(&Xs[0][0]);
        const __half2* Bs2 = reinterpret_cast<const __half2*>(&Bs[0][0]);
#pragma unroll
        for (int ks = 0; ks < 2; ks++) {
            int k2 = ks * 8;
            uint32_t af[2][4], bf[4][2];
#pragma unroll
            for (int mf = 0; mf < 2; mf++) {
                int rm = wm * 32 + mf * 16 + group;
                af[mf][0] = *reinterpret_cast<const uint32_t*>(&Xs2[(rm    ) * 20 + k2 + tig]);
                af[mf][1] = *reinterpret_cast<const uint32_t*>(&Xs2[(rm + 8) * 20 + k2 + tig]);
                af[mf][2] = *reinterpret_cast<const uint32_t*>(&Xs2[(rm    ) * 20 + k2 + tig + 4]);
                af[mf][3] = *reinterpret_cast<const uint32_t*>(&Xs2[(rm + 8) * 20 + k2 + tig + 4]);
            }
#pragma unroll
            for (int nf = 0; nf < 4; nf++) {
                int rn = wn * 32 + nf * 8 + group;
                bf[nf][0] = *reinterpret_cast<const uint32_t*>(&Bs2[rn * 20 + k2 + tig]);
                bf[nf][1] = *reinterpret_cast<const uint32_t*>(&Bs2[rn * 20 + k2 + tig + 4]);
            }
#pragma unroll
            for (int mf = 0; mf < 2; mf++)
#pragma unroll
                for (int nf = 0; nf < 4; nf++) MMA_F16(acc[mf][nf], af[mf], bf[nf]);
        }
        __syncthreads();
    }
    float* base = st + dir * SZ_ST + (size_t)((b * NC + c) * NH + h) * HD * DS;
#pragma unroll
    for (int mf = 0; mf < 2; mf++) {
#pragma unroll
        for (int nf = 0; nf < 4; nf++) {
            int gm = wm * 32 + mf * 16 + group;
            int gn = wn * 32 + nf * 8 + 2 * tig;
            *reinterpret_cast<float2*>(base + gm * DS + gn) =
                make_float2(acc[mf][nf][0], acc[mf][nf][1]);
            *reinterpret_cast<float2*>(base + (gm + 8) * DS + gn) =
                make_float2(acc[mf][nf][2], acc[mf][nf][3]);
        }
    }
}

// ---------------- inter-chunk recurrence ----------------
__global__ void chunkscan_k(const float* __restrict__ st, const float* __restrict__ acs,
                            float* __restrict__ pv) {
    int idx = blockIdx.x * blockDim.x + threadIdx.x;
    int n = idx & (DS - 1);
    int p = (idx >> 7) & (HD - 1);
    int h = (idx >> 13) & (NH - 1);
    int b = (idx >> 17) & (B_ - 1);
    int dir = idx >> 18;
    const float* std_ = st + dir * SZ_ST;
    const float* acsd = acs + dir * SZ_ACS;
    float* pvd = pv + dir * SZ_ST;
    float S = 0.f;
    for (int c = 0; c < NC; c++) {
        size_t off = ((size_t)((b * NC + c) * NH + h) * HD + p) * DS + n;
        pvd[off] = S;
        float at = acsd[(b * NH + h) * L_ + c * CH + CH - 1];
        S = S * expf(at) + std_[off];
    }
}

// ---------------- Y via fp16 mma, precomputed decay ----------------
__global__ void __launch_bounds__(256)
ssd_y_mma_k(const float* __restrict__ xbc, const float* __restrict__ dt,
            const float* __restrict__ acs, const float* __restrict__ cb,
            const float* __restrict__ pv,
            const float* __restrict__ Dh0, const float* __restrict__ Dh1,
            float* __restrict__ y) {
    int lt = blockIdx.x, h = blockIdx.y;
    int dir = blockIdx.z / (B_ * NC);
    int bc = blockIdx.z % (B_ * NC);
    int c = bc % NC, b = bc / NC;
    const float* xbcd = xbc + dir * SZ_XBC;
    const float* dtd  = dt  + dir * SZ_DT;
    const float* acsd = acs + dir * SZ_ACS;
    const float* Dh   = dir ? Dh1 : Dh0;
    int tid = threadIdx.x;
    int warp = tid >> 5, lane = tid & 31;
    int wm = warp >> 2, wn = warp & 3;   // 2(l) x 4(p)
    int group = lane >> 2, tig = lane & 3;
    __shared__ __half Ws[64][GLDH];    // [l][s] diag / [l][n] off-diag
    __shared__ __half Xs[64][GLDH];    // [p][s]
    __shared__ __half Ps[64][GLDH];    // [p][n]
    __shared__ float csl[64], el64[64], eoff[64];
    __shared__ float einv[CH];
    int l0 = lt * 64;
    int acsbase = (b * NH + h) * L_ + c * CH;
    float csl0 = acsd[acsbase + l0];
    if (tid < 64) {
        float v = acsd[acsbase + l0 + tid];
        csl[tid]  = v;
        el64[tid] = __expf(v - csl0);
        eoff[tid] = __expf(v);
    }
    einv[tid] = __expf(csl0 - acsd[acsbase + tid]);
    __syncthreads();
    const float* cbb = cb + dir * SZ_CB + (size_t)(b * NC + c) * CH * CH;
    float acc[2][2][4] = {};
    int nst = 2 * lt + 2;
    for (int stp = 0; stp < nst; stp++) {
        int s0 = stp * 32;
        bool lower = (s0 + 31 < l0);
        if (lower) {
#pragma unroll
            for (int i = 0; i < 8; i++) {
                int e = tid + i * 256;
                int j = e & 31, ii = e >> 5;
                Ws[ii][j] = __float2half(el64[ii] * einv[s0 + j] * cbb[(l0 + ii) * CH + s0 + j]);
            }
        } else {
#pragma unroll
            for (int i = 0; i < 8; i++) {
                int e = tid + i * 256;
                int j = e & 31, ii = e >> 5;
                float w = 0.f;
                if (s0 + j <= l0 + ii)
                    w = __expf(csl[ii] - acsd[acsbase + s0 + j]) * cbb[(l0 + ii) * CH + s0 + j];
                Ws[ii][j] = __float2half(w);
            }
        }
#pragma unroll
        for (int i = 0; i < 8; i++) {
            int e = tid + i * 256;
            int pp = e & 63, ss = e >> 6;
            int row = b * L_ + c * CH + s0 + ss;
            Xs[pp][ss] = __float2half(xbcd[(size_t)row * CD + h * HD + pp] * dtd[(size_t)row * NH + h]);
        }
        __syncthreads();
        const __half2* Ws2 = reinterpret_cast<const __half2*>(&Ws[0][0]);
        const __half2* Xs2 = reinterpret_cast<const __half2*>(&Xs[0][0]);
#pragma unroll
        for (int ks = 0; ks < 2; ks++) {
            int k2 = ks * 8;
            uint32_t af[2][4], bf[2][2];
#pragma unroll
            for (int mf = 0; mf < 2; mf++) {
                int rm = wm * 32 + mf * 16 + group;
                af[mf][0] = *reinterpret_cast<const uint32_t*>(&Ws2[(rm    ) * 20 + k2 + tig]);
                af[mf][1] = *reinterpret_cast<const uint32_t*>(&Ws2[(rm + 8) * 20 + k2 + tig]);
                af[mf][2] = *reinterpret_cast<const uint32_t*>(&Ws2[(rm    ) * 20 + k2 + tig + 4]);
                af[mf][3] = *reinterpret_cast<const uint32_t*>(&Ws2[(rm + 8) * 20 + k2 + tig + 4]);
            }
#pragma unroll
            for (int nf = 0; nf < 2; nf++) {
                int rn = wn * 16 + nf * 8 + group;
                bf[nf][0] = *reinterpret_cast<const uint32_t*>(&Xs2[rn * 20 + k2 + tig]);
                bf[nf][1] = *reinterpret_cast<const uint32_t*>(&Xs2[rn * 20 + k2 + tig + 4]);
            }
#pragma unroll
            for (int mf = 0; mf < 2; mf++)
#pragma unroll
                for (int nf = 0; nf < 2; nf++) MMA_F16(acc[mf][nf], af[mf], bf[nf]);
        }
        __syncthreads();
    }
    // off-diagonal: Y[l,p] += sum_n (C[l,n]*eoff[l]) * pv[p,n]
    const float* pvb = pv + dir * SZ_ST + (size_t)((b * NC + c) * NH + h) * HD * DS;
    for (int nt = 0; nt < 4; nt++) {
        int n0 = nt * 32;
#pragma unroll
        for (int i = 0; i < 8; i++) {
            int e = tid + i * 256;
            int j = e & 31, ii = e >> 5;
            int row = b * L_ + c * CH + l0 + ii;
            Ws[ii][j] = __float2half(xbcd[(size_t)row * CD + DI + DS + n0 + j] * eoff[ii]);
        }
#pragma unroll
        for (int i = 0; i < 8; i++) {
            int e = tid + i * 256;
            int j = e & 31, pp = e >> 5;
            Ps[pp][j] = __float2half(pvb[pp * DS + n0 + j]);
        }
        __syncthreads();
        const __half2* Ws2 = reinterpret_cast<const __half2*>(&Ws[0][0]);
        const __half2* Ps2 = reinterpret_cast<const __half2*>(&Ps[0][0]);
#pragma unroll
        for (int ks = 0; ks < 2; ks++) {
            int k2 = ks * 8;
            uint32_t af[2][4], bf[2][2];
#pragma unroll
            for (int mf = 0; mf < 2; mf++) {
                int rm = wm * 32 + mf * 16 + group;
                af[mf][0] = *reinterpret_cast<const uint32_t*>(&Ws2[(rm    ) * 20 + k2 + tig]);
                af[mf][1] = *reinterpret_cast<const uint32_t*>(&Ws2[(rm + 8) * 20 + k2 + tig]);
                af[mf][2] = *reinterpret_cast<const uint32_t*>(&Ws2[(rm    ) * 20 + k2 + tig + 4]);
                af[mf][3] = *reinterpret_cast<const uint32_t*>(&Ws2[(rm + 8) * 20 + k2 + tig + 4]);
            }
#pragma unroll
            for (int nf = 0; nf < 2; nf++) {
                int rn = wn * 16 + nf * 8 + group;
                bf[nf][0] = *reinterpret_cast<const uint32_t*>(&Ps2[rn * 20 + k2 + tig]);
                bf[nf][1] = *reinterpret_cast<const uint32_t*>(&Ps2[rn * 20 + k2 + tig + 4]);
            }
#pragma unroll
            for (int mf = 0; mf < 2; mf++)
#pragma unroll
                for (int nf = 0; nf < 2; nf++) MMA_F16(acc[mf][nf], af[mf], bf[nf]);
        }
        __syncthreads();
    }
    float dh = Dh[h];
    float* yd = y + dir * SZ_Y;
#pragma unroll
    for (int mf = 0; mf < 2; mf++) {
#pragma unroll
        for (int nf = 0; nf < 2; nf++) {
            int ll = l0 + wm * 32 + mf * 16 + group;
            int pp = wn * 16 + nf * 8 + 2 * tig;
#pragma unroll
            for (int rr = 0; rr < 2; rr++) {
                int row = b * L_ + c * CH + ll + rr * 8;
                float2 xr = *reinterpret_cast<const float2*>(
                    xbcd + (size_t)row * CD + h * HD + pp);
                *reinterpret_cast<float2*>(yd + (size_t)row * DI + h * HD + pp) =
                    make_float2(acc[mf][nf][rr * 2 + 0] + xr.x * dh,
                                acc[mf][nf][rr * 2 + 1] + xr.y * dh);
            }
        }
    }
}

// ---------------- gating + RMSNorm -> fp16 output ----------------
__global__ void gate_rms_k(const float* __restrict__ y, const float* __restrict__ zx,
                           const float* __restrict__ nw0, const float* __restrict__ nw1,
                           __half* __restrict__ yh) {
    int row = blockIdx.x;
    int dir = row / (B_ * L_);
    row %= B_ * L_;
    const float* nw = dir ? nw1 : nw0;
    const float* yd = y + dir * SZ_Y + (size_t)row * DI;
    const float* zxd = zx + dir * SZ_ZX + (size_t)row * DIP;
    int tid = threadIdx.x;
    float4 yv = *reinterpret_cast<const float4*>(yd + tid * 4);
    float4 zv = *reinterpret_cast<const float4*>(zxd + tid * 4);
    yv.x *= siluf(zv.x); yv.y *= siluf(zv.y); yv.z *= siluf(zv.z); yv.w *= siluf(zv.w);
    float ss = yv.x * yv.x + yv.y * yv.y + yv.z * yv.z + yv.w * yv.w;
    __shared__ float sh[256];
    sh[tid] = ss;
    __syncthreads();
    for (int o = 128; o > 0; o >>= 1) {
        if (tid < o) sh[tid] += sh[tid + o];
        __syncthreads();
    }
    float scale = rsqrtf(sh[0] / DI + RMS_EPS);
    float4 wv = *reinterpret_cast<const float4*>(nw + tid * 4);
    __half2* yp = reinterpret_cast<__half2*>(yh + dir * SZ_Y + (size_t)row * DI) + tid * 2;
    yp[0] = __floats2half2_rn(yv.x * scale * wv.x, yv.y * scale * wv.y);
    yp[1] = __floats2half2_rn(yv.z * scale * wv.z, yv.w * scale * wv.w);
}

// ---------------- launch ----------------
extern "C" void kernel_launch(void* const* d_in, const int* in_sizes, int n_in,
                              void* d_out, int out_size) {
    (void)in_sizes; (void)n_in; (void)out_size;
    const float* x      = (const float*)d_in[0];
    const float* gn_w   = (const float*)d_in[1];
    const float* gn_b   = (const float*)d_in[2];
    const float* proj_w = (const float*)d_in[3];
    const float* proj_b = (const float*)d_in[4];
    const float* fw[8], *bw[8];
    for (int i = 0; i < 8; i++) { fw[i] = (const float*)d_in[5 + i]; bw[i] = (const float*)d_in[13 + i]; }
    float* out = (float*)d_out;

    float *t_, *zx_, *xbc_, *dt_, *acs_, *cb_, *st_, *pv_, *y_, *part_, *stats_;
    __half *th_, *bch_, *yh_, *rh_, *wih_, *woh_, *wph_;
    cudaGetSymbolAddress((void**)&t_,    g_t);
    cudaGetSymbolAddress((void**)&th_,   g_th);
    cudaGetSymbolAddress((void**)&zx_,   g_zx);
    cudaGetSymbolAddress((void**)&xbc_,  g_xbc);
    cudaGetSymbolAddress((void**)&bch_,  g_bch);
    cudaGetSymbolAddress((void**)&dt_,   g_dt);
    cudaGetSymbolAddress((void**)&acs_,  g_acs);
    cudaGetSymbolAddress((void**)&cb_,   g_cb);
    cudaGetSymbolAddress((void**)&st_,   g_st);
    cudaGetSymbolAddress((void**)&pv_,   g_pv);
    cudaGetSymbolAddress((void**)&y_,    g_y);
    cudaGetSymbolAddress((void**)&yh_,   g_yh);
    cudaGetSymbolAddress((void**)&rh_,   g_rh);
    cudaGetSymbolAddress((void**)&wih_,  g_wih);
    cudaGetSymbolAddress((void**)&woh_,  g_woh);
    cudaGetSymbolAddress((void**)&wph_,  g_wph);
    cudaGetSymbolAddress((void**)&part_, g_part);
    cudaGetSymbolAddress((void**)&stats_,g_stats);

    static bool attr_done = false;
    if (!attr_done) {
        cudaFuncSetAttribute(gemm_h<0>, cudaFuncAttributeMaxDynamicSharedMemorySize, H_SMEM_BYTES);
        cudaFuncSetAttribute(gemm_h<1>, cudaFuncAttributeMaxDynamicSharedMemorySize, H_SMEM_BYTES);
        cudaFuncSetAttribute(gemm_h<2>, cudaFuncAttributeMaxDynamicSharedMemorySize, H_SMEM_BYTES);
        attr_done = true;
    }

    {
        int total = 2 * DIP * DM + 2 * DM * DI + DM * 2 * DM;
        cvt5_k<<<(total + 255) / 256, 256>>>(fw[0], bw[0], fw[7], bw[7], proj_w,
                                             wih_, woh_, wph_);
    }

    gn_part_k<<<dim3(64, B_), 256>>>(x, part_);
    gn_fin_k<<<B_, 64>>>(part_, stats_);
    gn_apply_k<<<dim3(L_ / 32, DM / 32, B_), dim3(32, 8)>>>(x, gn_w, gn_b, stats_, t_, th_);

    gemm_h<0><<<dim3((DIP + 127) / 128, (B_ * L_) / 128, 2), 128, H_SMEM_BYTES>>>(
        th_, wih_, wih_ + (long long)DIP * DM, zx_, B_ * L_, DIP, DM, DM, DM, DIP,
        0, 0, 0, 1, 0, SZ_ZX, L_, nullptr, nullptr);

    conv_silu_k<<<(int)((2LL * B_ * (L_ / 4) * (CD / 4) + 255) / 256), 256>>>(
        zx_, fw[1], fw[2], bw[1], bw[2], xbc_, bch_);
    dt_scan_k<<<2 * B_ * NH * NC, CH>>>(zx_, fw[3], fw[4], bw[3], bw[4], dt_, acs_);

    gemm_h<0><<<dim3(CH / 128, CH / 128, 2 * B_ * NC), 128, H_SMEM_BYTES>>>(
        bch_ + DS, bch_, bch_ + SZ_BCH, cb_, CH, CH, DS, 2 * DS, 2 * DS, CH,
        (long long)CH * 2 * DS, (long long)CH * 2 * DS, (long long)CH * CH,
        B_ * NC, SZ_BCH, SZ_CB, 0, nullptr, nullptr);

    states_mma_k<<<dim3(NH, NC, 2 * B_), 256>>>(xbc_, dt_, acs_, st_);
    chunkscan_k<<<(2 * B_ * NH * HD * DS) / 256, 256>>>(st_, acs_, pv_);
    ssd_y_mma_k<<<dim3(CH / 64, NH, 2 * B_ * NC), 256>>>(
        xbc_, dt_, acs_, cb_, pv_, fw[5], bw[5], y_);
    gate_rms_k<<<2 * B_ * L_, 256>>>(y_, zx_, fw[6], bw[6], yh_);

    gemm_h<1><<<dim3(DM / 128, (B_ * L_) / 128, 2), 128, H_SMEM_BYTES>>>(
        yh_, woh_, woh_ + (long long)DM * DI, (float*)rh_, B_ * L_, DM, DI, DI, DI, DM,
        0, 0, 0, 1, SZ_Y, 0, 0, t_, nullptr);

    gemm_h<2><<<dim3(DM / 128, (B_ * L_) / 128, 1), 128, H_SMEM_BYTES>>>(
        rh_, wph_, wph_, out, B_ * L_, DM, 2 * DM, 2 * DM, 2 * DM, DM,
        0, 0, 0, 1, 0, 0, 0, x, proj_b);
}

// round 12
// speedup vs baseline: 1.4585x; 1.0643x over previous
#include <cuda_runtime.h>
#include <cuda_bf16.h>
#include <cuda_fp16.h>
#include <math.h>
#include <stdint.h>

// ---------------- problem constants ----------------
static const int B_   = 2;
static const int L_   = 2048;
static const int DM   = 256;
static const int DS   = 128;
static const int DI   = 1024;
static const int NH   = 16;
static const int HD   = 64;
static const int CD   = 1280;
static const int DIP  = 2320;
static const int CH   = 256;
static const int NC   = 8;
#define GN_EPS 1.1920928955078125e-07f
#define RMS_EPS 1e-5f

#define SZ_ZX   ((long long)B_*L_*DIP)
#define SZ_XBC  ((long long)B_*L_*CD)
#define SZ_DT   ((long long)B_*L_*NH)
#define SZ_ACS  ((long long)B_*NH*L_)
#define SZ_CB   ((long long)B_*NC*CH*CH)
#define SZ_ST   ((long long)B_*NC*NH*HD*DS)
#define SZ_Y    ((long long)B_*L_*DI)

// ---------------- scratch ----------------
__device__ float  g_t    [B_*L_*DM];
__device__ __half g_th   [B_*L_*DM];
__device__ __half g_zx   [2*B_*L_*DIP];
__device__ __half g_xbc  [2*B_*L_*CD];
__device__ float  g_dt   [2*B_*L_*NH];
__device__ float  g_acs  [2*B_*NH*L_];
__device__ __half g_cb   [2*B_*NC*CH*CH];
__device__ float  g_st   [2*B_*NC*NH*HD*DS];
__device__ float  g_pv   [2*B_*NC*NH*HD*DS];
__device__ float  g_y    [2*B_*L_*DI];
__device__ __half g_yh   [2*B_*L_*DI];
__device__ __half g_rh   [B_*L_*2*DM];
__device__ __half g_wih  [2*DIP*DM];
__device__ __half g_woh  [2*DM*DI];
__device__ __half g_wph  [DM*2*DM];
__device__ float  g_part [B_*64*2];
__device__ float  g_stats[4];

__device__ __forceinline__ float siluf(float x) { return x / (1.f + __expf(-x)); }
__device__ __forceinline__ float softplusf(float x) { return x > 20.f ? x : log1pf(expf(x)); }

#define MMA_F16(acc, a, b) \
    asm volatile( \
        "mma.sync.aligned.m16n8k16.row.col.f32.f16.f16.f32 " \
        "{%0,%1,%2,%3},{%4,%5,%6,%7},{%8,%9},{%0,%1,%2,%3};" \
        : "+f"((acc)[0]), "+f"((acc)[1]), "+f"((acc)[2]), "+f"((acc)[3]) \
        : "r"((a)[0]), "r"((a)[1]), "r"((a)[2]), "r"((a)[3]), \
          "r"((b)[0]), "r"((b)[1]))

__device__ __forceinline__ void cpa16(uint32_t dst, const void* src, bool valid) {
    int sz = valid ? 16 : 0;
    asm volatile("cp.async.cg.shared.global [%0], [%1], 16, %2;\n"
                 :: "r"(dst), "l"(src), "r"(sz));
}
#define CPA_COMMIT() asm volatile("cp.async.commit_group;\n" ::)
#define CPA_WAIT1()  asm volatile("cp.async.wait_group 1;\n" ::)

// ---------------- weight fp32->fp16 conversion ----------------
__global__ void cvt5_k(const float* __restrict__ a0, const float* __restrict__ a1,
                       const float* __restrict__ a2, const float* __restrict__ a3,
                       const float* __restrict__ a4,
                       __half* __restrict__ w_in, __half* __restrict__ w_out,
                       __half* __restrict__ w_pj) {
    const int N1 = DIP * DM, N2 = DM * DI, N3 = DM * 2 * DM;
    int i = blockIdx.x * blockDim.x + threadIdx.x;
    if (i < N1) w_in[i] = __float2half(a0[i]);
    else if (i < 2 * N1) w_in[i] = __float2half(a1[i - N1]);
    else {
        int j = i - 2 * N1;
        if (j < N2) w_out[j] = __float2half(a2[j]);
        else if (j < 2 * N2) w_out[j] = __float2half(a3[j - N2]);
        else { int k = j - 2 * N2; if (k < N3) w_pj[k] = __float2half(a4[k]); }
    }
}

// ---------------- GroupNorm stats ----------------
__global__ void gn_part_k(const float* __restrict__ x, float* __restrict__ part) {
    int b = blockIdx.y;
    const float* xb = x + (size_t)b * DM * L_;
    float s = 0.f, ss = 0.f;
    for (int i = blockIdx.x * blockDim.x + threadIdx.x; i < DM * L_; i += 64 * 256) {
        float v = xb[i]; s += v; ss += v * v;
    }
    __shared__ float sh[256], sh2[256];
    sh[threadIdx.x] = s; sh2[threadIdx.x] = ss;
    __syncthreads();
    for (int o = 128; o > 0; o >>= 1) {
        if ((int)threadIdx.x < o) { sh[threadIdx.x] += sh[threadIdx.x + o]; sh2[threadIdx.x] += sh2[threadIdx.x + o]; }
        __syncthreads();
    }
    if (threadIdx.x == 0) {
        part[(b * 64 + blockIdx.x) * 2 + 0] = sh[0];
        part[(b * 64 + blockIdx.x) * 2 + 1] = sh2[0];
    }
}

__global__ void gn_fin_k(const float* __restrict__ part, float* __restrict__ stats) {
    int b = blockIdx.x;
    __shared__ double sh[64], sh2[64];
    int i = threadIdx.x;
    sh[i]  = (double)part[(b * 64 + i) * 2 + 0];
    sh2[i] = (double)part[(b * 64 + i) * 2 + 1];
    __syncthreads();
    for (int o = 32; o > 0; o >>= 1) {
        if (i < o) { sh[i] += sh[i + o]; sh2[i] += sh2[i + o]; }
        __syncthreads();
    }
    if (i == 0) {
        double n = (double)DM * L_;
        double mu = sh[0] / n;
        double var = sh2[0] / n - mu * mu;
        stats[b * 2 + 0] = (float)mu;
        stats[b * 2 + 1] = rsqrtf((float)var + GN_EPS);
    }
}

// ---------------- GroupNorm apply + transpose ----------------
__global__ void gn_apply_k(const float* __restrict__ x, const float* __restrict__ gw,
                           const float* __restrict__ gb, const float* __restrict__ stats,
                           float* __restrict__ t, __half* __restrict__ th) {
    int b = blockIdx.z;
    __shared__ float tile[32][33];
    int l0 = blockIdx.x * 32, d0 = blockIdx.y * 32;
    float mu = stats[b * 2], rs = stats[b * 2 + 1];
#pragma unroll
    for (int r = 0; r < 4; r++) {
        int d = d0 + threadIdx.y + r * 8;
        tile[threadIdx.y + r * 8][threadIdx.x] = x[((size_t)b * DM + d) * L_ + l0 + threadIdx.x];
    }
    __syncthreads();
    int d = d0 + threadIdx.x;
    float w = gw[d], bb = gb[d];
#pragma unroll
    for (int r = 0; r < 4; r++) {
        int l = l0 + threadIdx.y + r * 8;
        float v = (tile[threadIdx.x][threadIdx.y + r * 8] - mu) * rs * w + bb;
        t[((size_t)b * L_ + l) * DM + d] = v;
        th[((size_t)b * L_ + l) * DM + d] = __float2half(v);
    }
}

// ---- FP16 NT GEMM: 128x128 CTA tile, 4 warps (64x64), m16n8k16, 3-stage ----
// MODE 0: half store. MODE 1: out-proj epilogue (half into r). MODE 2: final (float).
#define GBM 128
#define GBN 128
#define HBK 32
#define GST 3
#define GLDH 40
#define H_SMEM_BYTES (GST * (GBM + GBN) * GLDH * 2)

template<int MODE>
__global__ void __launch_bounds__(128, 2)
gemm_h(const __half* __restrict__ A, const __half* __restrict__ B0,
       const __half* __restrict__ B1, void* __restrict__ Cv,
       int M, int N, int K, int lda, int ldb, int ldc,
       long long sA, long long sB, long long sC,
       int zPerDir, long long dA, long long dC, int revL,
       const float* __restrict__ extra, const float* __restrict__ bias) {
    constexpr int T  = 128;
    constexpr int MF = 4;
    constexpr int NF = 8;
    extern __shared__ __half hsm[];
    __half* Asm = hsm;
    __half* Bsm = hsm + GST * GBM * GLDH;
    int z = blockIdx.z;
    int dir = z / zPerDir, zz = z % zPerDir;
    const __half* Ap = A + dir * dA + zz * sA;
    const __half* Bp = (dir ? B1 : B0) + zz * sB;
    long long coff = dir * dC + zz * sC;
    int rev = dir ? revL : 0;
    int m0 = blockIdx.y * GBM, n0 = blockIdx.x * GBN;
    int tid = threadIdx.x;
    int warp = tid >> 5, lane = tid & 31;
    int wm = warp >> 1, wn = warp & 1;
    int group = lane >> 2, tig = lane & 3;
    float acc[MF][NF][4] = {};

    auto issue = [&](int k0, int s) {
        __half* As = Asm + s * GBM * GLDH;
        __half* Bs = Bsm + s * GBN * GLDH;
#pragma unroll
        for (int i = 0; i < 4; i++) {
            int e = tid + i * T;
            int mm = e >> 2;
            int kc = (e & 3) * 8;
            int gm = m0 + mm;
            int row = gm < M ? gm : 0;
            if (rev && gm < M) { int bb = gm / rev; int ll = gm % rev; row = bb * rev + (rev - 1 - ll); }
            cpa16((uint32_t)__cvta_generic_to_shared(As + mm * GLDH + kc),
                  Ap + (long long)row * lda + k0 + kc, gm < M);
        }
#pragma unroll
        for (int i = 0; i < 4; i++) {
            int e = tid + i * T;
            int nn = e >> 2;
            int kc = (e & 3) * 8;
            int gn = n0 + nn;
            int rowb = gn < N ? gn : 0;
            cpa16((uint32_t)__cvta_generic_to_shared(Bs + nn * GLDH + kc),
                  Bp + (long long)rowb * ldb + k0 + kc, gn < N);
        }
    };
    auto compute = [&](int s) {
        const __half2* As2 = reinterpret_cast<const __half2*>(Asm + s * GBM * GLDH);
        const __half2* Bs2 = reinterpret_cast<const __half2*>(Bsm + s * GBN * GLDH);
#pragma unroll
        for (int ks = 0; ks < 2; ks++) {
            int k2 = ks * 8;
            uint32_t af[MF][4], bf[NF][2];
#pragma unroll
            for (int mf = 0; mf < MF; mf++) {
                int rm = wm * 64 + mf * 16 + group;
                af[mf][0] = *reinterpret_cast<const uint32_t*>(&As2[(rm    ) * 20 + k2 + tig]);
                af[mf][1] = *reinterpret_cast<const uint32_t*>(&As2[(rm + 8) * 20 + k2 + tig]);
                af[mf][2] = *reinterpret_cast<const uint32_t*>(&As2[(rm    ) * 20 + k2 + tig + 4]);
                af[mf][3] = *reinterpret_cast<const uint32_t*>(&As2[(rm + 8) * 20 + k2 + tig + 4]);
            }
#pragma unroll
            for (int nf = 0; nf < NF; nf++) {
                int rn = wn * 64 + nf * 8 + group;
                bf[nf][0] = *reinterpret_cast<const uint32_t*>(&Bs2[rn * 20 + k2 + tig]);
                bf[nf][1] = *reinterpret_cast<const uint32_t*>(&Bs2[rn * 20 + k2 + tig + 4]);
            }
#pragma unroll
            for (int mf = 0; mf < MF; mf++)
#pragma unroll
                for (int nf = 0; nf < NF; nf++) MMA_F16(acc[mf][nf], af[mf], bf[nf]);
        }
    };

    int nIter = K / HBK;
    issue(0, 0);
    CPA_COMMIT();
    if (nIter > 1) issue(HBK, 1);
    CPA_COMMIT();
    for (int it = 0; it < nIter; it++) {
        CPA_WAIT1();
        __syncthreads();
        if (it + 2 < nIter) issue((it + 2) * HBK, (it + 2) % GST);
        CPA_COMMIT();
        compute(it % GST);
    }

#pragma unroll
    for (int mf = 0; mf < MF; mf++) {
#pragma unroll
        for (int nf = 0; nf < NF; nf++) {
            int gn = n0 + wn * 64 + nf * 8 + 2 * tig;
#pragma unroll
            for (int rr = 0; rr < 2; rr++) {
                int gm = m0 + wm * 64 + mf * 16 + group + rr * 8;
                float a0 = acc[mf][nf][rr * 2 + 0], a1 = acc[mf][nf][rr * 2 + 1];
                if (MODE == 0) {
                    if (gm < M && gn < N) {
                        __half2* cp2 = reinterpret_cast<__half2*>(Cv);
                        cp2[(coff + (long long)gm * ldc + gn) >> 1] = __floats2half2_rn(a0, a1);
                    }
                } else if (MODE == 1) {
                    int b = gm / L_, l = gm % L_;
                    int ltm = dir ? (L_ - 1 - l) : l;
                    long long base = (long long)(b * L_ + ltm);
                    float2 tv = *reinterpret_cast<const float2*>(extra + base * DM + gn);
                    __half2* rp = reinterpret_cast<__half2*>(Cv);
                    rp[(base * (2 * DM) + dir * DM + gn) >> 1] =
                        __floats2half2_rn(a0 + tv.x, a1 + tv.y);
                } else {
                    int b = gm / L_, l = gm % L_;
                    float* C = reinterpret_cast<float*>(Cv);
                    long long i0 = ((long long)(b * DM + gn)) * L_ + l;
                    long long i1 = ((long long)(b * DM + gn + 1)) * L_ + l;
                    C[i0] = extra[i0] + bias[gn] + a0;
                    C[i1] = extra[i1] + bias[gn + 1] + a1;
                }
            }
        }
    }
}

// ---------------- depthwise conv + SiLU (fp16 in/out, 4 l per thread) -------
__global__ void conv_silu_k(const __half* __restrict__ zx,
                            const float* __restrict__ cw0, const float* __restrict__ cb0,
                            const float* __restrict__ cw1, const float* __restrict__ cb1,
                            __half* __restrict__ xbc) {
    long long idx = (long long)blockIdx.x * blockDim.x + threadIdx.x;
    if (idx >= 2LL * B_ * (L_ / 4) * (CD / 4)) return;
    int cg = idx % (CD / 4);
    int lb = (idx / (CD / 4)) % (L_ / 4);
    long long rest = idx / ((long long)(CD / 4) * (L_ / 4));
    int b = rest % B_;
    int dir = rest / B_;
    int l0 = lb * 4;
    const float* cw = (dir ? cw1 : cw0) + cg * 16;
    const float* cb = (dir ? cb1 : cb0) + cg * 4;
    const __half* zxd = zx + dir * SZ_ZX + (size_t)(b * L_) * DIP + DI + cg * 4;
    float4 w0 = *reinterpret_cast<const float4*>(cw);
    float4 w1 = *reinterpret_cast<const float4*>(cw + 4);
    float4 w2 = *reinterpret_cast<const float4*>(cw + 8);
    float4 w3 = *reinterpret_cast<const float4*>(cw + 12);
    float4 bv = *reinterpret_cast<const float4*>(cb);
    float4 v[7];
#pragma unroll
    for (int r = 0; r < 7; r++) {
        int lp = l0 - 3 + r;
        if (lp >= 0) {
            const __half2* p = reinterpret_cast<const __half2*>(zxd + (size_t)lp * DIP);
            float2 f0 = __half22float2(p[0]);
            float2 f1 = __half22float2(p[1]);
            v[r] = make_float4(f0.x, f0.y, f1.x, f1.y);
        } else v[r] = make_float4(0.f, 0.f, 0.f, 0.f);
    }
    __half* outp = xbc + dir * SZ_XBC + ((size_t)(b * L_ + l0)) * CD + cg * 4;
#pragma unroll
    for (int j = 0; j < 4; j++) {
        float4 acc = bv;
#pragma unroll
        for (int k = 0; k < 4; k++) {
            float4 f = v[j + k];
            acc.x += ((const float*)&w0)[k] * f.x;
            acc.y += ((const float*)&w1)[k] * f.y;
            acc.z += ((const float*)&w2)[k] * f.z;
            acc.w += ((const float*)&w3)[k] * f.w;
        }
        __half2* op = reinterpret_cast<__half2*>(outp + (size_t)j * CD);
        op[0] = __floats2half2_rn(siluf(acc.x), siluf(acc.y));
        op[1] = __floats2half2_rn(siluf(acc.z), siluf(acc.w));
    }
}

// ---------------- dt softplus + per-chunk cumsum ----------------
__global__ void dt_scan_k(const __half* __restrict__ zx,
                          const float* __restrict__ db0, const float* __restrict__ al0,
                          const float* __restrict__ db1, const float* __restrict__ al1,
                          float* __restrict__ dt, float* __restrict__ acs) {
    int bi = blockIdx.x;
    int dir = bi / (B_ * NH * NC);
    bi %= B_ * NH * NC;
    int c = bi % NC, h = (bi / NC) % NH, b = bi / (NC * NH);
    const float* dt_bias = dir ? db1 : db0;
    const float* A_log   = dir ? al1 : al0;
    int l = threadIdx.x;
    int lane = l & 31, warp = l >> 5;
    int gl = c * CH + l;
    int row = b * L_ + gl;
    float v = __half2float(zx[dir * SZ_ZX + (size_t)row * DIP + (DIP - NH) + h]) + dt_bias[h];
    float dtv = softplusf(v);
    dt[dir * SZ_DT + (size_t)row * NH + h] = dtv;
    float a = -expf(A_log[h]) * dtv;
#pragma unroll
    for (int o = 1; o < 32; o <<= 1) {
        float t = __shfl_up_sync(0xffffffff, a, o);
        if (lane >= o) a += t;
    }
    __shared__ float wsum[8];
    if (lane == 31) wsum[warp] = a;
    __syncthreads();
    float off = 0.f;
#pragma unroll
    for (int w = 0; w < 8; w++) if (w < warp) off += wsum[w];
    acs[dir * SZ_ACS + (size_t)(b * NH + h) * L_ + gl] = a + off;
}

// ---------------- per-chunk end state via fp16 mma ----------------
__global__ void __launch_bounds__(256)
states_mma_k(const __half* __restrict__ xbc, const float* __restrict__ dt,
             const float* __restrict__ acs, float* __restrict__ st) {
    int h = blockIdx.x, c = blockIdx.y;
    int dir = blockIdx.z / B_, b = blockIdx.z % B_;
    const __half* xbcd = xbc + dir * SZ_XBC;
    const float* dtd  = dt  + dir * SZ_DT;
    const float* acsd = acs + dir * SZ_ACS;
    int tid = threadIdx.x;
    int warp = tid >> 5, lane = tid & 31;
    int wm = warp >> 2, wn = warp & 3;
    int group = lane >> 2, tig = lane & 3;
    __shared__ __half Xs[64][GLDH];
    __shared__ __half Bs[128][GLDH];
    __shared__ float wrow[CH];
    int acsbase = (b * NH + h) * L_ + c * CH;
    float csLast = acsd[acsbase + CH - 1];
    {
        int row = b * L_ + c * CH + tid;
        wrow[tid] = dtd[(size_t)row * NH + h] * __expf(csLast - acsd[acsbase + tid]);
    }
    __syncthreads();
    float acc[2][4][4] = {};
    for (int s0 = 0; s0 < CH; s0 += 32) {
#pragma unroll
        for (int i = 0; i < 8; i++) {
            int e = tid + i * 256;
            int pp = e & 63, ss = e >> 6;
            int row = b * L_ + c * CH + s0 + ss;
            Xs[pp][ss] = __float2half(
                __half2float(xbcd[(size_t)row * CD + h * HD + pp]) * wrow[s0 + ss]);
        }
#pragma unroll
        for (int i = 0; i < 16; i++) {
            int e = tid + i * 256;
            int nn = e & 127, ss = e >> 7;
            int row = b * L_ + c * CH + s0 + ss;
            Bs[nn][ss] = xbcd[(size_t)row * CD + DI + nn];
        }
        __syncthreads();
        const __half2* Xs2 = reinterpret_cast<const __half2*>(&Xs[0][0]);
        const __half2* Bs2 = reinterpret_cast<const __half2*>(&Bs[0][0]);
#pragma unroll
        for (int ks = 0; ks < 2; ks++) {
            int k2 = ks * 8;
            uint32_t af[2][4], bf[4][2];
#pragma unroll
            for (int mf = 0; mf < 2; mf++) {
                int rm = wm * 32 + mf * 16 + group;
                af[mf][0] = *reinterpret_cast<const uint32_t*>(&Xs2[(rm    ) * 20 + k2 + tig]);
                af[mf][1] = *reinterpret_cast<const uint32_t*>(&Xs2[(rm + 8) * 20 + k2 + tig]);
                af[mf][2] = *reinterpret_cast<const uint32_t*>(&Xs2[(rm    ) * 20 + k2 + tig + 4]);
                af[mf][3] = *reinterpret_cast<const uint32_t*>(&Xs2[(rm + 8) * 20 + k2 + tig + 4]);
            }
#pragma unroll
            for (int nf = 0; nf < 4; nf++) {
                int rn = wn * 32 + nf * 8 + group;
                bf[nf][0] = *reinterpret_cast<const uint32_t*>(&Bs2[rn * 20 + k2 + tig]);
                bf[nf][1] = *reinterpret_cast<const uint32_t*>(&Bs2[rn * 20 + k2 + tig + 4]);
            }
#pragma unroll
            for (int mf = 0; mf < 2; mf++)
#pragma unroll
                for (int nf = 0; nf < 4; nf++) MMA_F16(acc[mf][nf], af[mf], bf[nf]);
        }
        __syncthreads();
    }
    float* base = st + dir * SZ_ST + (size_t)((b * NC + c) * NH + h) * HD * DS;
#pragma unroll
    for (int mf = 0; mf < 2; mf++) {
#pragma unroll
        for (int nf = 0; nf < 4; nf++) {
            int gm = wm * 32 + mf * 16 + group;
            int gn = wn * 32 + nf * 8 + 2 * tig;
            *reinterpret_cast<float2*>(base + gm * DS + gn) =
                make_float2(acc[mf][nf][0], acc[mf][nf][1]);
            *reinterpret_cast<float2*>(base + (gm + 8) * DS + gn) =
                make_float2(acc[mf][nf][2], acc[mf][nf][3]);
        }
    }
}

// ---------------- inter-chunk recurrence ----------------
__global__ void chunkscan_k(const float* __restrict__ st, const float* __restrict__ acs,
                            float* __restrict__ pv) {
    int idx = blockIdx.x * blockDim.x + threadIdx.x;
    int n = idx & (DS - 1);
    int p = (idx >> 7) & (HD - 1);
    int h = (idx >> 13) & (NH - 1);
    int b = (idx >> 17) & (B_ - 1);
    int dir = idx >> 18;
    const float* std_ = st + dir * SZ_ST;
    const float* acsd = acs + dir * SZ_ACS;
    float* pvd = pv + dir * SZ_ST;
    float S = 0.f;
    for (int c = 0; c < NC; c++) {
        size_t off = ((size_t)((b * NC + c) * NH + h) * HD + p) * DS + n;
        pvd[off] = S;
        float at = acsd[(b * NH + h) * L_ + c * CH + CH - 1];
        S = S * expf(at) + std_[off];
    }
}

// ---------------- Y via fp16 mma, precomputed decay ----------------
__global__ void __launch_bounds__(256)
ssd_y_mma_k(const __half* __restrict__ xbc, const float* __restrict__ dt,
            const float* __restrict__ acs, const __half* __restrict__ cb,
            const float* __restrict__ pv,
            const float* __restrict__ Dh0, const float* __restrict__ Dh1,
            float* __restrict__ y) {
    int lt = blockIdx.x, h = blockIdx.y;
    int dir = blockIdx.z / (B_ * NC);
    int bc = blockIdx.z % (B_ * NC);
    int c = bc % NC, b = bc / NC;
    const __half* xbcd = xbc + dir * SZ_XBC;
    const float* dtd  = dt  + dir * SZ_DT;
    const float* acsd = acs + dir * SZ_ACS;
    const float* Dh   = dir ? Dh1 : Dh0;
    int tid = threadIdx.x;
    int warp = tid >> 5, lane = tid & 31;
    int wm = warp >> 2, wn = warp & 3;
    int group = lane >> 2, tig = lane & 3;
    __shared__ __half Ws[64][GLDH];
    __shared__ __half Xs[64][GLDH];
    __shared__ __half Ps[64][GLDH];
    __shared__ float csl[64], el64[64], eoff[64];
    __shared__ float einv[CH];
    int l0 = lt * 64;
    int acsbase = (b * NH + h) * L_ + c * CH;
    float csl0 = acsd[acsbase + l0];
    if (tid < 64) {
        float v = acsd[acsbase + l0 + tid];
        csl[tid]  = v;
        el64[tid] = __expf(v - csl0);
        eoff[tid] = __expf(v);
    }
    einv[tid] = __expf(csl0 - acsd[acsbase + tid]);
    __syncthreads();
    const __half* cbb = cb + dir * SZ_CB + (size_t)(b * NC + c) * CH * CH;
    float acc[2][2][4] = {};
    int nst = 2 * lt + 2;
    for (int stp = 0; stp < nst; stp++) {
        int s0 = stp * 32;
        bool lower = (s0 + 31 < l0);
        if (lower) {
#pragma unroll
            for (int i = 0; i < 8; i++) {
                int e = tid + i * 256;
                int j = e & 31, ii = e >> 5;
                Ws[ii][j] = __float2half(el64[ii] * einv[s0 + j] *
                                         __half2float(cbb[(l0 + ii) * CH + s0 + j]));
            }
        } else {
#pragma unroll
            for (int i = 0; i < 8; i++) {
                int e = tid + i * 256;
                int j = e & 31, ii = e >> 5;
                float w = 0.f;
                if (s0 + j <= l0 + ii)
                    w = __expf(csl[ii] - acsd[acsbase + s0 + j]) *
                        __half2float(cbb[(l0 + ii) * CH + s0 + j]);
                Ws[ii][j] = __float2half(w);
            }
        }
#pragma unroll
        for (int i = 0; i < 8; i++) {
            int e = tid + i * 256;
            int pp = e & 63, ss = e >> 6;
            int row = b * L_ + c * CH + s0 + ss;
            Xs[pp][ss] = __float2half(
                __half2float(xbcd[(size_t)row * CD + h * HD + pp]) * dtd[(size_t)row * NH + h]);
        }
        __syncthreads();
        const __half2* Ws2 = reinterpret_cast<const __half2*>(&Ws[0][0]);
        const __half2* Xs2 = reinterpret_cast<const __half2*>(&Xs[0][0]);
#pragma unroll
        for (int ks = 0; ks < 2; ks++) {
            int k2 = ks * 8;
            uint32_t af[2][4], bf[2][2];
#pragma unroll
            for (int mf = 0; mf < 2; mf++) {
                int rm = wm * 32 + mf * 16 + group;
                af[mf][0] = *reinterpret_cast<const uint32_t*>(&Ws2[(rm    ) * 20 + k2 + tig]);
                af[mf][1] = *reinterpret_cast<const uint32_t*>(&Ws2[(rm + 8) * 20 + k2 + tig]);
                af[mf][2] = *reinterpret_cast<const uint32_t*>(&Ws2[(rm    ) * 20 + k2 + tig + 4]);
                af[mf][3] = *reinterpret_cast<const uint32_t*>(&Ws2[(rm + 8) * 20 + k2 + tig + 4]);
            }
#pragma unroll
            for (int nf = 0; nf < 2; nf++) {
                int rn = wn * 16 + nf * 8 + group;
                bf[nf][0] = *reinterpret_cast<const uint32_t*>(&Xs2[rn * 20 + k2 + tig]);
                bf[nf][1] = *reinterpret_cast<const uint32_t*>(&Xs2[rn * 20 + k2 + tig + 4]);
            }
#pragma unroll
            for (int mf = 0; mf < 2; mf++)
#pragma unroll
                for (int nf = 0; nf < 2; nf++) MMA_F16(acc[mf][nf], af[mf], bf[nf]);
        }
        __syncthreads();
    }
    const float* pvb = pv + dir * SZ_ST + (size_t)((b * NC + c) * NH + h) * HD * DS;
    for (int nt = 0; nt < 4; nt++) {
        int n0 = nt * 32;
#pragma unroll
        for (int i = 0; i < 8; i++) {
            int e = tid + i * 256;
            int j = e & 31, ii = e >> 5;
            int row = b * L_ + c * CH + l0 + ii;
            Ws[ii][j] = __float2half(
                __half2float(xbcd[(size_t)row * CD + DI + DS + n0 + j]) * eoff[ii]);
        }
#pragma unroll
        for (int i = 0; i < 8; i++) {
            int e = tid + i * 256;
            int j = e & 31, pp = e >> 5;
            Ps[pp][j] = __float2half(pvb[pp * DS + n0 + j]);
        }
        __syncthreads();
        const __half2* Ws2 = reinterpret_cast<const __half2*>(&Ws[0][0]);
        const __half2* Ps2 = reinterpret_cast<const __half2*>(&Ps[0][0]);
#pragma unroll
        for (int ks = 0; ks < 2; ks++) {
            int k2 = ks * 8;
            uint32_t af[2][4], bf[2][2];
#pragma unroll
            for (int mf = 0; mf < 2; mf++) {
                int rm = wm * 32 + mf * 16 + group;
                af[mf][0] = *reinterpret_cast<const uint32_t*>(&Ws2[(rm    ) * 20 + k2 + tig]);
                af[mf][1] = *reinterpret_cast<const uint32_t*>(&Ws2[(rm + 8) * 20 + k2 + tig]);
                af[mf][2] = *reinterpret_cast<const uint32_t*>(&Ws2[(rm    ) * 20 + k2 + tig + 4]);
                af[mf][3] = *reinterpret_cast<const uint32_t*>(&Ws2[(rm + 8) * 20 + k2 + tig + 4]);
            }
#pragma unroll
            for (int nf = 0; nf < 2; nf++) {
                int rn = wn * 16 + nf * 8 + group;
                bf[nf][0] = *reinterpret_cast<const uint32_t*>(&Ps2[rn * 20 + k2 + tig]);
                bf[nf][1] = *reinterpret_cast<const uint32_t*>(&Ps2[rn * 20 + k2 + tig + 4]);
            }
#pragma unroll
            for (int mf = 0; mf < 2; mf++)
#pragma unroll
                for (int nf = 0; nf < 2; nf++) MMA_F16(acc[mf][nf], af[mf], bf[nf]);
        }
        __syncthreads();
    }
    float dh = Dh[h];
    float* yd = y + dir * SZ_Y;
#pragma unroll
    for (int mf = 0; mf < 2; mf++) {
#pragma unroll
        for (int nf = 0; nf < 2; nf++) {
            int ll = l0 + wm * 32 + mf * 16 + group;
            int pp = wn * 16 + nf * 8 + 2 * tig;
#pragma unroll
            for (int rr = 0; rr < 2; rr++) {
                int row = b * L_ + c * CH + ll + rr * 8;
                __half2 xrh = *reinterpret_cast<const __half2*>(
                    xbcd + (size_t)row * CD + h * HD + pp);
                float2 xr = __half22float2(xrh);
                *reinterpret_cast<float2*>(yd + (size_t)row * DI + h * HD + pp) =
                    make_float2(acc[mf][nf][rr * 2 + 0] + xr.x * dh,
                                acc[mf][nf][rr * 2 + 1] + xr.y * dh);
            }
        }
    }
}

// ---------------- gating + RMSNorm -> fp16 output ----------------
__global__ void gate_rms_k(const float* __restrict__ y, const __half* __restrict__ zx,
                           const float* __restrict__ nw0, const float* __restrict__ nw1,
                           __half* __restrict__ yh) {
    int row = blockIdx.x;
    int dir = row / (B_ * L_);
    row %= B_ * L_;
    const float* nw = dir ? nw1 : nw0;
    const float* yd = y + dir * SZ_Y + (size_t)row * DI;
    const __half* zxd = zx + dir * SZ_ZX + (size_t)row * DIP;
    int tid = threadIdx.x;
    float4 yv = *reinterpret_cast<const float4*>(yd + tid * 4);
    const __half2* zp = reinterpret_cast<const __half2*>(zxd + tid * 4);
    float2 z0 = __half22float2(zp[0]);
    float2 z1 = __half22float2(zp[1]);
    yv.x *= siluf(z0.x); yv.y *= siluf(z0.y); yv.z *= siluf(z1.x); yv.w *= siluf(z1.y);
    float ss = yv.x * yv.x + yv.y * yv.y + yv.z * yv.z + yv.w * yv.w;
    __shared__ float sh[256];
    sh[tid] = ss;
    __syncthreads();
    for (int o = 128; o > 0; o >>= 1) {
        if (tid < o) sh[tid] += sh[tid + o];
        __syncthreads();
    }
    float scale = rsqrtf(sh[0] / DI + RMS_EPS);
    float4 wv = *reinterpret_cast<const float4*>(nw + tid * 4);
    __half2* yp = reinterpret_cast<__half2*>(yh + dir * SZ_Y + (size_t)row * DI) + tid * 2;
    yp[0] = __floats2half2_rn(yv.x * scale * wv.x, yv.y * scale * wv.y);
    yp[1] = __floats2half2_rn(yv.z * scale * wv.z, yv.w * scale * wv.w);
}

// ---------------- launch ----------------
extern "C" void kernel_launch(void* const* d_in, const int* in_sizes, int n_in,
                              void* d_out, int out_size) {
    (void)in_sizes; (void)n_in; (void)out_size;
    const float* x      = (const float*)d_in[0];
    const float* gn_w   = (const float*)d_in[1];
    const float* gn_b   = (const float*)d_in[2];
    const float* proj_w = (const float*)d_in[3];
    const float* proj_b = (const float*)d_in[4];
    const float* fw[8], *bw[8];
    for (int i = 0; i < 8; i++) { fw[i] = (const float*)d_in[5 + i]; bw[i] = (const float*)d_in[13 + i]; }
    float* out = (float*)d_out;

    float *t_, *dt_, *acs_, *st_, *pv_, *y_, *part_, *stats_;
    __half *th_, *zx_, *xbc_, *cb_, *yh_, *rh_, *wih_, *woh_, *wph_;
    cudaGetSymbolAddress((void**)&t_,    g_t);
    cudaGetSymbolAddress((void**)&th_,   g_th);
    cudaGetSymbolAddress((void**)&zx_,   g_zx);
    cudaGetSymbolAddress((void**)&xbc_,  g_xbc);
    cudaGetSymbolAddress((void**)&dt_,   g_dt);
    cudaGetSymbolAddress((void**)&acs_,  g_acs);
    cudaGetSymbolAddress((void**)&cb_,   g_cb);
    cudaGetSymbolAddress((void**)&st_,   g_st);
    cudaGetSymbolAddress((void**)&pv_,   g_pv);
    cudaGetSymbolAddress((void**)&y_,    g_y);
    cudaGetSymbolAddress((void**)&yh_,   g_yh);
    cudaGetSymbolAddress((void**)&rh_,   g_rh);
    cudaGetSymbolAddress((void**)&wih_,  g_wih);
    cudaGetSymbolAddress((void**)&woh_,  g_woh);
    cudaGetSymbolAddress((void**)&wph_,  g_wph);
    cudaGetSymbolAddress((void**)&part_, g_part);
    cudaGetSymbolAddress((void**)&stats_,g_stats);

    static bool attr_done = false;
    if (!attr_done) {
        cudaFuncSetAttribute(gemm_h<0>, cudaFuncAttributeMaxDynamicSharedMemorySize, H_SMEM_BYTES);
        cudaFuncSetAttribute(gemm_h<1>, cudaFuncAttributeMaxDynamicSharedMemorySize, H_SMEM_BYTES);
        cudaFuncSetAttribute(gemm_h<2>, cudaFuncAttributeMaxDynamicSharedMemorySize, H_SMEM_BYTES);
        attr_done = true;
    }

    {
        int total = 2 * DIP * DM + 2 * DM * DI + DM * 2 * DM;
        cvt5_k<<<(total + 255) / 256, 256>>>(fw[0], bw[0], fw[7], bw[7], proj_w,
                                             wih_, woh_, wph_);
    }

    gn_part_k<<<dim3(64, B_), 256>>>(x, part_);
    gn_fin_k<<<B_, 64>>>(part_, stats_);
    gn_apply_k<<<dim3(L_ / 32, DM / 32, B_), dim3(32, 8)>>>(x, gn_w, gn_b, stats_, t_, th_);

    // in-projection -> zx (fp16)
    gemm_h<0><<<dim3((DIP + 127) / 128, (B_ * L_) / 128, 2), 128, H_SMEM_BYTES>>>(
        th_, wih_, wih_ + (long long)DIP * DM, zx_, B_ * L_, DIP, DM, DM, DM, DIP,
        0, 0, 0, 1, 0, SZ_ZX, L_, nullptr, nullptr);

    conv_silu_k<<<(int)((2LL * B_ * (L_ / 4) * (CD / 4) + 255) / 256), 256>>>(
        zx_, fw[1], fw[2], bw[1], bw[2], xbc_);
    dt_scan_k<<<2 * B_ * NH * NC, CH>>>(zx_, fw[3], fw[4], bw[3], bw[4], dt_, acs_);

    // CB = C @ B^T directly from fp16 xbc
    gemm_h<0><<<dim3(CH / 128, CH / 128, 2 * B_ * NC), 128, H_SMEM_BYTES>>>(
        xbc_ + DI + DS, xbc_ + DI, xbc_ + SZ_XBC + DI, cb_, CH, CH, DS, CD, CD, CH,
        (long long)CH * CD, (long long)CH * CD, (long long)CH * CH,
        B_ * NC, SZ_XBC, SZ_CB, 0, nullptr, nullptr);

    states_mma_k<<<dim3(NH, NC, 2 * B_), 256>>>(xbc_, dt_, acs_, st_);
    chunkscan_k<<<(2 * B_ * NH * HD * DS) / 256, 256>>>(st_, acs_, pv_);
    ssd_y_mma_k<<<dim3(CH / 64, NH, 2 * B_ * NC), 256>>>(
        xbc_, dt_, acs_, cb_, pv_, fw[5], bw[5], y_);
    gate_rms_k<<<2 * B_ * L_, 256>>>(y_, zx_, fw[6], bw[6], yh_);

    gemm_h<1><<<dim3(DM / 128, (B_ * L_) / 128, 2), 128, H_SMEM_BYTES>>>(
        yh_, woh_, woh_ + (long long)DM * DI, rh_, B_ * L_, DM, DI, DI, DI, DM,
        0, 0, 0, 1, SZ_Y, 0, 0, t_, nullptr);

    gemm_h<2><<<dim3(DM / 128, (B_ * L_) / 128, 1), 128, H_SMEM_BYTES>>>(
        rh_, wph_, wph_, out, B_ * L_, DM, 2 * DM, 2 * DM, 2 * DM, DM,
        0, 0, 0, 1, 0, 0, 0, x, proj_b);
}

// round 13
// speedup vs baseline: 1.4900x; 1.0215x over previous
#include <cuda_runtime.h>
#include <cuda_bf16.h>
#include <cuda_fp16.h>
#include <math.h>
#include <stdint.h>

// ---------------- problem constants ----------------
static const int B_   = 2;
static const int L_   = 2048;
static const int DM   = 256;
static const int DS   = 128;
static const int DI   = 1024;
static const int NH   = 16;
static const int HD   = 64;
static const int CD   = 1280;
static const int DIP  = 2320;
static const int CH   = 256;
static const int NC   = 8;
#define GN_EPS 1.1920928955078125e-07f
#define RMS_EPS 1e-5f

#define SZ_ZX   ((long long)B_*L_*DIP)
#define SZ_XBC  ((long long)B_*L_*CD)
#define SZ_DT   ((long long)B_*L_*NH)
#define SZ_ACS  ((long long)B_*NH*L_)
#define SZ_CB   ((long long)B_*NC*CH*CH)
#define SZ_ST   ((long long)B_*NC*NH*HD*DS)
#define SZ_Y    ((long long)B_*L_*DI)

// fused-kernel block counts
#define CVT_TOTAL (2*DIP*DM + 2*DM*DI + DM*2*DM)
#define CVT_BLOCKS ((CVT_TOTAL + 255) / 256)
#define GNP_BLOCKS (64 * B_)
#define CONV_BLOCKS ((int)((2LL * B_ * (L_/4) * (CD/4) + 255) / 256))
#define DTS_BLOCKS (2 * B_ * NH * NC)

// ---------------- scratch ----------------
__device__ float  g_t    [B_*L_*DM];
__device__ __half g_th   [B_*L_*DM];
__device__ __half g_zx   [2*B_*L_*DIP];
__device__ __half g_xbc  [2*B_*L_*CD];
__device__ float  g_dt   [2*B_*L_*NH];
__device__ float  g_acs  [2*B_*NH*L_];
__device__ __half g_cb   [2*B_*NC*CH*CH];
__device__ float  g_st   [2*B_*NC*NH*HD*DS];
__device__ float  g_pv   [2*B_*NC*NH*HD*DS];
__device__ __half g_yh   [2*B_*L_*DI];
__device__ __half g_rh   [B_*L_*2*DM];
__device__ __half g_wih  [2*DIP*DM];
__device__ __half g_woh  [2*DM*DI];
__device__ __half g_wph  [DM*2*DM];
__device__ float  g_part [B_*64*2];
__device__ float  g_stats[4];

__device__ __forceinline__ float siluf(float x) { return x / (1.f + __expf(-x)); }
__device__ __forceinline__ float softplusf(float x) { return x > 20.f ? x : log1pf(expf(x)); }

#define MMA_F16(acc, a, b) \
    asm volatile( \
        "mma.sync.aligned.m16n8k16.row.col.f32.f16.f16.f32 " \
        "{%0,%1,%2,%3},{%4,%5,%6,%7},{%8,%9},{%0,%1,%2,%3};" \
        : "+f"((acc)[0]), "+f"((acc)[1]), "+f"((acc)[2]), "+f"((acc)[3]) \
        : "r"((a)[0]), "r"((a)[1]), "r"((a)[2]), "r"((a)[3]), \
          "r"((b)[0]), "r"((b)[1]))

__device__ __forceinline__ void cpa16(uint32_t dst, const void* src, bool valid) {
    int sz = valid ? 16 : 0;
    asm volatile("cp.async.cg.shared.global [%0], [%1], 16, %2;\n"
                 :: "r"(dst), "l"(src), "r"(sz));
}
#define CPA_COMMIT() asm volatile("cp.async.commit_group;\n" ::)
#define CPA_WAIT1()  asm volatile("cp.async.wait_group 1;\n" ::)

// ---------------- fused: weight conversion + GroupNorm partials -------------
__global__ void prep_k(const float* __restrict__ a0, const float* __restrict__ a1,
                       const float* __restrict__ a2, const float* __restrict__ a3,
                       const float* __restrict__ a4,
                       __half* __restrict__ w_in, __half* __restrict__ w_out,
                       __half* __restrict__ w_pj,
                       const float* __restrict__ x, float* __restrict__ part) {
    int bi = blockIdx.x;
    if (bi < CVT_BLOCKS) {
        const int N1 = DIP * DM, N2 = DM * DI, N3 = DM * 2 * DM;
        int i = bi * 256 + threadIdx.x;
        if (i < N1) w_in[i] = __float2half(a0[i]);
        else if (i < 2 * N1) w_in[i] = __float2half(a1[i - N1]);
        else {
            int j = i - 2 * N1;
            if (j < N2) w_out[j] = __float2half(a2[j]);
            else if (j < 2 * N2) w_out[j] = __float2half(a3[j - N2]);
            else { int k = j - 2 * N2; if (k < N3) w_pj[k] = __float2half(a4[k]); }
        }
        return;
    }
    int gi = bi - CVT_BLOCKS;           // 0 .. GNP_BLOCKS-1
    int b = gi / 64, blk = gi % 64;
    const float* xb = x + (size_t)b * DM * L_;
    float s = 0.f, ss = 0.f;
    for (int i = blk * 256 + threadIdx.x; i < DM * L_; i += 64 * 256) {
        float v = xb[i]; s += v; ss += v * v;
    }
    __shared__ float sh[256], sh2[256];
    sh[threadIdx.x] = s; sh2[threadIdx.x] = ss;
    __syncthreads();
    for (int o = 128; o > 0; o >>= 1) {
        if ((int)threadIdx.x < o) { sh[threadIdx.x] += sh[threadIdx.x + o]; sh2[threadIdx.x] += sh2[threadIdx.x + o]; }
        __syncthreads();
    }
    if (threadIdx.x == 0) {
        part[(b * 64 + blk) * 2 + 0] = sh[0];
        part[(b * 64 + blk) * 2 + 1] = sh2[0];
    }
}

__global__ void gn_fin_k(const float* __restrict__ part, float* __restrict__ stats) {
    int b = blockIdx.x;
    __shared__ double sh[64], sh2[64];
    int i = threadIdx.x;
    sh[i]  = (double)part[(b * 64 + i) * 2 + 0];
    sh2[i] = (double)part[(b * 64 + i) * 2 + 1];
    __syncthreads();
    for (int o = 32; o > 0; o >>= 1) {
        if (i < o) { sh[i] += sh[i + o]; sh2[i] += sh2[i + o]; }
        __syncthreads();
    }
    if (i == 0) {
        double n = (double)DM * L_;
        double mu = sh[0] / n;
        double var = sh2[0] / n - mu * mu;
        stats[b * 2 + 0] = (float)mu;
        stats[b * 2 + 1] = rsqrtf((float)var + GN_EPS);
    }
}

// ---------------- GroupNorm apply + transpose ----------------
__global__ void gn_apply_k(const float* __restrict__ x, const float* __restrict__ gw,
                           const float* __restrict__ gb, const float* __restrict__ stats,
                           float* __restrict__ t, __half* __restrict__ th) {
    int b = blockIdx.z;
    __shared__ float tile[32][33];
    int l0 = blockIdx.x * 32, d0 = blockIdx.y * 32;
    float mu = stats[b * 2], rs = stats[b * 2 + 1];
#pragma unroll
    for (int r = 0; r < 4; r++) {
        int d = d0 + threadIdx.y + r * 8;
        tile[threadIdx.y + r * 8][threadIdx.x] = x[((size_t)b * DM + d) * L_ + l0 + threadIdx.x];
    }
    __syncthreads();
    int d = d0 + threadIdx.x;
    float w = gw[d], bb = gb[d];
#pragma unroll
    for (int r = 0; r < 4; r++) {
        int l = l0 + threadIdx.y + r * 8;
        float v = (tile[threadIdx.x][threadIdx.y + r * 8] - mu) * rs * w + bb;
        t[((size_t)b * L_ + l) * DM + d] = v;
        th[((size_t)b * L_ + l) * DM + d] = __float2half(v);
    }
}

// ---- FP16 NT GEMM: 128x128 CTA tile, 4 warps (64x64), m16n8k16, 3-stage ----
#define GBM 128
#define GBN 128
#define HBK 32
#define GST 3
#define GLDH 40
#define H_SMEM_BYTES (GST * (GBM + GBN) * GLDH * 2)

template<int MODE>
__global__ void __launch_bounds__(128, 2)
gemm_h(const __half* __restrict__ A, const __half* __restrict__ B0,
       const __half* __restrict__ B1, void* __restrict__ Cv,
       int M, int N, int K, int lda, int ldb, int ldc,
       long long sA, long long sB, long long sC,
       int zPerDir, long long dA, long long dC, int revL,
       const float* __restrict__ extra, const float* __restrict__ bias) {
    constexpr int T  = 128;
    constexpr int MF = 4;
    constexpr int NF = 8;
    extern __shared__ __half hsm[];
    __half* Asm = hsm;
    __half* Bsm = hsm + GST * GBM * GLDH;
    int z = blockIdx.z;
    int dir = z / zPerDir, zz = z % zPerDir;
    const __half* Ap = A + dir * dA + zz * sA;
    const __half* Bp = (dir ? B1 : B0) + zz * sB;
    long long coff = dir * dC + zz * sC;
    int rev = dir ? revL : 0;
    int m0 = blockIdx.y * GBM, n0 = blockIdx.x * GBN;
    int tid = threadIdx.x;
    int warp = tid >> 5, lane = tid & 31;
    int wm = warp >> 1, wn = warp & 1;
    int group = lane >> 2, tig = lane & 3;
    float acc[MF][NF][4] = {};

    auto issue = [&](int k0, int s) {
        __half* As = Asm + s * GBM * GLDH;
        __half* Bs = Bsm + s * GBN * GLDH;
#pragma unroll
        for (int i = 0; i < 4; i++) {
            int e = tid + i * T;
            int mm = e >> 2;
            int kc = (e & 3) * 8;
            int gm = m0 + mm;
            int row = gm < M ? gm : 0;
            if (rev && gm < M) { int bb = gm / rev; int ll = gm % rev; row = bb * rev + (rev - 1 - ll); }
            cpa16((uint32_t)__cvta_generic_to_shared(As + mm * GLDH + kc),
                  Ap + (long long)row * lda + k0 + kc, gm < M);
        }
#pragma unroll
        for (int i = 0; i < 4; i++) {
            int e = tid + i * T;
            int nn = e >> 2;
            int kc = (e & 3) * 8;
            int gn = n0 + nn;
            int rowb = gn < N ? gn : 0;
            cpa16((uint32_t)__cvta_generic_to_shared(Bs + nn * GLDH + kc),
                  Bp + (long long)rowb * ldb + k0 + kc, gn < N);
        }
    };
    auto compute = [&](int s) {
        const __half2* As2 = reinterpret_cast<const __half2*>(Asm + s * GBM * GLDH);
        const __half2* Bs2 = reinterpret_cast<const __half2*>(Bsm + s * GBN * GLDH);
#pragma unroll
        for (int ks = 0; ks < 2; ks++) {
            int k2 = ks * 8;
            uint32_t af[MF][4], bf[NF][2];
#pragma unroll
            for (int mf = 0; mf < MF; mf++) {
                int rm = wm * 64 + mf * 16 + group;
                af[mf][0] = *reinterpret_cast<const uint32_t*>(&As2[(rm    ) * 20 + k2 + tig]);
                af[mf][1] = *reinterpret_cast<const uint32_t*>(&As2[(rm + 8) * 20 + k2 + tig]);
                af[mf][2] = *reinterpret_cast<const uint32_t*>(&As2[(rm    ) * 20 + k2 + tig + 4]);
                af[mf][3] = *reinterpret_cast<const uint32_t*>(&As2[(rm + 8) * 20 + k2 + tig + 4]);
            }
#pragma unroll
            for (int nf = 0; nf < NF; nf++) {
                int rn = wn * 64 + nf * 8 + group;
                bf[nf][0] = *reinterpret_cast<const uint32_t*>(&Bs2[rn * 20 + k2 + tig]);
                bf[nf][1] = *reinterpret_cast<const uint32_t*>(&Bs2[rn * 20 + k2 + tig + 4]);
            }
#pragma unroll
            for (int mf = 0; mf < MF; mf++)
#pragma unroll
                for (int nf = 0; nf < NF; nf++) MMA_F16(acc[mf][nf], af[mf], bf[nf]);
        }
    };

    int nIter = K / HBK;
    issue(0, 0);
    CPA_COMMIT();
    if (nIter > 1) issue(HBK, 1);
    CPA_COMMIT();
    for (int it = 0; it < nIter; it++) {
        CPA_WAIT1();
        __syncthreads();
        if (it + 2 < nIter) issue((it + 2) * HBK, (it + 2) % GST);
        CPA_COMMIT();
        compute(it % GST);
    }

#pragma unroll
    for (int mf = 0; mf < MF; mf++) {
#pragma unroll
        for (int nf = 0; nf < NF; nf++) {
            int gn = n0 + wn * 64 + nf * 8 + 2 * tig;
#pragma unroll
            for (int rr = 0; rr < 2; rr++) {
                int gm = m0 + wm * 64 + mf * 16 + group + rr * 8;
                float a0 = acc[mf][nf][rr * 2 + 0], a1 = acc[mf][nf][rr * 2 + 1];
                if (MODE == 0) {
                    if (gm < M && gn < N) {
                        __half2* cp2 = reinterpret_cast<__half2*>(Cv);
                        cp2[(coff + (long long)gm * ldc + gn) >> 1] = __floats2half2_rn(a0, a1);
                    }
                } else if (MODE == 1) {
                    int b = gm / L_, l = gm % L_;
                    int ltm = dir ? (L_ - 1 - l) : l;
                    long long base = (long long)(b * L_ + ltm);
                    float2 tv = *reinterpret_cast<const float2*>(extra + base * DM + gn);
                    __half2* rp = reinterpret_cast<__half2*>(Cv);
                    rp[(base * (2 * DM) + dir * DM + gn) >> 1] =
                        __floats2half2_rn(a0 + tv.x, a1 + tv.y);
                } else {
                    int b = gm / L_, l = gm % L_;
                    float* C = reinterpret_cast<float*>(Cv);
                    long long i0 = ((long long)(b * DM + gn)) * L_ + l;
                    long long i1 = ((long long)(b * DM + gn + 1)) * L_ + l;
                    C[i0] = extra[i0] + bias[gn] + a0;
                    C[i1] = extra[i1] + bias[gn + 1] + a1;
                }
            }
        }
    }
}

// ---------------- fused: depthwise conv+SiLU  AND  dt softplus+scan ---------
__global__ void convdt_k(const __half* __restrict__ zx,
                         const float* __restrict__ cw0, const float* __restrict__ cb0,
                         const float* __restrict__ cw1, const float* __restrict__ cb1,
                         const float* __restrict__ db0, const float* __restrict__ al0,
                         const float* __restrict__ db1, const float* __restrict__ al1,
                         __half* __restrict__ xbc,
                         float* __restrict__ dt, float* __restrict__ acs) {
    int bi = blockIdx.x;
    if (bi < CONV_BLOCKS) {
        long long idx = (long long)bi * 256 + threadIdx.x;
        if (idx >= 2LL * B_ * (L_ / 4) * (CD / 4)) return;
        int cg = idx % (CD / 4);
        int lb = (idx / (CD / 4)) % (L_ / 4);
        long long rest = idx / ((long long)(CD / 4) * (L_ / 4));
        int b = rest % B_;
        int dir = rest / B_;
        int l0 = lb * 4;
        const float* cw = (dir ? cw1 : cw0) + cg * 16;
        const float* cb = (dir ? cb1 : cb0) + cg * 4;
        const __half* zxd = zx + dir * SZ_ZX + (size_t)(b * L_) * DIP + DI + cg * 4;
        float4 w0 = *reinterpret_cast<const float4*>(cw);
        float4 w1 = *reinterpret_cast<const float4*>(cw + 4);
        float4 w2 = *reinterpret_cast<const float4*>(cw + 8);
        float4 w3 = *reinterpret_cast<const float4*>(cw + 12);
        float4 bv = *reinterpret_cast<const float4*>(cb);
        float4 v[7];
#pragma unroll
        for (int r = 0; r < 7; r++) {
            int lp = l0 - 3 + r;
            if (lp >= 0) {
                const __half2* p = reinterpret_cast<const __half2*>(zxd + (size_t)lp * DIP);
                float2 f0 = __half22float2(p[0]);
                float2 f1 = __half22float2(p[1]);
                v[r] = make_float4(f0.x, f0.y, f1.x, f1.y);
            } else v[r] = make_float4(0.f, 0.f, 0.f, 0.f);
        }
        __half* outp = xbc + dir * SZ_XBC + ((size_t)(b * L_ + l0)) * CD + cg * 4;
#pragma unroll
        for (int j = 0; j < 4; j++) {
            float4 acc = bv;
#pragma unroll
            for (int k = 0; k < 4; k++) {
                float4 f = v[j + k];
                acc.x += ((const float*)&w0)[k] * f.x;
                acc.y += ((const float*)&w1)[k] * f.y;
                acc.z += ((const float*)&w2)[k] * f.z;
                acc.w += ((const float*)&w3)[k] * f.w;
            }
            __half2* op = reinterpret_cast<__half2*>(outp + (size_t)j * CD);
            op[0] = __floats2half2_rn(siluf(acc.x), siluf(acc.y));
            op[1] = __floats2half2_rn(siluf(acc.z), siluf(acc.w));
        }
        return;
    }
    // dt softplus + per-chunk cumsum
    int di = bi - CONV_BLOCKS;
    int dir = di / (B_ * NH * NC);
    di %= B_ * NH * NC;
    int c = di % NC, h = (di / NC) % NH, b = di / (NC * NH);
    const float* dt_bias = dir ? db1 : db0;
    const float* A_log   = dir ? al1 : al0;
    int l = threadIdx.x;
    int lane = l & 31, warp = l >> 5;
    int gl = c * CH + l;
    int row = b * L_ + gl;
    float v = __half2float(zx[dir * SZ_ZX + (size_t)row * DIP + (DIP - NH) + h]) + dt_bias[h];
    float dtv = softplusf(v);
    dt[dir * SZ_DT + (size_t)row * NH + h] = dtv;
    float a = -expf(A_log[h]) * dtv;
#pragma unroll
    for (int o = 1; o < 32; o <<= 1) {
        float t = __shfl_up_sync(0xffffffff, a, o);
        if (lane >= o) a += t;
    }
    __shared__ float wsum[8];
    if (lane == 31) wsum[warp] = a;
    __syncthreads();
    float off = 0.f;
#pragma unroll
    for (int w = 0; w < 8; w++) if (w < warp) off += wsum[w];
    acs[dir * SZ_ACS + (size_t)(b * NH + h) * L_ + gl] = a + off;
}

// ---------------- per-chunk end state via fp16 mma ----------------
__global__ void __launch_bounds__(256)
states_mma_k(const __half* __restrict__ xbc, const float* __restrict__ dt,
             const float* __restrict__ acs, float* __restrict__ st) {
    int h = blockIdx.x, c = blockIdx.y;
    int dir = blockIdx.z / B_, b = blockIdx.z % B_;
    const __half* xbcd = xbc + dir * SZ_XBC;
    const float* dtd  = dt  + dir * SZ_DT;
    const float* acsd = acs + dir * SZ_ACS;
    int tid = threadIdx.x;
    int warp = tid >> 5, lane = tid & 31;
    int wm = warp >> 2, wn = warp & 3;
    int group = lane >> 2, tig = lane & 3;
    __shared__ __half Xs[64][GLDH];
    __shared__ __half Bs[128][GLDH];
    __shared__ float wrow[CH];
    int acsbase = (b * NH + h) * L_ + c * CH;
    float csLast = acsd[acsbase + CH - 1];
    {
        int row = b * L_ + c * CH + tid;
        wrow[tid] = dtd[(size_t)row * NH + h] * __expf(csLast - acsd[acsbase + tid]);
    }
    __syncthreads();
    float acc[2][4][4] = {};
    for (int s0 = 0; s0 < CH; s0 += 32) {
#pragma unroll
        for (int i = 0; i < 8; i++) {
            int e = tid + i * 256;
            int pp = e & 63, ss = e >> 6;
            int row = b * L_ + c * CH + s0 + ss;
            Xs[pp][ss] = __float2half(
                __half2float(xbcd[(size_t)row * CD + h * HD + pp]) * wrow[s0 + ss]);
        }
#pragma unroll
        for (int i = 0; i < 16; i++) {
            int e = tid + i * 256;
            int nn = e & 127, ss = e >> 7;
            int row = b * L_ + c * CH + s0 + ss;
            Bs[nn][ss] = xbcd[(size_t)row * CD + DI + nn];
        }
        __syncthreads();
        const __half2* Xs2 = reinterpret_cast<const __half2*>(&Xs[0][0]);
        const __half2* Bs2 = reinterpret_cast<const __half2*>(&Bs[0][0]);
#pragma unroll
        for (int ks = 0; ks < 2; ks++) {
            int k2 = ks * 8;
            uint32_t af[2][4], bf[4][2];
#pragma unroll
            for (int mf = 0; mf < 2; mf++) {
                int rm = wm * 32 + mf * 16 + group;
                af[mf][0] = *reinterpret_cast<const uint32_t*>(&Xs2[(rm    ) * 20 + k2 + tig]);
                af[mf][1] = *reinterpret_cast<const uint32_t*>(&Xs2[(rm + 8) * 20 + k2 + tig]);
                af[mf][2] = *reinterpret_cast<const uint32_t*>(&Xs2[(rm    ) * 20 + k2 + tig + 4]);
                af[mf][3] = *reinterpret_cast<const uint32_t*>(&Xs2[(rm + 8) * 20 + k2 + tig + 4]);
            }
#pragma unroll
            for (int nf = 0; nf < 4; nf++) {
                int rn = wn * 32 + nf * 8 + group;
                bf[nf][0] = *reinterpret_cast<const uint32_t*>(&Bs2[rn * 20 + k2 + tig]);
                bf[nf][1] = *reinterpret_cast<const uint32_t*>(&Bs2[rn * 20 + k2 + tig + 4]);
            }
#pragma unroll
            for (int mf = 0; mf < 2; mf++)
#pragma unroll
                for (int nf = 0; nf < 4; nf++) MMA_F16(acc[mf][nf], af[mf], bf[nf]);
        }
        __syncthreads();
    }
    float* base = st + dir * SZ_ST + (size_t)((b * NC + c) * NH + h) * HD * DS;
#pragma unroll
    for (int mf = 0; mf < 2; mf++) {
#pragma unroll
        for (int nf = 0; nf < 4; nf++) {
            int gm = wm * 32 + mf * 16 + group;
            int gn = wn * 32 + nf * 8 + 2 * tig;
            *reinterpret_cast<float2*>(base + gm * DS + gn) =
                make_float2(acc[mf][nf][0], acc[mf][nf][1]);
            *reinterpret_cast<float2*>(base + (gm + 8) * DS + gn) =
                make_float2(acc[mf][nf][2], acc[mf][nf][3]);
        }
    }
}

// ---------------- inter-chunk recurrence ----------------
__global__ void chunkscan_k(const float* __restrict__ st, const float* __restrict__ acs,
                            float* __restrict__ pv) {
    int idx = blockIdx.x * blockDim.x + threadIdx.x;
    int n = idx & (DS - 1);
    int p = (idx >> 7) & (HD - 1);
    int h = (idx >> 13) & (NH - 1);
    int b = (idx >> 17) & (B_ - 1);
    int dir = idx >> 18;
    const float* std_ = st + dir * SZ_ST;
    const float* acsd = acs + dir * SZ_ACS;
    float* pvd = pv + dir * SZ_ST;
    float S = 0.f;
    for (int c = 0; c < NC; c++) {
        size_t off = ((size_t)((b * NC + c) * NH + h) * HD + p) * DS + n;
        pvd[off] = S;
        float at = acsd[(b * NH + h) * L_ + c * CH + CH - 1];
        S = S * expf(at) + std_[off];
    }
}

// ---------------- Y via fp16 mma -> fp16 output ----------------
__global__ void __launch_bounds__(256)
ssd_y_mma_k(const __half* __restrict__ xbc, const float* __restrict__ dt,
            const float* __restrict__ acs, const __half* __restrict__ cb,
            const float* __restrict__ pv,
            const float* __restrict__ Dh0, const float* __restrict__ Dh1,
            __half* __restrict__ yh) {
    int lt = blockIdx.x, h = blockIdx.y;
    int dir = blockIdx.z / (B_ * NC);
    int bc = blockIdx.z % (B_ * NC);
    int c = bc % NC, b = bc / NC;
    const __half* xbcd = xbc + dir * SZ_XBC;
    const float* dtd  = dt  + dir * SZ_DT;
    const float* acsd = acs + dir * SZ_ACS;
    const float* Dh   = dir ? Dh1 : Dh0;
    int tid = threadIdx.x;
    int warp = tid >> 5, lane = tid & 31;
    int wm = warp >> 2, wn = warp & 3;
    int group = lane >> 2, tig = lane & 3;
    __shared__ __half Ws[64][GLDH];
    __shared__ __half Xs[64][GLDH];
    __shared__ __half Ps[64][GLDH];
    __shared__ float csl[64], el64[64], eoff[64];
    __shared__ float einv[CH];
    int l0 = lt * 64;
    int acsbase = (b * NH + h) * L_ + c * CH;
    float csl0 = acsd[acsbase + l0];
    if (tid < 64) {
        float v = acsd[acsbase + l0 + tid];
        csl[tid]  = v;
        el64[tid] = __expf(v - csl0);
        eoff[tid] = __expf(v);
    }
    einv[tid] = __expf(csl0 - acsd[acsbase + tid]);
    __syncthreads();
    const __half* cbb = cb + dir * SZ_CB + (size_t)(b * NC + c) * CH * CH;
    float acc[2][2][4] = {};
    int nst = 2 * lt + 2;
    for (int stp = 0; stp < nst; stp++) {
        int s0 = stp * 32;
        bool lower = (s0 + 31 < l0);
        if (lower) {
#pragma unroll
            for (int i = 0; i < 8; i++) {
                int e = tid + i * 256;
                int j = e & 31, ii = e >> 5;
                Ws[ii][j] = __float2half(el64[ii] * einv[s0 + j] *
                                         __half2float(cbb[(l0 + ii) * CH + s0 + j]));
            }
        } else {
#pragma unroll
            for (int i = 0; i < 8; i++) {
                int e = tid + i * 256;
                int j = e & 31, ii = e >> 5;
                float w = 0.f;
                if (s0 + j <= l0 + ii)
                    w = __expf(csl[ii] - acsd[acsbase + s0 + j]) *
                        __half2float(cbb[(l0 + ii) * CH + s0 + j]);
                Ws[ii][j] = __float2half(w);
            }
        }
#pragma unroll
        for (int i = 0; i < 8; i++) {
            int e = tid + i * 256;
            int pp = e & 63, ss = e >> 6;
            int row = b * L_ + c * CH + s0 + ss;
            Xs[pp][ss] = __float2half(
                __half2float(xbcd[(size_t)row * CD + h * HD + pp]) * dtd[(size_t)row * NH + h]);
        }
        __syncthreads();
        const __half2* Ws2 = reinterpret_cast<const __half2*>(&Ws[0][0]);
        const __half2* Xs2 = reinterpret_cast<const __half2*>(&Xs[0][0]);
#pragma unroll
        for (int ks = 0; ks < 2; ks++) {
            int k2 = ks * 8;
            uint32_t af[2][4], bf[2][2];
#pragma unroll
            for (int mf = 0; mf < 2; mf++) {
                int rm = wm * 32 + mf * 16 + group;
                af[mf][0] = *reinterpret_cast<const uint32_t*>(&Ws2[(rm    ) * 20 + k2 + tig]);
                af[mf][1] = *reinterpret_cast<const uint32_t*>(&Ws2[(rm + 8) * 20 + k2 + tig]);
                af[mf][2] = *reinterpret_cast<const uint32_t*>(&Ws2[(rm    ) * 20 + k2 + tig + 4]);
                af[mf][3] = *reinterpret_cast<const uint32_t*>(&Ws2[(rm + 8) * 20 + k2 + tig + 4]);
            }
#pragma unroll
            for (int nf = 0; nf < 2; nf++) {
                int rn = wn * 16 + nf * 8 + group;
                bf[nf][0] = *reinterpret_cast<const uint32_t*>(&Xs2[rn * 20 + k2 + tig]);
                bf[nf][1] = *reinterpret_cast<const uint32_t*>(&Xs2[rn * 20 + k2 + tig + 4]);
            }
#pragma unroll
            for (int mf = 0; mf < 2; mf++)
#pragma unroll
                for (int nf = 0; nf < 2; nf++) MMA_F16(acc[mf][nf], af[mf], bf[nf]);
        }
        __syncthreads();
    }
    const float* pvb = pv + dir * SZ_ST + (size_t)((b * NC + c) * NH + h) * HD * DS;
    for (int nt = 0; nt < 4; nt++) {
        int n0 = nt * 32;
#pragma unroll
        for (int i = 0; i < 8; i++) {
            int e = tid + i * 256;
            int j = e & 31, ii = e >> 5;
            int row = b * L_ + c * CH + l0 + ii;
            Ws[ii][j] = __float2half(
                __half2float(xbcd[(size_t)row * CD + DI + DS + n0 + j]) * eoff[ii]);
        }
#pragma unroll
        for (int i = 0; i < 8; i++) {
            int e = tid + i * 256;
            int j = e & 31, pp = e >> 5;
            Ps[pp][j] = __float2half(pvb[pp * DS + n0 + j]);
        }
        __syncthreads();
        const __half2* Ws2 = reinterpret_cast<const __half2*>(&Ws[0][0]);
        const __half2* Ps2 = reinterpret_cast<const __half2*>(&Ps[0][0]);
#pragma unroll
        for (int ks = 0; ks < 2; ks++) {
            int k2 = ks * 8;
            uint32_t af[2][4], bf[2][2];
#pragma unroll
            for (int mf = 0; mf < 2; mf++) {
                int rm = wm * 32 + mf * 16 + group;
                af[mf][0] = *reinterpret_cast<const uint32_t*>(&Ws2[(rm    ) * 20 + k2 + tig]);
                af[mf][1] = *reinterpret_cast<const uint32_t*>(&Ws2[(rm + 8) * 20 + k2 + tig]);
                af[mf][2] = *reinterpret_cast<const uint32_t*>(&Ws2[(rm    ) * 20 + k2 + tig + 4]);
                af[mf][3] = *reinterpret_cast<const uint32_t*>(&Ws2[(rm + 8) * 20 + k2 + tig + 4]);
            }
#pragma unroll
            for (int nf = 0; nf < 2; nf++) {
                int rn = wn * 16 + nf * 8 + group;
                bf[nf][0] = *reinterpret_cast<const uint32_t*>(&Ps2[rn * 20 + k2 + tig]);
                bf[nf][1] = *reinterpret_cast<const uint32_t*>(&Ps2[rn * 20 + k2 + tig + 4]);
            }
#pragma unroll
            for (int mf = 0; mf < 2; mf++)
#pragma unroll
                for (int nf = 0; nf < 2; nf++) MMA_F16(acc[mf][nf], af[mf], bf[nf]);
        }
        __syncthreads();
    }
    float dh = Dh[h];
    __half* yd = yh + dir * SZ_Y;
#pragma unroll
    for (int mf = 0; mf < 2; mf++) {
#pragma unroll
        for (int nf = 0; nf < 2; nf++) {
            int ll = l0 + wm * 32 + mf * 16 + group;
            int pp = wn * 16 + nf * 8 + 2 * tig;
#pragma unroll
            for (int rr = 0; rr < 2; rr++) {
                int row = b * L_ + c * CH + ll + rr * 8;
                __half2 xrh = *reinterpret_cast<const __half2*>(
                    xbcd + (size_t)row * CD + h * HD + pp);
                float2 xr = __half22float2(xrh);
                *reinterpret_cast<__half2*>(yd + (size_t)row * DI + h * HD + pp) =
                    __floats2half2_rn(acc[mf][nf][rr * 2 + 0] + xr.x * dh,
                                      acc[mf][nf][rr * 2 + 1] + xr.y * dh);
            }
        }
    }
}

// ---------------- gating + RMSNorm, in place on fp16 yh ----------------
__global__ void gate_rms_k(__half* __restrict__ yh, const __half* __restrict__ zx,
                           const float* __restrict__ nw0, const float* __restrict__ nw1) {
    int row = blockIdx.x;
    int dir = row / (B_ * L_);
    row %= B_ * L_;
    const float* nw = dir ? nw1 : nw0;
    __half* yd = yh + dir * SZ_Y + (size_t)row * DI;
    const __half* zxd = zx + dir * SZ_ZX + (size_t)row * DIP;
    int tid = threadIdx.x;
    const __half2* yp = reinterpret_cast<const __half2*>(yd) + tid * 2;
    float2 y0 = __half22float2(yp[0]);
    float2 y1 = __half22float2(yp[1]);
    const __half2* zp = reinterpret_cast<const __half2*>(zxd + tid * 4);
    float2 z0 = __half22float2(zp[0]);
    float2 z1 = __half22float2(zp[1]);
    y0.x *= siluf(z0.x); y0.y *= siluf(z0.y); y1.x *= siluf(z1.x); y1.y *= siluf(z1.y);
    float ss = y0.x * y0.x + y0.y * y0.y + y1.x * y1.x + y1.y * y1.y;
    __shared__ float sh[256];
    sh[tid] = ss;
    __syncthreads();
    for (int o = 128; o > 0; o >>= 1) {
        if (tid < o) sh[tid] += sh[tid + o];
        __syncthreads();
    }
    float scale = rsqrtf(sh[0] / DI + RMS_EPS);
    float4 wv = *reinterpret_cast<const float4*>(nw + tid * 4);
    __half2* yw = reinterpret_cast<__half2*>(yd) + tid * 2;
    yw[0] = __floats2half2_rn(y0.x * scale * wv.x, y0.y * scale * wv.y);
    yw[1] = __floats2half2_rn(y1.x * scale * wv.z, y1.y * scale * wv.w);
}

// ---------------- launch ----------------
extern "C" void kernel_launch(void* const* d_in, const int* in_sizes, int n_in,
                              void* d_out, int out_size) {
    (void)in_sizes; (void)n_in; (void)out_size;
    const float* x      = (const float*)d_in[0];
    const float* gn_w   = (const float*)d_in[1];
    const float* gn_b   = (const float*)d_in[2];
    const float* proj_w = (const float*)d_in[3];
    const float* proj_b = (const float*)d_in[4];
    const float* fw[8], *bw[8];
    for (int i = 0; i < 8; i++) { fw[i] = (const float*)d_in[5 + i]; bw[i] = (const float*)d_in[13 + i]; }
    float* out = (float*)d_out;

    float *t_, *dt_, *acs_, *st_, *pv_, *part_, *stats_;
    __half *th_, *zx_, *xbc_, *cb_, *yh_, *rh_, *wih_, *woh_, *wph_;
    cudaGetSymbolAddress((void**)&t_,    g_t);
    cudaGetSymbolAddress((void**)&th_,   g_th);
    cudaGetSymbolAddress((void**)&zx_,   g_zx);
    cudaGetSymbolAddress((void**)&xbc_,  g_xbc);
    cudaGetSymbolAddress((void**)&dt_,   g_dt);
    cudaGetSymbolAddress((void**)&acs_,  g_acs);
    cudaGetSymbolAddress((void**)&cb_,   g_cb);
    cudaGetSymbolAddress((void**)&st_,   g_st);
    cudaGetSymbolAddress((void**)&pv_,   g_pv);
    cudaGetSymbolAddress((void**)&yh_,   g_yh);
    cudaGetSymbolAddress((void**)&rh_,   g_rh);
    cudaGetSymbolAddress((void**)&wih_,  g_wih);
    cudaGetSymbolAddress((void**)&woh_,  g_woh);
    cudaGetSymbolAddress((void**)&wph_,  g_wph);
    cudaGetSymbolAddress((void**)&part_, g_part);
    cudaGetSymbolAddress((void**)&stats_,g_stats);

    static bool attr_done = false;
    if (!attr_done) {
        cudaFuncSetAttribute(gemm_h<0>, cudaFuncAttributeMaxDynamicSharedMemorySize, H_SMEM_BYTES);
        cudaFuncSetAttribute(gemm_h<1>, cudaFuncAttributeMaxDynamicSharedMemorySize, H_SMEM_BYTES);
        cudaFuncSetAttribute(gemm_h<2>, cudaFuncAttributeMaxDynamicSharedMemorySize, H_SMEM_BYTES);
        attr_done = true;
    }

    // fused weight conversion + GN partial sums
    prep_k<<<CVT_BLOCKS + GNP_BLOCKS, 256>>>(fw[0], bw[0], fw[7], bw[7], proj_w,
                                             wih_, woh_, wph_, x, part_);
    gn_fin_k<<<B_, 64>>>(part_, stats_);
    gn_apply_k<<<dim3(L_ / 32, DM / 32, B_), dim3(32, 8)>>>(x, gn_w, gn_b, stats_, t_, th_);

    // in-projection -> zx (fp16)
    gemm_h<0><<<dim3((DIP + 127) / 128, (B_ * L_) / 128, 2), 128, H_SMEM_BYTES>>>(
        th_, wih_, wih_ + (long long)DIP * DM, zx_, B_ * L_, DIP, DM, DM, DM, DIP,
        0, 0, 0, 1, 0, SZ_ZX, L_, nullptr, nullptr);

    // fused conv+silu and dt softplus+scan
    convdt_k<<<CONV_BLOCKS + DTS_BLOCKS, 256>>>(
        zx_, fw[1], fw[2], bw[1], bw[2], fw[3], fw[4], bw[3], bw[4],
        xbc_, dt_, acs_);

    // CB = C @ B^T directly from fp16 xbc
    gemm_h<0><<<dim3(CH / 128, CH / 128, 2 * B_ * NC), 128, H_SMEM_BYTES>>>(
        xbc_ + DI + DS, xbc_ + DI, xbc_ + SZ_XBC + DI, cb_, CH, CH, DS, CD, CD, CH,
        (long long)CH * CD, (long long)CH * CD, (long long)CH * CH,
        B_ * NC, SZ_XBC, SZ_CB, 0, nullptr, nullptr);

    states_mma_k<<<dim3(NH, NC, 2 * B_), 256>>>(xbc_, dt_, acs_, st_);
    chunkscan_k<<<(2 * B_ * NH * HD * DS) / 256, 256>>>(st_, acs_, pv_);
    ssd_y_mma_k<<<dim3(CH / 64, NH, 2 * B_ * NC), 256>>>(
        xbc_, dt_, acs_, cb_, pv_, fw[5], bw[5], yh_);
    gate_rms_k<<<2 * B_ * L_, 256>>>(yh_, zx_, fw[6], bw[6]);

    gemm_h<1><<<dim3(DM / 128, (B_ * L_) / 128, 2), 128, H_SMEM_BYTES>>>(
        yh_, woh_, woh_ + (long long)DM * DI, rh_, B_ * L_, DM, DI, DI, DI, DM,
        0, 0, 0, 1, SZ_Y, 0, 0, t_, nullptr);

    gemm_h<2><<<dim3(DM / 128, (B_ * L_) / 128, 1), 128, H_SMEM_BYTES>>>(
        rh_, wph_, wph_, out, B_ * L_, DM, 2 * DM, 2 * DM, 2 * DM, DM,
        0, 0, 0, 1, 0, 0, 0, x, proj_b);
}

// round 14
// speedup vs baseline: 1.5189x; 1.0195x over previous
#include <cuda_runtime.h>
#include <cuda_bf16.h>
#include <cuda_fp16.h>
#include <math.h>
#include <stdint.h>

// ---------------- problem constants ----------------
static const int B_   = 2;
static const int L_   = 2048;
static const int DM   = 256;
static const int DS   = 128;
static const int DI   = 1024;
static const int NH   = 16;
static const int HD   = 64;
static const int CD   = 1280;
static const int DIP  = 2320;
static const int CH   = 256;
static const int NC   = 8;
#define GN_EPS 1.1920928955078125e-07f
#define RMS_EPS 1e-5f

#define SZ_ZX   ((long long)B_*L_*DIP)
#define SZ_XBC  ((long long)B_*L_*CD)
#define SZ_DT   ((long long)B_*L_*NH)
#define SZ_ACS  ((long long)B_*NH*L_)
#define SZ_CB   ((long long)B_*NC*CH*CH)
#define SZ_ST   ((long long)B_*NC*NH*HD*DS)
#define SZ_Y    ((long long)B_*L_*DI)

#define CVT_TOTAL (2*DIP*DM + 2*DM*DI + DM*2*DM)
#define CVT_BLOCKS ((CVT_TOTAL + 255) / 256)
#define GNP_BLOCKS (64 * B_)
#define CONV_BLOCKS ((int)((2LL * B_ * (L_/4) * (CD/4) + 255) / 256))
#define DTS_BLOCKS (2 * B_ * NH * NC)

// ---------------- scratch ----------------
__device__ float  g_t    [B_*L_*DM];
__device__ __half g_th   [B_*L_*DM];
__device__ __half g_zx   [2*B_*L_*DIP];
__device__ __half g_xbc  [2*B_*L_*CD];
__device__ float  g_dt   [2*B_*L_*NH];
__device__ float  g_acs  [2*B_*NH*L_];
__device__ __half g_cb   [2*B_*NC*CH*CH];
__device__ float  g_st   [2*B_*NC*NH*HD*DS];
__device__ float  g_pv   [2*B_*NC*NH*HD*DS];
__device__ __half g_yh   [2*B_*L_*DI];
__device__ __half g_rh   [B_*L_*2*DM];
__device__ __half g_wih  [2*DIP*DM];
__device__ __half g_woh  [2*DM*DI];
__device__ __half g_wph  [DM*2*DM];
__device__ float  g_part [B_*64*2];
__device__ float  g_stats[4];

__device__ __forceinline__ float siluf(float x) { return x / (1.f + __expf(-x)); }
__device__ __forceinline__ float softplusf(float x) { return x > 20.f ? x : log1pf(expf(x)); }

#define MMA_F16(acc, a, b) \
    asm volatile( \
        "mma.sync.aligned.m16n8k16.row.col.f32.f16.f16.f32 " \
        "{%0,%1,%2,%3},{%4,%5,%6,%7},{%8,%9},{%0,%1,%2,%3};" \
        : "+f"((acc)[0]), "+f"((acc)[1]), "+f"((acc)[2]), "+f"((acc)[3]) \
        : "r"((a)[0]), "r"((a)[1]), "r"((a)[2]), "r"((a)[3]), \
          "r"((b)[0]), "r"((b)[1]))

__device__ __forceinline__ void cpa16(uint32_t dst, const void* src, bool valid) {
    int sz = valid ? 16 : 0;
    asm volatile("cp.async.cg.shared.global [%0], [%1], 16, %2;\n"
                 :: "r"(dst), "l"(src), "r"(sz));
}
#define CPA_COMMIT() asm volatile("cp.async.commit_group;\n" ::)
#define CPA_WAIT1()  asm volatile("cp.async.wait_group 1;\n" ::)

// ---------------- fused: weight conversion + GroupNorm partials -------------
__global__ void prep_k(const float* __restrict__ a0, const float* __restrict__ a1,
                       const float* __restrict__ a2, const float* __restrict__ a3,
                       const float* __restrict__ a4,
                       __half* __restrict__ w_in, __half* __restrict__ w_out,
                       __half* __restrict__ w_pj,
                       const float* __restrict__ x, float* __restrict__ part) {
    int bi = blockIdx.x;
    if (bi < CVT_BLOCKS) {
        const int N1 = DIP * DM, N2 = DM * DI, N3 = DM * 2 * DM;
        int i = bi * 256 + threadIdx.x;
        if (i < N1) w_in[i] = __float2half(a0[i]);
        else if (i < 2 * N1) w_in[i] = __float2half(a1[i - N1]);
        else {
            int j = i - 2 * N1;
            if (j < N2) w_out[j] = __float2half(a2[j]);
            else if (j < 2 * N2) w_out[j] = __float2half(a3[j - N2]);
            else { int k = j - 2 * N2; if (k < N3) w_pj[k] = __float2half(a4[k]); }
        }
        return;
    }
    int gi = bi - CVT_BLOCKS;
    int b = gi / 64, blk = gi % 64;
    const float* xb = x + (size_t)b * DM * L_;
    float s = 0.f, ss = 0.f;
    for (int i = blk * 256 + threadIdx.x; i < DM * L_; i += 64 * 256) {
        float v = xb[i]; s += v; ss += v * v;
    }
    __shared__ float sh[256], sh2[256];
    sh[threadIdx.x] = s; sh2[threadIdx.x] = ss;
    __syncthreads();
    for (int o = 128; o > 0; o >>= 1) {
        if ((int)threadIdx.x < o) { sh[threadIdx.x] += sh[threadIdx.x + o]; sh2[threadIdx.x] += sh2[threadIdx.x + o]; }
        __syncthreads();
    }
    if (threadIdx.x == 0) {
        part[(b * 64 + blk) * 2 + 0] = sh[0];
        part[(b * 64 + blk) * 2 + 1] = sh2[0];
    }
}

__global__ void gn_fin_k(const float* __restrict__ part, float* __restrict__ stats) {
    int b = blockIdx.x;
    __shared__ double sh[64], sh2[64];
    int i = threadIdx.x;
    sh[i]  = (double)part[(b * 64 + i) * 2 + 0];
    sh2[i] = (double)part[(b * 64 + i) * 2 + 1];
    __syncthreads();
    for (int o = 32; o > 0; o >>= 1) {
        if (i < o) { sh[i] += sh[i + o]; sh2[i] += sh2[i + o]; }
        __syncthreads();
    }
    if (i == 0) {
        double n = (double)DM * L_;
        double mu = sh[0] / n;
        double var = sh2[0] / n - mu * mu;
        stats[b * 2 + 0] = (float)mu;
        stats[b * 2 + 1] = rsqrtf((float)var + GN_EPS);
    }
}

// ---------------- GroupNorm apply + transpose ----------------
__global__ void gn_apply_k(const float* __restrict__ x, const float* __restrict__ gw,
                           const float* __restrict__ gb, const float* __restrict__ stats,
                           float* __restrict__ t, __half* __restrict__ th) {
    int b = blockIdx.z;
    __shared__ float tile[32][33];
    int l0 = blockIdx.x * 32, d0 = blockIdx.y * 32;
    float mu = stats[b * 2], rs = stats[b * 2 + 1];
#pragma unroll
    for (int r = 0; r < 4; r++) {
        int d = d0 + threadIdx.y + r * 8;
        tile[threadIdx.y + r * 8][threadIdx.x] = x[((size_t)b * DM + d) * L_ + l0 + threadIdx.x];
    }
    __syncthreads();
    int d = d0 + threadIdx.x;
    float w = gw[d], bb = gb[d];
#pragma unroll
    for (int r = 0; r < 4; r++) {
        int l = l0 + threadIdx.y + r * 8;
        float v = (tile[threadIdx.x][threadIdx.y + r * 8] - mu) * rs * w + bb;
        t[((size_t)b * L_ + l) * DM + d] = v;
        th[((size_t)b * L_ + l) * DM + d] = __float2half(v);
    }
}

// ---- FP16 NT GEMM: 128x128 tile, 4 warps (64x64), BK=64 halves, 3-stage ----
#define GBM 128
#define GBN 128
#define HBK 64               // halves per k-iter (2x k16x2 blocks)
#define GST 3
#define GLDH2 72             // smem row stride in halves (36 half2)
#define H_SMEM_BYTES (GST * (GBM + GBN) * GLDH2 * 2)

template<int MODE>
__global__ void __launch_bounds__(128, 2)
gemm_h(const __half* __restrict__ A, const __half* __restrict__ B0,
       const __half* __restrict__ B1, void* __restrict__ Cv,
       int M, int N, int K, int lda, int ldb, int ldc,
       long long sA, long long sB, long long sC,
       int zPerDir, long long dA, long long dC, int revL,
       const float* __restrict__ extra, const float* __restrict__ bias) {
    constexpr int T  = 128;
    constexpr int MF = 4;
    constexpr int NF = 8;
    extern __shared__ __half hsm[];
    __half* Asm = hsm;
    __half* Bsm = hsm + GST * GBM * GLDH2;
    int z = blockIdx.z;
    int dir = z / zPerDir, zz = z % zPerDir;
    const __half* Ap = A + dir * dA + zz * sA;
    const __half* Bp = (dir ? B1 : B0) + zz * sB;
    long long coff = dir * dC + zz * sC;
    int rev = dir ? revL : 0;
    int m0 = blockIdx.y * GBM, n0 = blockIdx.x * GBN;
    int tid = threadIdx.x;
    int warp = tid >> 5, lane = tid & 31;
    int wm = warp >> 1, wn = warp & 1;
    int group = lane >> 2, tig = lane & 3;
    float acc[MF][NF][4] = {};

    auto issue = [&](int k0, int s) {     // k0 in halves
        __half* As = Asm + s * GBM * GLDH2;
        __half* Bs = Bsm + s * GBN * GLDH2;
#pragma unroll
        for (int i = 0; i < 8; i++) {
            int e = tid + i * T;
            int mm = e >> 3;
            int kc = (e & 7) * 8;
            int gm = m0 + mm;
            int row = gm < M ? gm : 0;
            if (rev && gm < M) { int bb = gm / rev; int ll = gm % rev; row = bb * rev + (rev - 1 - ll); }
            cpa16((uint32_t)__cvta_generic_to_shared(As + mm * GLDH2 + kc),
                  Ap + (long long)row * lda + k0 + kc, gm < M);
        }
#pragma unroll
        for (int i = 0; i < 8; i++) {
            int e = tid + i * T;
            int nn = e >> 3;
            int kc = (e & 7) * 8;
            int gn = n0 + nn;
            int rowb = gn < N ? gn : 0;
            cpa16((uint32_t)__cvta_generic_to_shared(Bs + nn * GLDH2 + kc),
                  Bp + (long long)rowb * ldb + k0 + kc, gn < N);
        }
    };
    auto compute = [&](int s) {
        const __half2* As2 = reinterpret_cast<const __half2*>(Asm + s * GBM * GLDH2);
        const __half2* Bs2 = reinterpret_cast<const __half2*>(Bsm + s * GBN * GLDH2);
#pragma unroll
        for (int ks = 0; ks < 4; ks++) {   // four k16 steps per 64-half iter
            int k2 = ks * 8;
            uint32_t af[MF][4], bf[NF][2];
#pragma unroll
            for (int mf = 0; mf < MF; mf++) {
                int rm = wm * 64 + mf * 16 + group;
                af[mf][0] = *reinterpret_cast<const uint32_t*>(&As2[(rm    ) * 36 + k2 + tig]);
                af[mf][1] = *reinterpret_cast<const uint32_t*>(&As2[(rm + 8) * 36 + k2 + tig]);
                af[mf][2] = *reinterpret_cast<const uint32_t*>(&As2[(rm    ) * 36 + k2 + tig + 4]);
                af[mf][3] = *reinterpret_cast<const uint32_t*>(&As2[(rm + 8) * 36 + k2 + tig + 4]);
            }
#pragma unroll
            for (int nf = 0; nf < NF; nf++) {
                int rn = wn * 64 + nf * 8 + group;
                bf[nf][0] = *reinterpret_cast<const uint32_t*>(&Bs2[rn * 36 + k2 + tig]);
                bf[nf][1] = *reinterpret_cast<const uint32_t*>(&Bs2[rn * 36 + k2 + tig + 4]);
            }
#pragma unroll
            for (int mf = 0; mf < MF; mf++)
#pragma unroll
                for (int nf = 0; nf < NF; nf++) MMA_F16(acc[mf][nf], af[mf], bf[nf]);
        }
    };

    int nIter = K / HBK;
    issue(0, 0);
    CPA_COMMIT();
    if (nIter > 1) issue(HBK, 1);
    CPA_COMMIT();
    for (int it = 0; it < nIter; it++) {
        CPA_WAIT1();
        __syncthreads();
        if (it + 2 < nIter) issue((it + 2) * HBK, (it + 2) % GST);
        CPA_COMMIT();
        compute(it % GST);
    }

#pragma unroll
    for (int mf = 0; mf < MF; mf++) {
#pragma unroll
        for (int nf = 0; nf < NF; nf++) {
            int gn = n0 + wn * 64 + nf * 8 + 2 * tig;
#pragma unroll
            for (int rr = 0; rr < 2; rr++) {
                int gm = m0 + wm * 64 + mf * 16 + group + rr * 8;
                float a0 = acc[mf][nf][rr * 2 + 0], a1 = acc[mf][nf][rr * 2 + 1];
                if (MODE == 0) {
                    if (gm < M && gn < N) {
                        __half2* cp2 = reinterpret_cast<__half2*>(Cv);
                        cp2[(coff + (long long)gm * ldc + gn) >> 1] = __floats2half2_rn(a0, a1);
                    }
                } else if (MODE == 1) {
                    int b = gm / L_, l = gm % L_;
                    int ltm = dir ? (L_ - 1 - l) : l;
                    long long base = (long long)(b * L_ + ltm);
                    float2 tv = *reinterpret_cast<const float2*>(extra + base * DM + gn);
                    __half2* rp = reinterpret_cast<__half2*>(Cv);
                    rp[(base * (2 * DM) + dir * DM + gn) >> 1] =
                        __floats2half2_rn(a0 + tv.x, a1 + tv.y);
                } else {
                    int b = gm / L_, l = gm % L_;
                    float* C = reinterpret_cast<float*>(Cv);
                    long long i0 = ((long long)(b * DM + gn)) * L_ + l;
                    long long i1 = ((long long)(b * DM + gn + 1)) * L_ + l;
                    C[i0] = extra[i0] + bias[gn] + a0;
                    C[i1] = extra[i1] + bias[gn + 1] + a1;
                }
            }
        }
    }
}

// ---------------- fused: depthwise conv+SiLU  AND  dt softplus+scan ---------
__global__ void convdt_k(const __half* __restrict__ zx,
                         const float* __restrict__ cw0, const float* __restrict__ cb0,
                         const float* __restrict__ cw1, const float* __restrict__ cb1,
                         const float* __restrict__ db0, const float* __restrict__ al0,
                         const float* __restrict__ db1, const float* __restrict__ al1,
                         __half* __restrict__ xbc,
                         float* __restrict__ dt, float* __restrict__ acs) {
    int bi = blockIdx.x;
    if (bi < CONV_BLOCKS) {
        long long idx = (long long)bi * 256 + threadIdx.x;
        if (idx >= 2LL * B_ * (L_ / 4) * (CD / 4)) return;
        int cg = idx % (CD / 4);
        int lb = (idx / (CD / 4)) % (L_ / 4);
        long long rest = idx / ((long long)(CD / 4) * (L_ / 4));
        int b = rest % B_;
        int dir = rest / B_;
        int l0 = lb * 4;
        const float* cw = (dir ? cw1 : cw0) + cg * 16;
        const float* cb = (dir ? cb1 : cb0) + cg * 4;
        const __half* zxd = zx + dir * SZ_ZX + (size_t)(b * L_) * DIP + DI + cg * 4;
        float4 w0 = *reinterpret_cast<const float4*>(cw);
        float4 w1 = *reinterpret_cast<const float4*>(cw + 4);
        float4 w2 = *reinterpret_cast<const float4*>(cw + 8);
        float4 w3 = *reinterpret_cast<const float4*>(cw + 12);
        float4 bv = *reinterpret_cast<const float4*>(cb);
        float4 v[7];
#pragma unroll
        for (int r = 0; r < 7; r++) {
            int lp = l0 - 3 + r;
            if (lp >= 0) {
                const __half2* p = reinterpret_cast<const __half2*>(zxd + (size_t)lp * DIP);
                float2 f0 = __half22float2(p[0]);
                float2 f1 = __half22float2(p[1]);
                v[r] = make_float4(f0.x, f0.y, f1.x, f1.y);
            } else v[r] = make_float4(0.f, 0.f, 0.f, 0.f);
        }
        __half* outp = xbc + dir * SZ_XBC + ((size_t)(b * L_ + l0)) * CD + cg * 4;
#pragma unroll
        for (int j = 0; j < 4; j++) {
            float4 acc = bv;
#pragma unroll
            for (int k = 0; k < 4; k++) {
                float4 f = v[j + k];
                acc.x += ((const float*)&w0)[k] * f.x;
                acc.y += ((const float*)&w1)[k] * f.y;
                acc.z += ((const float*)&w2)[k] * f.z;
                acc.w += ((const float*)&w3)[k] * f.w;
            }
            __half2* op = reinterpret_cast<__half2*>(outp + (size_t)j * CD);
            op[0] = __floats2half2_rn(siluf(acc.x), siluf(acc.y));
            op[1] = __floats2half2_rn(siluf(acc.z), siluf(acc.w));
        }
        return;
    }
    int di = bi - CONV_BLOCKS;
    int dir = di / (B_ * NH * NC);
    di %= B_ * NH * NC;
    int c = di % NC, h = (di / NC) % NH, b = di / (NC * NH);
    const float* dt_bias = dir ? db1 : db0;
    const float* A_log   = dir ? al1 : al0;
    int l = threadIdx.x;
    int lane = l & 31, warp = l >> 5;
    int gl = c * CH + l;
    int row = b * L_ + gl;
    float v = __half2float(zx[dir * SZ_ZX + (size_t)row * DIP + (DIP - NH) + h]) + dt_bias[h];
    float dtv = softplusf(v);
    dt[dir * SZ_DT + (size_t)row * NH + h] = dtv;
    float a = -expf(A_log[h]) * dtv;
#pragma unroll
    for (int o = 1; o < 32; o <<= 1) {
        float t = __shfl_up_sync(0xffffffff, a, o);
        if (lane >= o) a += t;
    }
    __shared__ float wsum[8];
    if (lane == 31) wsum[warp] = a;
    __syncthreads();
    float off = 0.f;
#pragma unroll
    for (int w = 0; w < 8; w++) if (w < warp) off += wsum[w];
    acs[dir * SZ_ACS + (size_t)(b * NH + h) * L_ + gl] = a + off;
}

// ---------------- per-chunk end state via fp16 mma ----------------
#define SLDH 40
__global__ void __launch_bounds__(256)
states_mma_k(const __half* __restrict__ xbc, const float* __restrict__ dt,
             const float* __restrict__ acs, float* __restrict__ st) {
    int h = blockIdx.x, c = blockIdx.y;
    int dir = blockIdx.z / B_, b = blockIdx.z % B_;
    const __half* xbcd = xbc + dir * SZ_XBC;
    const float* dtd  = dt  + dir * SZ_DT;
    const float* acsd = acs + dir * SZ_ACS;
    int tid = threadIdx.x;
    int warp = tid >> 5, lane = tid & 31;
    int wm = warp >> 2, wn = warp & 3;
    int group = lane >> 2, tig = lane & 3;
    __shared__ __half Xs[64][SLDH];
    __shared__ __half Bs[128][SLDH];
    __shared__ float wrow[CH];
    int acsbase = (b * NH + h) * L_ + c * CH;
    float csLast = acsd[acsbase + CH - 1];
    {
        int row = b * L_ + c * CH + tid;
        wrow[tid] = dtd[(size_t)row * NH + h] * __expf(csLast - acsd[acsbase + tid]);
    }
    __syncthreads();
    float acc[2][4][4] = {};
    for (int s0 = 0; s0 < CH; s0 += 32) {
#pragma unroll
        for (int i = 0; i < 8; i++) {
            int e = tid + i * 256;
            int pp = e & 63, ss = e >> 6;
            int row = b * L_ + c * CH + s0 + ss;
            Xs[pp][ss] = __float2half(
                __half2float(xbcd[(size_t)row * CD + h * HD + pp]) * wrow[s0 + ss]);
        }
#pragma unroll
        for (int i = 0; i < 16; i++) {
            int e = tid + i * 256;
            int nn = e & 127, ss = e >> 7;
            int row = b * L_ + c * CH + s0 + ss;
            Bs[nn][ss] = xbcd[(size_t)row * CD + DI + nn];
        }
        __syncthreads();
        const __half2* Xs2 = reinterpret_cast<const __half2*>(&Xs[0][0]);
        const __half2* Bs2 = reinterpret_cast<const __half2*>(&Bs[0][0]);
#pragma unroll
        for (int ks = 0; ks < 2; ks++) {
            int k2 = ks * 8;
            uint32_t af[2][4], bf[4][2];
#pragma unroll
            for (int mf = 0; mf < 2; mf++) {
                int rm = wm * 32 + mf * 16 + group;
                af[mf][0] = *reinterpret_cast<const uint32_t*>(&Xs2[(rm    ) * 20 + k2 + tig]);
                af[mf][1] = *reinterpret_cast<const uint32_t*>(&Xs2[(rm + 8) * 20 + k2 + tig]);
                af[mf][2] = *reinterpret_cast<const uint32_t*>(&Xs2[(rm    ) * 20 + k2 + tig + 4]);
                af[mf][3] = *reinterpret_cast<const uint32_t*>(&Xs2[(rm + 8) * 20 + k2 + tig + 4]);
            }
#pragma unroll
            for (int nf = 0; nf < 4; nf++) {
                int rn = wn * 32 + nf * 8 + group;
                bf[nf][0] = *reinterpret_cast<const uint32_t*>(&Bs2[rn * 20 + k2 + tig]);
                bf[nf][1] = *reinterpret_cast<const uint32_t*>(&Bs2[rn * 20 + k2 + tig + 4]);
            }
#pragma unroll
            for (int mf = 0; mf < 2; mf++)
#pragma unroll
                for (int nf = 0; nf < 4; nf++) MMA_F16(acc[mf][nf], af[mf], bf[nf]);
        }
        __syncthreads();
    }
    float* base = st + dir * SZ_ST + (size_t)((b * NC + c) * NH + h) * HD * DS;
#pragma unroll
    for (int mf = 0; mf < 2; mf++) {
#pragma unroll
        for (int nf = 0; nf < 4; nf++) {
            int gm = wm * 32 + mf * 16 + group;
            int gn = wn * 32 + nf * 8 + 2 * tig;
            *reinterpret_cast<float2*>(base + gm * DS + gn) =
                make_float2(acc[mf][nf][0], acc[mf][nf][1]);
            *reinterpret_cast<float2*>(base + (gm + 8) * DS + gn) =
                make_float2(acc[mf][nf][2], acc[mf][nf][3]);
        }
    }
}

// ---------------- inter-chunk recurrence ----------------
__global__ void chunkscan_k(const float* __restrict__ st, const float* __restrict__ acs,
                            float* __restrict__ pv) {
    int idx = blockIdx.x * blockDim.x + threadIdx.x;
    int n = idx & (DS - 1);
    int p = (idx >> 7) & (HD - 1);
    int h = (idx >> 13) & (NH - 1);
    int b = (idx >> 17) & (B_ - 1);
    int dir = idx >> 18;
    const float* std_ = st + dir * SZ_ST;
    const float* acsd = acs + dir * SZ_ACS;
    float* pvd = pv + dir * SZ_ST;
    float S = 0.f;
    for (int c = 0; c < NC; c++) {
        size_t off = ((size_t)((b * NC + c) * NH + h) * HD + p) * DS + n;
        pvd[off] = S;
        float at = acsd[(b * NH + h) * L_ + c * CH + CH - 1];
        S = S * expf(at) + std_[off];
    }
}

// ---------------- Y via fp16 mma -> fp16 output ----------------
__global__ void __launch_bounds__(256)
ssd_y_mma_k(const __half* __restrict__ xbc, const float* __restrict__ dt,
            const float* __restrict__ acs, const __half* __restrict__ cb,
            const float* __restrict__ pv,
            const float* __restrict__ Dh0, const float* __restrict__ Dh1,
            __half* __restrict__ yh) {
    int lt = blockIdx.x, h = blockIdx.y;
    int dir = blockIdx.z / (B_ * NC);
    int bc = blockIdx.z % (B_ * NC);
    int c = bc % NC, b = bc / NC;
    const __half* xbcd = xbc + dir * SZ_XBC;
    const float* dtd  = dt  + dir * SZ_DT;
    const float* acsd = acs + dir * SZ_ACS;
    const float* Dh   = dir ? Dh1 : Dh0;
    int tid = threadIdx.x;
    int warp = tid >> 5, lane = tid & 31;
    int wm = warp >> 2, wn = warp & 3;
    int group = lane >> 2, tig = lane & 3;
    __shared__ __half Ws[64][SLDH];
    __shared__ __half Xs[64][SLDH];
    __shared__ __half Ps[64][SLDH];
    __shared__ float csl[64], el64[64], eoff[64];
    __shared__ float einv[CH];
    int l0 = lt * 64;
    int acsbase = (b * NH + h) * L_ + c * CH;
    float csl0 = acsd[acsbase + l0];
    if (tid < 64) {
        float v = acsd[acsbase + l0 + tid];
        csl[tid]  = v;
        el64[tid] = __expf(v - csl0);
        eoff[tid] = __expf(v);
    }
    einv[tid] = __expf(csl0 - acsd[acsbase + tid]);
    __syncthreads();
    const __half* cbb = cb + dir * SZ_CB + (size_t)(b * NC + c) * CH * CH;
    float acc[2][2][4] = {};
    int nst = 2 * lt + 2;
    for (int stp = 0; stp < nst; stp++) {
        int s0 = stp * 32;
        bool lower = (s0 + 31 < l0);
        if (lower) {
#pragma unroll
            for (int i = 0; i < 8; i++) {
                int e = tid + i * 256;
                int j = e & 31, ii = e >> 5;
                Ws[ii][j] = __float2half(el64[ii] * einv[s0 + j] *
                                         __half2float(cbb[(l0 + ii) * CH + s0 + j]));
            }
        } else {
#pragma unroll
            for (int i = 0; i < 8; i++) {
                int e = tid + i * 256;
                int j = e & 31, ii = e >> 5;
                float w = 0.f;
                if (s0 + j <= l0 + ii)
                    w = __expf(csl[ii] - acsd[acsbase + s0 + j]) *
                        __half2float(cbb[(l0 + ii) * CH + s0 + j]);
                Ws[ii][j] = __float2half(w);
            }
        }
#pragma unroll
        for (int i = 0; i < 8; i++) {
            int e = tid + i * 256;
            int pp = e & 63, ss = e >> 6;
            int row = b * L_ + c * CH + s0 + ss;
            Xs[pp][ss] = __float2half(
                __half2float(xbcd[(size_t)row * CD + h * HD + pp]) * dtd[(size_t)row * NH + h]);
        }
        __syncthreads();
        const __half2* Ws2 = reinterpret_cast<const __half2*>(&Ws[0][0]);
        const __half2* Xs2 = reinterpret_cast<const __half2*>(&Xs[0][0]);
#pragma unroll
        for (int ks = 0; ks < 2; ks++) {
            int k2 = ks * 8;
            uint32_t af[2][4], bf[2][2];
#pragma unroll
            for (int mf = 0; mf < 2; mf++) {
                int rm = wm * 32 + mf * 16 + group;
                af[mf][0] = *reinterpret_cast<const uint32_t*>(&Ws2[(rm    ) * 20 + k2 + tig]);
                af[mf][1] = *reinterpret_cast<const uint32_t*>(&Ws2[(rm + 8) * 20 + k2 + tig]);
                af[mf][2] = *reinterpret_cast<const uint32_t*>(&Ws2[(rm    ) * 20 + k2 + tig + 4]);
                af[mf][3] = *reinterpret_cast<const uint32_t*>(&Ws2[(rm + 8) * 20 + k2 + tig + 4]);
            }
#pragma unroll
            for (int nf = 0; nf < 2; nf++) {
                int rn = wn * 16 + nf * 8 + group;
                bf[nf][0] = *reinterpret_cast<const uint32_t*>(&Xs2[rn * 20 + k2 + tig]);
                bf[nf][1] = *reinterpret_cast<const uint32_t*>(&Xs2[rn * 20 + k2 + tig + 4]);
            }
#pragma unroll
            for (int mf = 0; mf < 2; mf++)
#pragma unroll
                for (int nf = 0; nf < 2; nf++) MMA_F16(acc[mf][nf], af[mf], bf[nf]);
        }
        __syncthreads();
    }
    const float* pvb = pv + dir * SZ_ST + (size_t)((b * NC + c) * NH + h) * HD * DS;
    for (int nt = 0; nt < 4; nt++) {
        int n0 = nt * 32;
#pragma unroll
        for (int i = 0; i < 8; i++) {
            int e = tid + i * 256;
            int j = e & 31, ii = e >> 5;
            int row = b * L_ + c * CH + l0 + ii;
            Ws[ii][j] = __float2half(
                __half2float(xbcd[(size_t)row * CD + DI + DS + n0 + j]) * eoff[ii]);
        }
#pragma unroll
        for (int i = 0; i < 8; i++) {
            int e = tid + i * 256;
            int j = e & 31, pp = e >> 5;
            Ps[pp][j] = __float2half(pvb[pp * DS + n0 + j]);
        }
        __syncthreads();
        const __half2* Ws2 = reinterpret_cast<const __half2*>(&Ws[0][0]);
        const __half2* Ps2 = reinterpret_cast<const __half2*>(&Ps[0][0]);
#pragma unroll
        for (int ks = 0; ks < 2; ks++) {
            int k2 = ks * 8;
            uint32_t af[2][4], bf[2][2];
#pragma unroll
            for (int mf = 0; mf < 2; mf++) {
                int rm = wm * 32 + mf * 16 + group;
                af[mf][0] = *reinterpret_cast<const uint32_t*>(&Ws2[(rm    ) * 20 + k2 + tig]);
                af[mf][1] = *reinterpret_cast<const uint32_t*>(&Ws2[(rm + 8) * 20 + k2 + tig]);
                af[mf][2] = *reinterpret_cast<const uint32_t*>(&Ws2[(rm    ) * 20 + k2 + tig + 4]);
                af[mf][3] = *reinterpret_cast<const uint32_t*>(&Ws2[(rm + 8) * 20 + k2 + tig + 4]);
            }
#pragma unroll
            for (int nf = 0; nf < 2; nf++) {
                int rn = wn * 16 + nf * 8 + group;
                bf[nf][0] = *reinterpret_cast<const uint32_t*>(&Ps2[rn * 20 + k2 + tig]);
                bf[nf][1] = *reinterpret_cast<const uint32_t*>(&Ps2[rn * 20 + k2 + tig + 4]);
            }
#pragma unroll
            for (int mf = 0; mf < 2; mf++)
#pragma unroll
                for (int nf = 0; nf < 2; nf++) MMA_F16(acc[mf][nf], af[mf], bf[nf]);
        }
        __syncthreads();
    }
    float dh = Dh[h];
    __half* yd = yh + dir * SZ_Y;
#pragma unroll
    for (int mf = 0; mf < 2; mf++) {
#pragma unroll
        for (int nf = 0; nf < 2; nf++) {
            int ll = l0 + wm * 32 + mf * 16 + group;
            int pp = wn * 16 + nf * 8 + 2 * tig;
#pragma unroll
            for (int rr = 0; rr < 2; rr++) {
                int row = b * L_ + c * CH + ll + rr * 8;
                __half2 xrh = *reinterpret_cast<const __half2*>(
                    xbcd + (size_t)row * CD + h * HD + pp);
                float2 xr = __half22float2(xrh);
                *reinterpret_cast<__half2*>(yd + (size_t)row * DI + h * HD + pp) =
                    __floats2half2_rn(acc[mf][nf][rr * 2 + 0] + xr.x * dh,
                                      acc[mf][nf][rr * 2 + 1] + xr.y * dh);
            }
        }
    }
}

// ---------------- gating + RMSNorm, in place on fp16 yh ----------------
__global__ void gate_rms_k(__half* __restrict__ yh, const __half* __restrict__ zx,
                           const float* __restrict__ nw0, const float* __restrict__ nw1) {
    int row = blockIdx.x;
    int dir = row / (B_ * L_);
    row %= B_ * L_;
    const float* nw = dir ? nw1 : nw0;
    __half* yd = yh + dir * SZ_Y + (size_t)row * DI;
    const __half* zxd = zx + dir * SZ_ZX + (size_t)row * DIP;
    int tid = threadIdx.x;
    const __half2* yp = reinterpret_cast<const __half2*>(yd) + tid * 2;
    float2 y0 = __half22float2(yp[0]);
    float2 y1 = __half22float2(yp[1]);
    const __half2* zp = reinterpret_cast<const __half2*>(zxd + tid * 4);
    float2 z0 = __half22float2(zp[0]);
    float2 z1 = __half22float2(zp[1]);
    y0.x *= siluf(z0.x); y0.y *= siluf(z0.y); y1.x *= siluf(z1.x); y1.y *= siluf(z1.y);
    float ss = y0.x * y0.x + y0.y * y0.y + y1.x * y1.x + y1.y * y1.y;
    __shared__ float sh[256];
    sh[tid] = ss;
    __syncthreads();
    for (int o = 128; o > 0; o >>= 1) {
        if (tid < o) sh[tid] += sh[tid + o];
        __syncthreads();
    }
    float scale = rsqrtf(sh[0] / DI + RMS_EPS);
    float4 wv = *reinterpret_cast<const float4*>(nw + tid * 4);
    __half2* yw = reinterpret_cast<__half2*>(yd) + tid * 2;
    yw[0] = __floats2half2_rn(y0.x * scale * wv.x, y0.y * scale * wv.y);
    yw[1] = __floats2half2_rn(y1.x * scale * wv.z, y1.y * scale * wv.w);
}

// ---------------- launch ----------------
extern "C" void kernel_launch(void* const* d_in, const int* in_sizes, int n_in,
                              void* d_out, int out_size) {
    (void)in_sizes; (void)n_in; (void)out_size;
    const float* x      = (const float*)d_in[0];
    const float* gn_w   = (const float*)d_in[1];
    const float* gn_b   = (const float*)d_in[2];
    const float* proj_w = (const float*)d_in[3];
    const float* proj_b = (const float*)d_in[4];
    const float* fw[8], *bw[8];
    for (int i = 0; i < 8; i++) { fw[i] = (const float*)d_in[5 + i]; bw[i] = (const float*)d_in[13 + i]; }
    float* out = (float*)d_out;

    float *t_, *dt_, *acs_, *st_, *pv_, *part_, *stats_;
    __half *th_, *zx_, *xbc_, *cb_, *yh_, *rh_, *wih_, *woh_, *wph_;
    cudaGetSymbolAddress((void**)&t_,    g_t);
    cudaGetSymbolAddress((void**)&th_,   g_th);
    cudaGetSymbolAddress((void**)&zx_,   g_zx);
    cudaGetSymbolAddress((void**)&xbc_,  g_xbc);
    cudaGetSymbolAddress((void**)&dt_,   g_dt);
    cudaGetSymbolAddress((void**)&acs_,  g_acs);
    cudaGetSymbolAddress((void**)&cb_,   g_cb);
    cudaGetSymbolAddress((void**)&st_,   g_st);
    cudaGetSymbolAddress((void**)&pv_,   g_pv);
    cudaGetSymbolAddress((void**)&yh_,   g_yh);
    cudaGetSymbolAddress((void**)&rh_,   g_rh);
    cudaGetSymbolAddress((void**)&wih_,  g_wih);
    cudaGetSymbolAddress((void**)&woh_,  g_woh);
    cudaGetSymbolAddress((void**)&wph_,  g_wph);
    cudaGetSymbolAddress((void**)&part_, g_part);
    cudaGetSymbolAddress((void**)&stats_,g_stats);

    static bool attr_done = false;
    if (!attr_done) {
        cudaFuncSetAttribute(gemm_h<0>, cudaFuncAttributeMaxDynamicSharedMemorySize, H_SMEM_BYTES);
        cudaFuncSetAttribute(gemm_h<1>, cudaFuncAttributeMaxDynamicSharedMemorySize, H_SMEM_BYTES);
        cudaFuncSetAttribute(gemm_h<2>, cudaFuncAttributeMaxDynamicSharedMemorySize, H_SMEM_BYTES);
        attr_done = true;
    }

    prep_k<<<CVT_BLOCKS + GNP_BLOCKS, 256>>>(fw[0], bw[0], fw[7], bw[7], proj_w,
                                             wih_, woh_, wph_, x, part_);
    gn_fin_k<<<B_, 64>>>(part_, stats_);
    gn_apply_k<<<dim3(L_ / 32, DM / 32, B_), dim3(32, 8)>>>(x, gn_w, gn_b, stats_, t_, th_);

    gemm_h<0><<<dim3((DIP + 127) / 128, (B_ * L_) / 128, 2), 128, H_SMEM_BYTES>>>(
        th_, wih_, wih_ + (long long)DIP * DM, zx_, B_ * L_, DIP, DM, DM, DM, DIP,
        0, 0, 0, 1, 0, SZ_ZX, L_, nullptr, nullptr);

    convdt_k<<<CONV_BLOCKS + DTS_BLOCKS, 256>>>(
        zx_, fw[1], fw[2], bw[1], bw[2], fw[3], fw[4], bw[3], bw[4],
        xbc_, dt_, acs_);

    gemm_h<0><<<dim3(CH / 128, CH / 128, 2 * B_ * NC), 128, H_SMEM_BYTES>>>(
        xbc_ + DI + DS, xbc_ + DI, xbc_ + SZ_XBC + DI, cb_, CH, CH, DS, CD, CD, CH,
        (long long)CH * CD, (long long)CH * CD, (long long)CH * CH,
        B_ * NC, SZ_XBC, SZ_CB, 0, nullptr, nullptr);

    states_mma_k<<<dim3(NH, NC, 2 * B_), 256>>>(xbc_, dt_, acs_, st_);
    chunkscan_k<<<(2 * B_ * NH * HD * DS) / 256, 256>>>(st_, acs_, pv_);
    ssd_y_mma_k<<<dim3(CH / 64, NH, 2 * B_ * NC), 256>>>(
        xbc_, dt_, acs_, cb_, pv_, fw[5], bw[5], yh_);
    gate_rms_k<<<2 * B_ * L_, 256>>>(yh_, zx_, fw[6], bw[6]);

    gemm_h<1><<<dim3(DM / 128, (B_ * L_) / 128, 2), 128, H_SMEM_BYTES>>>(
        yh_, woh_, woh_ + (long long)DM * DI, rh_, B_ * L_, DM, DI, DI, DI, DM,
        0, 0, 0, 1, SZ_Y, 0, 0, t_, nullptr);

    gemm_h<2><<<dim3(DM / 128, (B_ * L_) / 128, 1), 128, H_SMEM_BYTES>>>(
        rh_, wph_, wph_, out, B_ * L_, DM, 2 * DM, 2 * DM, 2 * DM, DM,
        0, 0, 0, 1, 0, 0, 0, x, proj_b);
}

// round 15
// speedup vs baseline: 1.5684x; 1.0325x over previous
#include <cuda_runtime.h>
#include <cuda_bf16.h>
#include <cuda_fp16.h>
#include <math.h>
#include <stdint.h>

// ---------------- problem constants ----------------
static const int B_   = 2;
static const int L_   = 2048;
static const int DM   = 256;
static const int DS   = 128;
static const int DI   = 1024;
static const int NH   = 16;
static const int HD   = 64;
static const int CD   = 1280;
static const int DIP  = 2320;
static const int CH   = 256;
static const int NC   = 8;
#define GN_EPS 1.1920928955078125e-07f
#define RMS_EPS 1e-5f

#define SZ_ZX   ((long long)B_*L_*DIP)
#define SZ_XBC  ((long long)B_*L_*CD)
#define SZ_DT   ((long long)B_*L_*NH)
#define SZ_ACS  ((long long)B_*NH*L_)
#define SZ_CB   ((long long)B_*NC*CH*CH)
#define SZ_ST   ((long long)B_*NC*NH*HD*DS)
#define SZ_Y    ((long long)B_*L_*DI)

#define CVT_TOTAL (2*DIP*DM + 2*DM*DI + DM*2*DM)
#define CVT_BLOCKS ((CVT_TOTAL + 255) / 256)
#define GNP_BLOCKS (64 * B_)
#define CONV_BLOCKS ((int)((2LL * B_ * (L_/4) * (CD/4) + 255) / 256))
#define DTS_BLOCKS (2 * B_ * NH * NC)

// ---------------- scratch ----------------
__device__ float  g_t    [B_*L_*DM];
__device__ __half g_th   [B_*L_*DM];
__device__ __half g_zx   [2*B_*L_*DIP];
__device__ __half g_xbc  [2*B_*L_*CD];
__device__ float  g_dt   [2*B_*L_*NH];
__device__ float  g_acs  [2*B_*NH*L_];
__device__ __half g_cb   [2*B_*NC*CH*CH];
__device__ float  g_st   [2*B_*NC*NH*HD*DS];
__device__ float  g_pv   [2*B_*NC*NH*HD*DS];
__device__ __half g_yh   [2*B_*L_*DI];
__device__ __half g_rh   [B_*L_*2*DM];
__device__ __half g_wih  [2*DIP*DM];
__device__ __half g_woh  [2*DM*DI];
__device__ __half g_wph  [DM*2*DM];
__device__ float  g_part [B_*64*2];
__device__ float  g_stats[4];

__device__ __forceinline__ float siluf(float x) { return x / (1.f + __expf(-x)); }
__device__ __forceinline__ float softplusf(float x) { return x > 20.f ? x : log1pf(expf(x)); }

#define MMA_F16(acc, a, b) \
    asm volatile( \
        "mma.sync.aligned.m16n8k16.row.col.f32.f16.f16.f32 " \
        "{%0,%1,%2,%3},{%4,%5,%6,%7},{%8,%9},{%0,%1,%2,%3};" \
        : "+f"((acc)[0]), "+f"((acc)[1]), "+f"((acc)[2]), "+f"((acc)[3]) \
        : "r"((a)[0]), "r"((a)[1]), "r"((a)[2]), "r"((a)[3]), \
          "r"((b)[0]), "r"((b)[1]))

__device__ __forceinline__ void cpa16(uint32_t dst, const void* src, bool valid) {
    int sz = valid ? 16 : 0;
    asm volatile("cp.async.cg.shared.global [%0], [%1], 16, %2;\n"
                 :: "r"(dst), "l"(src), "r"(sz));
}
#define CPA_COMMIT() asm volatile("cp.async.commit_group;\n" ::)
#define CPA_WAIT1()  asm volatile("cp.async.wait_group 1;\n" ::)

// ---------------- fused: weight conversion + GroupNorm partials -------------
__global__ void prep_k(const float* __restrict__ a0, const float* __restrict__ a1,
                       const float* __restrict__ a2, const float* __restrict__ a3,
                       const float* __restrict__ a4,
                       __half* __restrict__ w_in, __half* __restrict__ w_out,
                       __half* __restrict__ w_pj,
                       const float* __restrict__ x, float* __restrict__ part) {
    int bi = blockIdx.x;
    if (bi < CVT_BLOCKS) {
        const int N1 = DIP * DM, N2 = DM * DI, N3 = DM * 2 * DM;
        int i = bi * 256 + threadIdx.x;
        if (i < N1) w_in[i] = __float2half(a0[i]);
        else if (i < 2 * N1) w_in[i] = __float2half(a1[i - N1]);
        else {
            int j = i - 2 * N1;
            if (j < N2) w_out[j] = __float2half(a2[j]);
            else if (j < 2 * N2) w_out[j] = __float2half(a3[j - N2]);
            else { int k = j - 2 * N2; if (k < N3) w_pj[k] = __float2half(a4[k]); }
        }
        return;
    }
    int gi = bi - CVT_BLOCKS;
    int b = gi / 64, blk = gi % 64;
    const float* xb = x + (size_t)b * DM * L_;
    float s = 0.f, ss = 0.f;
    for (int i = blk * 256 + threadIdx.x; i < DM * L_; i += 64 * 256) {
        float v = xb[i]; s += v; ss += v * v;
    }
    __shared__ float sh[256], sh2[256];
    sh[threadIdx.x] = s; sh2[threadIdx.x] = ss;
    __syncthreads();
    for (int o = 128; o > 0; o >>= 1) {
        if ((int)threadIdx.x < o) { sh[threadIdx.x] += sh[threadIdx.x + o]; sh2[threadIdx.x] += sh2[threadIdx.x + o]; }
        __syncthreads();
    }
    if (threadIdx.x == 0) {
        part[(b * 64 + blk) * 2 + 0] = sh[0];
        part[(b * 64 + blk) * 2 + 1] = sh2[0];
    }
}

__global__ void gn_fin_k(const float* __restrict__ part, float* __restrict__ stats) {
    int b = blockIdx.x;
    __shared__ double sh[64], sh2[64];
    int i = threadIdx.x;
    sh[i]  = (double)part[(b * 64 + i) * 2 + 0];
    sh2[i] = (double)part[(b * 64 + i) * 2 + 1];
    __syncthreads();
    for (int o = 32; o > 0; o >>= 1) {
        if (i < o) { sh[i] += sh[i + o]; sh2[i] += sh2[i + o]; }
        __syncthreads();
    }
    if (i == 0) {
        double n = (double)DM * L_;
        double mu = sh[0] / n;
        double var = sh2[0] / n - mu * mu;
        stats[b * 2 + 0] = (float)mu;
        stats[b * 2 + 1] = rsqrtf((float)var + GN_EPS);
    }
}

// ---------------- GroupNorm apply + transpose ----------------
__global__ void gn_apply_k(const float* __restrict__ x, const float* __restrict__ gw,
                           const float* __restrict__ gb, const float* __restrict__ stats,
                           float* __restrict__ t, __half* __restrict__ th) {
    int b = blockIdx.z;
    __shared__ float tile[32][33];
    int l0 = blockIdx.x * 32, d0 = blockIdx.y * 32;
    float mu = stats[b * 2], rs = stats[b * 2 + 1];
#pragma unroll
    for (int r = 0; r < 4; r++) {
        int d = d0 + threadIdx.y + r * 8;
        tile[threadIdx.y + r * 8][threadIdx.x] = x[((size_t)b * DM + d) * L_ + l0 + threadIdx.x];
    }
    __syncthreads();
    int d = d0 + threadIdx.x;
    float w = gw[d], bb = gb[d];
#pragma unroll
    for (int r = 0; r < 4; r++) {
        int l = l0 + threadIdx.y + r * 8;
        float v = (tile[threadIdx.x][threadIdx.y + r * 8] - mu) * rs * w + bb;
        t[((size_t)b * L_ + l) * DM + d] = v;
        th[((size_t)b * L_ + l) * DM + d] = __float2half(v);
    }
}

// ---- FP16 NT GEMM: 128x128 tile, 8 warps (32x64 each), BK=64, 3-stage ------
#define GBM 128
#define GBN 128
#define HBK 64
#define GST 3
#define GLDH2 72
#define H_SMEM_BYTES (GST * (GBM + GBN) * GLDH2 * 2)

template<int MODE>
__global__ void __launch_bounds__(256, 2)
gemm_h(const __half* __restrict__ A, const __half* __restrict__ B0,
       const __half* __restrict__ B1, void* __restrict__ Cv,
       int M, int N, int K, int lda, int ldb, int ldc,
       long long sA, long long sB, long long sC,
       int zPerDir, long long dA, long long dC, int revL,
       const float* __restrict__ extra, const float* __restrict__ bias) {
    constexpr int T  = 256;
    constexpr int MF = 2;
    constexpr int NF = 8;
    extern __shared__ __half hsm[];
    __half* Asm = hsm;
    __half* Bsm = hsm + GST * GBM * GLDH2;
    int z = blockIdx.z;
    int dir = z / zPerDir, zz = z % zPerDir;
    const __half* Ap = A + dir * dA + zz * sA;
    const __half* Bp = (dir ? B1 : B0) + zz * sB;
    long long coff = dir * dC + zz * sC;
    int rev = dir ? revL : 0;
    int m0 = blockIdx.y * GBM, n0 = blockIdx.x * GBN;
    int tid = threadIdx.x;
    int warp = tid >> 5, lane = tid & 31;
    int wm = warp >> 1, wn = warp & 1;      // 4(M) x 2(N) warps
    int group = lane >> 2, tig = lane & 3;
    float acc[MF][NF][4] = {};

    auto issue = [&](int k0, int s) {
        __half* As = Asm + s * GBM * GLDH2;
        __half* Bs = Bsm + s * GBN * GLDH2;
#pragma unroll
        for (int i = 0; i < 4; i++) {
            int e = tid + i * T;
            int mm = e >> 3;
            int kc = (e & 7) * 8;
            int gm = m0 + mm;
            int row = gm < M ? gm : 0;
            if (rev && gm < M) { int bb = gm / rev; int ll = gm % rev; row = bb * rev + (rev - 1 - ll); }
            cpa16((uint32_t)__cvta_generic_to_shared(As + mm * GLDH2 + kc),
                  Ap + (long long)row * lda + k0 + kc, gm < M);
        }
#pragma unroll
        for (int i = 0; i < 4; i++) {
            int e = tid + i * T;
            int nn = e >> 3;
            int kc = (e & 7) * 8;
            int gn = n0 + nn;
            int rowb = gn < N ? gn : 0;
            cpa16((uint32_t)__cvta_generic_to_shared(Bs + nn * GLDH2 + kc),
                  Bp + (long long)rowb * ldb + k0 + kc, gn < N);
        }
    };
    auto compute = [&](int s) {
        const __half2* As2 = reinterpret_cast<const __half2*>(Asm + s * GBM * GLDH2);
        const __half2* Bs2 = reinterpret_cast<const __half2*>(Bsm + s * GBN * GLDH2);
#pragma unroll
        for (int ks = 0; ks < 4; ks++) {
            int k2 = ks * 8;
            uint32_t af[MF][4], bf[NF][2];
#pragma unroll
            for (int mf = 0; mf < MF; mf++) {
                int rm = wm * 32 + mf * 16 + group;
                af[mf][0] = *reinterpret_cast<const uint32_t*>(&As2[(rm    ) * 36 + k2 + tig]);
                af[mf][1] = *reinterpret_cast<const uint32_t*>(&As2[(rm + 8) * 36 + k2 + tig]);
                af[mf][2] = *reinterpret_cast<const uint32_t*>(&As2[(rm    ) * 36 + k2 + tig + 4]);
                af[mf][3] = *reinterpret_cast<const uint32_t*>(&As2[(rm + 8) * 36 + k2 + tig + 4]);
            }
#pragma unroll
            for (int nf = 0; nf < NF; nf++) {
                int rn = wn * 64 + nf * 8 + group;
                bf[nf][0] = *reinterpret_cast<const uint32_t*>(&Bs2[rn * 36 + k2 + tig]);
                bf[nf][1] = *reinterpret_cast<const uint32_t*>(&Bs2[rn * 36 + k2 + tig + 4]);
            }
#pragma unroll
            for (int mf = 0; mf < MF; mf++)
#pragma unroll
                for (int nf = 0; nf < NF; nf++) MMA_F16(acc[mf][nf], af[mf], bf[nf]);
        }
    };

    int nIter = K / HBK;
    issue(0, 0);
    CPA_COMMIT();
    if (nIter > 1) issue(HBK, 1);
    CPA_COMMIT();
    for (int it = 0; it < nIter; it++) {
        CPA_WAIT1();
        __syncthreads();
        if (it + 2 < nIter) issue((it + 2) * HBK, (it + 2) % GST);
        CPA_COMMIT();
        compute(it % GST);
    }

#pragma unroll
    for (int mf = 0; mf < MF; mf++) {
#pragma unroll
        for (int nf = 0; nf < NF; nf++) {
            int gn = n0 + wn * 64 + nf * 8 + 2 * tig;
#pragma unroll
            for (int rr = 0; rr < 2; rr++) {
                int gm = m0 + wm * 32 + mf * 16 + group + rr * 8;
                float a0 = acc[mf][nf][rr * 2 + 0], a1 = acc[mf][nf][rr * 2 + 1];
                if (MODE == 0) {
                    if (gm < M && gn < N) {
                        __half2* cp2 = reinterpret_cast<__half2*>(Cv);
                        cp2[(coff + (long long)gm * ldc + gn) >> 1] = __floats2half2_rn(a0, a1);
                    }
                } else if (MODE == 1) {
                    int b = gm / L_, l = gm % L_;
                    int ltm = dir ? (L_ - 1 - l) : l;
                    long long base = (long long)(b * L_ + ltm);
                    float2 tv = *reinterpret_cast<const float2*>(extra + base * DM + gn);
                    __half2* rp = reinterpret_cast<__half2*>(Cv);
                    rp[(base * (2 * DM) + dir * DM + gn) >> 1] =
                        __floats2half2_rn(a0 + tv.x, a1 + tv.y);
                } else {
                    int b = gm / L_, l = gm % L_;
                    float* C = reinterpret_cast<float*>(Cv);
                    long long i0 = ((long long)(b * DM + gn)) * L_ + l;
                    long long i1 = ((long long)(b * DM + gn + 1)) * L_ + l;
                    C[i0] = extra[i0] + bias[gn] + a0;
                    C[i1] = extra[i1] + bias[gn + 1] + a1;
                }
            }
        }
    }
}

// ---------------- fused: depthwise conv+SiLU  AND  dt softplus+scan ---------
__global__ void convdt_k(const __half* __restrict__ zx,
                         const float* __restrict__ cw0, const float* __restrict__ cb0,
                         const float* __restrict__ cw1, const float* __restrict__ cb1,
                         const float* __restrict__ db0, const float* __restrict__ al0,
                         const float* __restrict__ db1, const float* __restrict__ al1,
                         __half* __restrict__ xbc,
                         float* __restrict__ dt, float* __restrict__ acs) {
    int bi = blockIdx.x;
    if (bi < CONV_BLOCKS) {
        long long idx = (long long)bi * 256 + threadIdx.x;
        if (idx >= 2LL * B_ * (L_ / 4) * (CD / 4)) return;
        int cg = idx % (CD / 4);
        int lb = (idx / (CD / 4)) % (L_ / 4);
        long long rest = idx / ((long long)(CD / 4) * (L_ / 4));
        int b = rest % B_;
        int dir = rest / B_;
        int l0 = lb * 4;
        const float* cw = (dir ? cw1 : cw0) + cg * 16;
        const float* cb = (dir ? cb1 : cb0) + cg * 4;
        const __half* zxd = zx + dir * SZ_ZX + (size_t)(b * L_) * DIP + DI + cg * 4;
        float4 w0 = *reinterpret_cast<const float4*>(cw);
        float4 w1 = *reinterpret_cast<const float4*>(cw + 4);
        float4 w2 = *reinterpret_cast<const float4*>(cw + 8);
        float4 w3 = *reinterpret_cast<const float4*>(cw + 12);
        float4 bv = *reinterpret_cast<const float4*>(cb);
        float4 v[7];
#pragma unroll
        for (int r = 0; r < 7; r++) {
            int lp = l0 - 3 + r;
            if (lp >= 0) {
                const __half2* p = reinterpret_cast<const __half2*>(zxd + (size_t)lp * DIP);
                float2 f0 = __half22float2(p[0]);
                float2 f1 = __half22float2(p[1]);
                v[r] = make_float4(f0.x, f0.y, f1.x, f1.y);
            } else v[r] = make_float4(0.f, 0.f, 0.f, 0.f);
        }
        __half* outp = xbc + dir * SZ_XBC + ((size_t)(b * L_ + l0)) * CD + cg * 4;
#pragma unroll
        for (int j = 0; j < 4; j++) {
            float4 acc = bv;
#pragma unroll
            for (int k = 0; k < 4; k++) {
                float4 f = v[j + k];
                acc.x += ((const float*)&w0)[k] * f.x;
                acc.y += ((const float*)&w1)[k] * f.y;
                acc.z += ((const float*)&w2)[k] * f.z;
                acc.w += ((const float*)&w3)[k] * f.w;
            }
            __half2* op = reinterpret_cast<__half2*>(outp + (size_t)j * CD);
            op[0] = __floats2half2_rn(siluf(acc.x), siluf(acc.y));
            op[1] = __floats2half2_rn(siluf(acc.z), siluf(acc.w));
        }
        return;
    }
    int di = bi - CONV_BLOCKS;
    int dir = di / (B_ * NH * NC);
    di %= B_ * NH * NC;
    int c = di % NC, h = (di / NC) % NH, b = di / (NC * NH);
    const float* dt_bias = dir ? db1 : db0;
    const float* A_log   = dir ? al1 : al0;
    int l = threadIdx.x;
    int lane = l & 31, warp = l >> 5;
    int gl = c * CH + l;
    int row = b * L_ + gl;
    float v = __half2float(zx[dir * SZ_ZX + (size_t)row * DIP + (DIP - NH) + h]) + dt_bias[h];
    float dtv = softplusf(v);
    dt[dir * SZ_DT + (size_t)row * NH + h] = dtv;
    float a = -expf(A_log[h]) * dtv;
#pragma unroll
    for (int o = 1; o < 32; o <<= 1) {
        float t = __shfl_up_sync(0xffffffff, a, o);
        if (lane >= o) a += t;
    }
    __shared__ float wsum[8];
    if (lane == 31) wsum[warp] = a;
    __syncthreads();
    float off = 0.f;
#pragma unroll
    for (int w = 0; w < 8; w++) if (w < warp) off += wsum[w];
    acs[dir * SZ_ACS + (size_t)(b * NH + h) * L_ + gl] = a + off;
}

// ---------------- per-chunk end state via fp16 mma ----------------
#define SLDH 40
__global__ void __launch_bounds__(256)
states_mma_k(const __half* __restrict__ xbc, const float* __restrict__ dt,
             const float* __restrict__ acs, float* __restrict__ st) {
    int h = blockIdx.x, c = blockIdx.y;
    int dir = blockIdx.z / B_, b = blockIdx.z % B_;
    const __half* xbcd = xbc + dir * SZ_XBC;
    const float* dtd  = dt  + dir * SZ_DT;
    const float* acsd = acs + dir * SZ_ACS;
    int tid = threadIdx.x;
    int warp = tid >> 5, lane = tid & 31;
    int wm = warp >> 2, wn = warp & 3;
    int group = lane >> 2, tig = lane & 3;
    __shared__ __half Xs[64][SLDH];
    __shared__ __half Bs[128][SLDH];
    __shared__ float wrow[CH];
    int acsbase = (b * NH + h) * L_ + c * CH;
    float csLast = acsd[acsbase + CH - 1];
    {
        int row = b * L_ + c * CH + tid;
        wrow[tid] = dtd[(size_t)row * NH + h] * __expf(csLast - acsd[acsbase + tid]);
    }
    __syncthreads();
    float acc[2][4][4] = {};
    for (int s0 = 0; s0 < CH; s0 += 32) {
#pragma unroll
        for (int i = 0; i < 8; i++) {
            int e = tid + i * 256;
            int pp = e & 63, ss = e >> 6;
            int row = b * L_ + c * CH + s0 + ss;
            Xs[pp][ss] = __float2half(
                __half2float(xbcd[(size_t)row * CD + h * HD + pp]) * wrow[s0 + ss]);
        }
#pragma unroll
        for (int i = 0; i < 16; i++) {
            int e = tid + i * 256;
            int nn = e & 127, ss = e >> 7;
            int row = b * L_ + c * CH + s0 + ss;
            Bs[nn][ss] = xbcd[(size_t)row * CD + DI + nn];
        }
        __syncthreads();
        const __half2* Xs2 = reinterpret_cast<const __half2*>(&Xs[0][0]);
        const __half2* Bs2 = reinterpret_cast<const __half2*>(&Bs[0][0]);
#pragma unroll
        for (int ks = 0; ks < 2; ks++) {
            int k2 = ks * 8;
            uint32_t af[2][4], bf[4][2];
#pragma unroll
            for (int mf = 0; mf < 2; mf++) {
                int rm = wm * 32 + mf * 16 + group;
                af[mf][0] = *reinterpret_cast<const uint32_t*>(&Xs2[(rm    ) * 20 + k2 + tig]);
                af[mf][1] = *reinterpret_cast<const uint32_t*>(&Xs2[(rm + 8) * 20 + k2 + tig]);
                af[mf][2] = *reinterpret_cast<const uint32_t*>(&Xs2[(rm    ) * 20 + k2 + tig + 4]);
                af[mf][3] = *reinterpret_cast<const uint32_t*>(&Xs2[(rm + 8) * 20 + k2 + tig + 4]);
            }
#pragma unroll
            for (int nf = 0; nf < 4; nf++) {
                int rn = wn * 32 + nf * 8 + group;
                bf[nf][0] = *reinterpret_cast<const uint32_t*>(&Bs2[rn * 20 + k2 + tig]);
                bf[nf][1] = *reinterpret_cast<const uint32_t*>(&Bs2[rn * 20 + k2 + tig + 4]);
            }
#pragma unroll
            for (int mf = 0; mf < 2; mf++)
#pragma unroll
                for (int nf = 0; nf < 4; nf++) MMA_F16(acc[mf][nf], af[mf], bf[nf]);
        }
        __syncthreads();
    }
    float* base = st + dir * SZ_ST + (size_t)((b * NC + c) * NH + h) * HD * DS;
#pragma unroll
    for (int mf = 0; mf < 2; mf++) {
#pragma unroll
        for (int nf = 0; nf < 4; nf++) {
            int gm = wm * 32 + mf * 16 + group;
            int gn = wn * 32 + nf * 8 + 2 * tig;
            *reinterpret_cast<float2*>(base + gm * DS + gn) =
                make_float2(acc[mf][nf][0], acc[mf][nf][1]);
            *reinterpret_cast<float2*>(base + (gm + 8) * DS + gn) =
                make_float2(acc[mf][nf][2], acc[mf][nf][3]);
        }
    }
}

// ---------------- inter-chunk recurrence ----------------
__global__ void chunkscan_k(const float* __restrict__ st, const float* __restrict__ acs,
                            float* __restrict__ pv) {
    int idx = blockIdx.x * blockDim.x + threadIdx.x;
    int n = idx & (DS - 1);
    int p = (idx >> 7) & (HD - 1);
    int h = (idx >> 13) & (NH - 1);
    int b = (idx >> 17) & (B_ - 1);
    int dir = idx >> 18;
    const float* std_ = st + dir * SZ_ST;
    const float* acsd = acs + dir * SZ_ACS;
    float* pvd = pv + dir * SZ_ST;
    float S = 0.f;
    for (int c = 0; c < NC; c++) {
        size_t off = ((size_t)((b * NC + c) * NH + h) * HD + p) * DS + n;
        pvd[off] = S;
        float at = acsd[(b * NH + h) * L_ + c * CH + CH - 1];
        S = S * expf(at) + std_[off];
    }
}

// ---------------- Y via fp16 mma -> fp16 output ----------------
__global__ void __launch_bounds__(256)
ssd_y_mma_k(const __half* __restrict__ xbc, const float* __restrict__ dt,
            const float* __restrict__ acs, const __half* __restrict__ cb,
            const float* __restrict__ pv,
            const float* __restrict__ Dh0, const float* __restrict__ Dh1,
            __half* __restrict__ yh) {
    int lt = blockIdx.x, h = blockIdx.y;
    int dir = blockIdx.z / (B_ * NC);
    int bc = blockIdx.z % (B_ * NC);
    int c = bc % NC, b = bc / NC;
    const __half* xbcd = xbc + dir * SZ_XBC;
    const float* dtd  = dt  + dir * SZ_DT;
    const float* acsd = acs + dir * SZ_ACS;
    const float* Dh   = dir ? Dh1 : Dh0;
    int tid = threadIdx.x;
    int warp = tid >> 5, lane = tid & 31;
    int wm = warp >> 2, wn = warp & 3;
    int group = lane >> 2, tig = lane & 3;
    __shared__ __half Ws[64][SLDH];
    __shared__ __half Xs[64][SLDH];
    __shared__ __half Ps[64][SLDH];
    __shared__ float csl[64], el64[64], eoff[64];
    __shared__ float einv[CH];
    int l0 = lt * 64;
    int acsbase = (b * NH + h) * L_ + c * CH;
    float csl0 = acsd[acsbase + l0];
    if (tid < 64) {
        float v = acsd[acsbase + l0 + tid];
        csl[tid]  = v;
        el64[tid] = __expf(v - csl0);
        eoff[tid] = __expf(v);
    }
    einv[tid] = __expf(csl0 - acsd[acsbase + tid]);
    __syncthreads();
    const __half* cbb = cb + dir * SZ_CB + (size_t)(b * NC + c) * CH * CH;
    float acc[2][2][4] = {};
    int nst = 2 * lt + 2;
    for (int stp = 0; stp < nst; stp++) {
        int s0 = stp * 32;
        bool lower = (s0 + 31 < l0);
        if (lower) {
#pragma unroll
            for (int i = 0; i < 8; i++) {
                int e = tid + i * 256;
                int j = e & 31, ii = e >> 5;
                Ws[ii][j] = __float2half(el64[ii] * einv[s0 + j] *
                                         __half2float(cbb[(l0 + ii) * CH + s0 + j]));
            }
        } else {
#pragma unroll
            for (int i = 0; i < 8; i++) {
                int e = tid + i * 256;
                int j = e & 31, ii = e >> 5;
                float w = 0.f;
                if (s0 + j <= l0 + ii)
                    w = __expf(csl[ii] - acsd[acsbase + s0 + j]) *
                        __half2float(cbb[(l0 + ii) * CH + s0 + j]);
                Ws[ii][j] = __float2half(w);
            }
        }
#pragma unroll
        for (int i = 0; i < 8; i++) {
            int e = tid + i * 256;
            int pp = e & 63, ss = e >> 6;
            int row = b * L_ + c * CH + s0 + ss;
            Xs[pp][ss] = __float2half(
                __half2float(xbcd[(size_t)row * CD + h * HD + pp]) * dtd[(size_t)row * NH + h]);
        }
        __syncthreads();
        const __half2* Ws2 = reinterpret_cast<const __half2*>(&Ws[0][0]);
        const __half2* Xs2 = reinterpret_cast<const __half2*>(&Xs[0][0]);
#pragma unroll
        for (int ks = 0; ks < 2; ks++) {
            int k2 = ks * 8;
            uint32_t af[2][4], bf[2][2];
#pragma unroll
            for (int mf = 0; mf < 2; mf++) {
                int rm = wm * 32 + mf * 16 + group;
                af[mf][0] = *reinterpret_cast<const uint32_t*>(&Ws2[(rm    ) * 20 + k2 + tig]);
                af[mf][1] = *reinterpret_cast<const uint32_t*>(&Ws2[(rm + 8) * 20 + k2 + tig]);
                af[mf][2] = *reinterpret_cast<const uint32_t*>(&Ws2[(rm    ) * 20 + k2 + tig + 4]);
                af[mf][3] = *reinterpret_cast<const uint32_t*>(&Ws2[(rm + 8) * 20 + k2 + tig + 4]);
            }
#pragma unroll
            for (int nf = 0; nf < 2; nf++) {
                int rn = wn * 16 + nf * 8 + group;
                bf[nf][0] = *reinterpret_cast<const uint32_t*>(&Xs2[rn * 20 + k2 + tig]);
                bf[nf][1] = *reinterpret_cast<const uint32_t*>(&Xs2[rn * 20 + k2 + tig + 4]);
            }
#pragma unroll
            for (int mf = 0; mf < 2; mf++)
#pragma unroll
                for (int nf = 0; nf < 2; nf++) MMA_F16(acc[mf][nf], af[mf], bf[nf]);
        }
        __syncthreads();
    }
    const float* pvb = pv + dir * SZ_ST + (size_t)((b * NC + c) * NH + h) * HD * DS;
    for (int nt = 0; nt < 4; nt++) {
        int n0 = nt * 32;
#pragma unroll
        for (int i = 0; i < 8; i++) {
            int e = tid + i * 256;
            int j = e & 31, ii = e >> 5;
            int row = b * L_ + c * CH + l0 + ii;
            Ws[ii][j] = __float2half(
                __half2float(xbcd[(size_t)row * CD + DI + DS + n0 + j]) * eoff[ii]);
        }
#pragma unroll
        for (int i = 0; i < 8; i++) {
            int e = tid + i * 256;
            int j = e & 31, pp = e >> 5;
            Ps[pp][j] = __float2half(pvb[pp * DS + n0 + j]);
        }
        __syncthreads();
        const __half2* Ws2 = reinterpret_cast<const __half2*>(&Ws[0][0]);
        const __half2* Ps2 = reinterpret_cast<const __half2*>(&Ps[0][0]);
#pragma unroll
        for (int ks = 0; ks < 2; ks++) {
            int k2 = ks * 8;
            uint32_t af[2][4], bf[2][2];
#pragma unroll
            for (int mf = 0; mf < 2; mf++) {
                int rm = wm * 32 + mf * 16 + group;
                af[mf][0] = *reinterpret_cast<const uint32_t*>(&Ws2[(rm    ) * 20 + k2 + tig]);
                af[mf][1] = *reinterpret_cast<const uint32_t*>(&Ws2[(rm + 8) * 20 + k2 + tig]);
                af[mf][2] = *reinterpret_cast<const uint32_t*>(&Ws2[(rm    ) * 20 + k2 + tig + 4]);
                af[mf][3] = *reinterpret_cast<const uint32_t*>(&Ws2[(rm + 8) * 20 + k2 + tig + 4]);
            }
#pragma unroll
            for (int nf = 0; nf < 2; nf++) {
                int rn = wn * 16 + nf * 8 + group;
                bf[nf][0] = *reinterpret_cast<const uint32_t*>(&Ps2[rn * 20 + k2 + tig]);
                bf[nf][1] = *reinterpret_cast<const uint32_t*>(&Ps2[rn * 20 + k2 + tig + 4]);
            }
#pragma unroll
            for (int mf = 0; mf < 2; mf++)
#pragma unroll
                for (int nf = 0; nf < 2; nf++) MMA_F16(acc[mf][nf], af[mf], bf[nf]);
        }
        __syncthreads();
    }
    float dh = Dh[h];
    __half* yd = yh + dir * SZ_Y;
#pragma unroll
    for (int mf = 0; mf < 2; mf++) {
#pragma unroll
        for (int nf = 0; nf < 2; nf++) {
            int ll = l0 + wm * 32 + mf * 16 + group;
            int pp = wn * 16 + nf * 8 + 2 * tig;
#pragma unroll
            for (int rr = 0; rr < 2; rr++) {
                int row = b * L_ + c * CH + ll + rr * 8;
                __half2 xrh = *reinterpret_cast<const __half2*>(
                    xbcd + (size_t)row * CD + h * HD + pp);
                float2 xr = __half22float2(xrh);
                *reinterpret_cast<__half2*>(yd + (size_t)row * DI + h * HD + pp) =
                    __floats2half2_rn(acc[mf][nf][rr * 2 + 0] + xr.x * dh,
                                      acc[mf][nf][rr * 2 + 1] + xr.y * dh);
            }
        }
    }
}

// ---------------- gating + RMSNorm, in place on fp16 yh ----------------
__global__ void gate_rms_k(__half* __restrict__ yh, const __half* __restrict__ zx,
                           const float* __restrict__ nw0, const float* __restrict__ nw1) {
    int row = blockIdx.x;
    int dir = row / (B_ * L_);
    row %= B_ * L_;
    const float* nw = dir ? nw1 : nw0;
    __half* yd = yh + dir * SZ_Y + (size_t)row * DI;
    const __half* zxd = zx + dir * SZ_ZX + (size_t)row * DIP;
    int tid = threadIdx.x;
    const __half2* yp = reinterpret_cast<const __half2*>(yd) + tid * 2;
    float2 y0 = __half22float2(yp[0]);
    float2 y1 = __half22float2(yp[1]);
    const __half2* zp = reinterpret_cast<const __half2*>(zxd + tid * 4);
    float2 z0 = __half22float2(zp[0]);
    float2 z1 = __half22float2(zp[1]);
    y0.x *= siluf(z0.x); y0.y *= siluf(z0.y); y1.x *= siluf(z1.x); y1.y *= siluf(z1.y);
    float ss = y0.x * y0.x + y0.y * y0.y + y1.x * y1.x + y1.y * y1.y;
    __shared__ float sh[256];
    sh[tid] = ss;
    __syncthreads();
    for (int o = 128; o > 0; o >>= 1) {
        if (tid < o) sh[tid] += sh[tid + o];
        __syncthreads();
    }
    float scale = rsqrtf(sh[0] / DI + RMS_EPS);
    float4 wv = *reinterpret_cast<const float4*>(nw + tid * 4);
    __half2* yw = reinterpret_cast<__half2*>(yd) + tid * 2;
    yw[0] = __floats2half2_rn(y0.x * scale * wv.x, y0.y * scale * wv.y);
    yw[1] = __floats2half2_rn(y1.x * scale * wv.z, y1.y * scale * wv.w);
}

// ---------------- launch ----------------
extern "C" void kernel_launch(void* const* d_in, const int* in_sizes, int n_in,
                              void* d_out, int out_size) {
    (void)in_sizes; (void)n_in; (void)out_size;
    const float* x      = (const float*)d_in[0];
    const float* gn_w   = (const float*)d_in[1];
    const float* gn_b   = (const float*)d_in[2];
    const float* proj_w = (const float*)d_in[3];
    const float* proj_b = (const float*)d_in[4];
    const float* fw[8], *bw[8];
    for (int i = 0; i < 8; i++) { fw[i] = (const float*)d_in[5 + i]; bw[i] = (const float*)d_in[13 + i]; }
    float* out = (float*)d_out;

    float *t_, *dt_, *acs_, *st_, *pv_, *part_, *stats_;
    __half *th_, *zx_, *xbc_, *cb_, *yh_, *rh_, *wih_, *woh_, *wph_;
    cudaGetSymbolAddress((void**)&t_,    g_t);
    cudaGetSymbolAddress((void**)&th_,   g_th);
    cudaGetSymbolAddress((void**)&zx_,   g_zx);
    cudaGetSymbolAddress((void**)&xbc_,  g_xbc);
    cudaGetSymbolAddress((void**)&dt_,   g_dt);
    cudaGetSymbolAddress((void**)&acs_,  g_acs);
    cudaGetSymbolAddress((void**)&cb_,   g_cb);
    cudaGetSymbolAddress((void**)&st_,   g_st);
    cudaGetSymbolAddress((void**)&pv_,   g_pv);
    cudaGetSymbolAddress((void**)&yh_,   g_yh);
    cudaGetSymbolAddress((void**)&rh_,   g_rh);
    cudaGetSymbolAddress((void**)&wih_,  g_wih);
    cudaGetSymbolAddress((void**)&woh_,  g_woh);
    cudaGetSymbolAddress((void**)&wph_,  g_wph);
    cudaGetSymbolAddress((void**)&part_, g_part);
    cudaGetSymbolAddress((void**)&stats_,g_stats);

    static bool attr_done = false;
    if (!attr_done) {
        cudaFuncSetAttribute(gemm_h<0>, cudaFuncAttributeMaxDynamicSharedMemorySize, H_SMEM_BYTES);
        cudaFuncSetAttribute(gemm_h<1>, cudaFuncAttributeMaxDynamicSharedMemorySize, H_SMEM_BYTES);
        cudaFuncSetAttribute(gemm_h<2>, cudaFuncAttributeMaxDynamicSharedMemorySize, H_SMEM_BYTES);
        attr_done = true;
    }

    prep_k<<<CVT_BLOCKS + GNP_BLOCKS, 256>>>(fw[0], bw[0], fw[7], bw[7], proj_w,
                                             wih_, woh_, wph_, x, part_);
    gn_fin_k<<<B_, 64>>>(part_, stats_);
    gn_apply_k<<<dim3(L_ / 32, DM / 32, B_), dim3(32, 8)>>>(x, gn_w, gn_b, stats_, t_, th_);

    gemm_h<0><<<dim3((DIP + 127) / 128, (B_ * L_) / 128, 2), 256, H_SMEM_BYTES>>>(
        th_, wih_, wih_ + (long long)DIP * DM, zx_, B_ * L_, DIP, DM, DM, DM, DIP,
        0, 0, 0, 1, 0, SZ_ZX, L_, nullptr, nullptr);

    convdt_k<<<CONV_BLOCKS + DTS_BLOCKS, 256>>>(
        zx_, fw[1], fw[2], bw[1], bw[2], fw[3], fw[4], bw[3], bw[4],
        xbc_, dt_, acs_);

    gemm_h<0><<<dim3(CH / 128, CH / 128, 2 * B_ * NC), 256, H_SMEM_BYTES>>>(
        xbc_ + DI + DS, xbc_ + DI, xbc_ + SZ_XBC + DI, cb_, CH, CH, DS, CD, CD, CH,
        (long long)CH * CD, (long long)CH * CD, (long long)CH * CH,
        B_ * NC, SZ_XBC, SZ_CB, 0, nullptr, nullptr);

    states_mma_k<<<dim3(NH, NC, 2 * B_), 256>>>(xbc_, dt_, acs_, st_);
    chunkscan_k<<<(2 * B_ * NH * HD * DS) / 256, 256>>>(st_, acs_, pv_);
    ssd_y_mma_k<<<dim3(CH / 64, NH, 2 * B_ * NC), 256>>>(
        xbc_, dt_, acs_, cb_, pv_, fw[5], bw[5], yh_);
    gate_rms_k<<<2 * B_ * L_, 256>>>(yh_, zx_, fw[6], bw[6]);

    gemm_h<1><<<dim3(DM / 128, (B_ * L_) / 128, 2), 256, H_SMEM_BYTES>>>(
        yh_, woh_, woh_ + (long long)DM * DI, rh_, B_ * L_, DM, DI, DI, DI, DM,
        0, 0, 0, 1, SZ_Y, 0, 0, t_, nullptr);

    gemm_h<2><<<dim3(DM / 128, (B_ * L_) / 128, 1), 256, H_SMEM_BYTES>>>(
        rh_, wph_, wph_, out, B_ * L_, DM, 2 * DM, 2 * DM, 2 * DM, DM,
        0, 0, 0, 1, 0, 0, 0, x, proj_b);
}